// round 4
// baseline (speedup 1.0000x reference)
#include <cuda_runtime.h>
#include <math.h>

#define DIMC 768
#define NH 12
#define HD 64
#define NB 8
#define NT 1024
#define M_TOK (NB*NT)   // 8192

// ---- scratch (device globals: no allocations allowed) ----
__device__ float g_q[NB*NH*NT*HD];          // [b,h,n,d], Q pre-scaled
__device__ float g_k[NB*NH*NT*HD];
__device__ float g_v[NB*NH*NT*HD];
__device__ float g_S[(size_t)NB*NH*NT*NT];  // 402 MB scores / probs (in place)
__device__ float g_O[(size_t)M_TOK*DIMC];   // [tok, dim]

// ---------- helpers ----------
__device__ __forceinline__ unsigned f2tf(float f) {
    unsigned u; asm("cvt.rna.tf32.f32 %0, %1;" : "=r"(u) : "f"(f)); return u;
}
__device__ __forceinline__ unsigned ld_tf(const float* p) { return f2tf(*p); }
__device__ __forceinline__ void mma8(float* d, unsigned a0, unsigned a1,
                                     unsigned a2, unsigned a3,
                                     unsigned b0, unsigned b1) {
    asm volatile(
        "mma.sync.aligned.m16n8k8.row.col.f32.tf32.tf32.f32 "
        "{%0,%1,%2,%3},{%4,%5,%6,%7},{%8,%9},{%0,%1,%2,%3};"
        : "+f"(d[0]), "+f"(d[1]), "+f"(d[2]), "+f"(d[3])
        : "r"(a0), "r"(a1), "r"(a2), "r"(a3), "r"(b0), "r"(b1));
}
__device__ __forceinline__ void cp16(void* s, const void* g) {
    unsigned sa = (unsigned)__cvta_generic_to_shared(s);
    asm volatile("cp.async.ca.shared.global [%0], [%1], 16;" :: "r"(sa), "l"(g));
}
#define CP_COMMIT asm volatile("cp.async.commit_group;")
#define CP_WAIT1  asm volatile("cp.async.wait_group 1;")

// ============================================================
// proj body: C[.,768] = scale*(A @ B[768,768]) (+bias)
// 128x128 tile, BK=16, 3-stage cp.async, 256 thr, warp 64x32.
// ============================================================
template<int HEAD_SPLIT>
__device__ __forceinline__ void proj_body(
    const float* __restrict__ A, const float* __restrict__ Bm,
    float* __restrict__ C, const float* __restrict__ bias, float scale)
{
    extern __shared__ float sm[];
    float* As = sm;               // [3][128][20]
    float* Bs = sm + 3 * 2560;    // [3][16][136]

    int tid = threadIdx.x, lane = tid & 31, wid = tid >> 5;
    int warp_m = wid & 1, warp_n = wid >> 1;
    int rowBase = blockIdx.y * 128, colBase = blockIdx.x * 128;
    int lr = lane >> 2, lc = lane & 3;
    int m0 = warp_m * 64, n0 = warp_n * 32;

    const float* Ap = A + (size_t)rowBase * DIMC;
    const float* Bp = Bm + colBase;

#define PROJ_LOAD(s, k0) do {                                          \
    float* Ad = As + (s) * 2560;                                       \
    float* Bd = Bs + (s) * 2176;                                       \
    _Pragma("unroll")                                                  \
    for (int i_ = 0; i_ < 2; i_++) {                                   \
        int t_ = tid + i_ * 256;                                       \
        int r_ = t_ >> 2, c_ = (t_ & 3) * 4;                           \
        cp16(&Ad[r_ * 20 + c_], Ap + (size_t)r_ * DIMC + (k0) + c_);   \
        int br_ = t_ >> 5, bc_ = (t_ & 31) * 4;                        \
        cp16(&Bd[br_ * 136 + bc_], Bp + (size_t)((k0) + br_) * DIMC + bc_); \
    }                                                                  \
    CP_COMMIT;                                                         \
} while (0)

    PROJ_LOAD(0, 0);
    PROJ_LOAD(1, 16);

    float acc[4][4][4] = {};
    const int NITER = DIMC / 16;   // 48
    for (int it = 0; it < NITER; it++) {
        CP_WAIT1;
        __syncthreads();
        int s = it % 3;
        const float* Aq = As + s * 2560;
        const float* Bq = Bs + s * 2176;
#pragma unroll
        for (int kk = 0; kk < 16; kk += 8) {
            unsigned a[4][4], b[4][2];
#pragma unroll
            for (int mi = 0; mi < 4; mi++) {
                int r = m0 + mi * 16 + lr;
                a[mi][0] = ld_tf(&Aq[r * 20 + kk + lc]);
                a[mi][1] = ld_tf(&Aq[(r + 8) * 20 + kk + lc]);
                a[mi][2] = ld_tf(&Aq[r * 20 + kk + lc + 4]);
                a[mi][3] = ld_tf(&Aq[(r + 8) * 20 + kk + lc + 4]);
            }
#pragma unroll
            for (int ni = 0; ni < 4; ni++) {
                int c = n0 + ni * 8 + lr;
                b[ni][0] = ld_tf(&Bq[(kk + lc) * 136 + c]);
                b[ni][1] = ld_tf(&Bq[(kk + lc + 4) * 136 + c]);
            }
#pragma unroll
            for (int mi = 0; mi < 4; mi++)
#pragma unroll
                for (int ni = 0; ni < 4; ni++)
                    mma8(acc[mi][ni], a[mi][0], a[mi][1], a[mi][2], a[mi][3],
                         b[ni][0], b[ni][1]);
        }
        __syncthreads();
        if (it + 2 < NITER) PROJ_LOAD((it + 2) % 3, (it + 2) * 16);
        else CP_COMMIT;
    }
#undef PROJ_LOAD

#pragma unroll
    for (int mi = 0; mi < 4; mi++) {
#pragma unroll
        for (int ni = 0; ni < 4; ni++) {
            int col = colBase + n0 + ni * 8 + 2 * lc;
            float bv0 = 0.f, bv1 = 0.f;
            if (bias) { bv0 = bias[col]; bv1 = bias[col + 1]; }
#pragma unroll
            for (int half = 0; half < 2; half++) {
                int row = rowBase + m0 + mi * 16 + lr + half * 8;
                float2 v = make_float2(acc[mi][ni][half*2 + 0] * scale + bv0,
                                       acc[mi][ni][half*2 + 1] * scale + bv1);
                if (HEAD_SPLIT) {
                    int b_ = row >> 10, rr = row & 1023;
                    int h = col >> 6, d = col & 63;
                    *(float2*)&C[(((size_t)(b_ * NH + h) * NT + rr) * HD + d)] = v;
                } else {
                    *(float2*)&C[(size_t)row * DIMC + col] = v;
                }
            }
        }
    }
}

// fused QKV: blockIdx.z selects (W, dst, scale)
__global__ __launch_bounds__(256, 2) void qkv_tf32(
    const float* __restrict__ x,
    const float* __restrict__ Wq, const float* __restrict__ Wk,
    const float* __restrict__ Wv,
    float* __restrict__ q, float* __restrict__ k, float* __restrict__ v)
{
    int z = blockIdx.z;
    const float* Bm = (z == 0) ? Wq : (z == 1) ? Wk : Wv;
    float* C = (z == 0) ? q : (z == 1) ? k : v;
    float scale = (z == 0) ? 0.125f : 1.0f;
    proj_body<1>(x, Bm, C, nullptr, scale);
}

__global__ __launch_bounds__(256, 2) void outproj_tf32(
    const float* __restrict__ A, const float* __restrict__ Bm,
    float* __restrict__ C, const float* __restrict__ bias)
{
    proj_body<0>(A, Bm, C, bias, 1.0f);
}

// ============================================================
// score_tf32: per (b,h): S = Q(1024x64) @ K^T. 128x128 tile,
// whole K=64 resident in smem (tf32 stored once).
// ============================================================
__global__ __launch_bounds__(256, 2) void score_tf32(
    const float* __restrict__ Q, const float* __restrict__ Kp,
    float* __restrict__ S)
{
    extern __shared__ float sm[];
    float (*Qs)[68] = (float(*)[68])sm;
    float (*Ks)[68] = (float(*)[68])(sm + 128 * 68);

    int bh = blockIdx.z;
    const float* Qg = Q + (size_t)bh * NT * HD + (size_t)blockIdx.y * 128 * HD;
    const float* Kg = Kp + (size_t)bh * NT * HD + (size_t)blockIdx.x * 128 * HD;

    int tid = threadIdx.x, lane = tid & 31, wid = tid >> 5;
    int lr = lane >> 2, lc = lane & 3;
    int warp_m = wid & 1, warp_n = wid >> 1;

    int row = tid >> 4, col4 = (tid & 15) * 4;
#pragma unroll
    for (int it = 0; it < 8; it++) {
        int r = it * 16 + row;
        float4 v = *(const float4*)(Qg + (size_t)r * HD + col4);
        Qs[r][col4+0] = __uint_as_float(f2tf(v.x));
        Qs[r][col4+1] = __uint_as_float(f2tf(v.y));
        Qs[r][col4+2] = __uint_as_float(f2tf(v.z));
        Qs[r][col4+3] = __uint_as_float(f2tf(v.w));
        float4 w = *(const float4*)(Kg + (size_t)r * HD + col4);
        Ks[r][col4+0] = __uint_as_float(f2tf(w.x));
        Ks[r][col4+1] = __uint_as_float(f2tf(w.y));
        Ks[r][col4+2] = __uint_as_float(f2tf(w.z));
        Ks[r][col4+3] = __uint_as_float(f2tf(w.w));
    }
    __syncthreads();

    float acc[4][4][4] = {};
    int m0 = warp_m * 64, n0 = warp_n * 32;
#pragma unroll
    for (int kk = 0; kk < 64; kk += 8) {
        unsigned a[4][4], b[4][2];
#pragma unroll
        for (int mi = 0; mi < 4; mi++) {
            int r = m0 + mi * 16 + lr;
            a[mi][0] = __float_as_uint(Qs[r    ][kk + lc]);
            a[mi][1] = __float_as_uint(Qs[r + 8][kk + lc]);
            a[mi][2] = __float_as_uint(Qs[r    ][kk + lc + 4]);
            a[mi][3] = __float_as_uint(Qs[r + 8][kk + lc + 4]);
        }
#pragma unroll
        for (int ni = 0; ni < 4; ni++) {
            int c = n0 + ni * 8 + lr;
            b[ni][0] = __float_as_uint(Ks[c][kk + lc]);
            b[ni][1] = __float_as_uint(Ks[c][kk + lc + 4]);
        }
#pragma unroll
        for (int mi = 0; mi < 4; mi++)
#pragma unroll
            for (int ni = 0; ni < 4; ni++)
                mma8(acc[mi][ni], a[mi][0], a[mi][1], a[mi][2], a[mi][3],
                     b[ni][0], b[ni][1]);
    }

    float* Sg = S + (size_t)bh * NT * NT;
#pragma unroll
    for (int mi = 0; mi < 4; mi++) {
#pragma unroll
        for (int ni = 0; ni < 4; ni++) {
            int c = blockIdx.x * 128 + n0 + ni * 8 + 2 * lc;
#pragma unroll
            for (int half = 0; half < 2; half++) {
                int r = blockIdx.y * 128 + m0 + mi * 16 + lr + half * 8;
                *(float2*)&Sg[(size_t)r * NT + c] =
                    make_float2(acc[mi][ni][half*2], acc[mi][ni][half*2 + 1]);
            }
        }
    }
}

// ============================================================
// Fused talking-heads softmax; 2 query rows per CTA, 768 thr.
// smem: 2 x 12 x 1024 floats (96 KB) + weights.
// ============================================================
__global__ __launch_bounds__(768) void softmax_mix_kernel(
    float* __restrict__ S, const float* __restrict__ Wl,
    const float* __restrict__ bl, const float* __restrict__ Ww,
    const float* __restrict__ bw)
{
    extern __shared__ float sm[];
    float* buf = sm;                 // [2][12][1024]
    float* wl  = sm + 24576;         // 144
    float* ww  = wl + 144;           // 144
    float* blv = ww + 144;           // 12
    float* bwv = blv + 12;           // 12

    int tid = threadIdx.x;
    int i0 = blockIdx.x * 2, b = blockIdx.y;
    if (tid < 144)               wl[tid]        = Wl[tid];
    if (tid >= 160 && tid < 304) ww[tid - 160]  = Ww[tid - 160];
    if (tid >= 320 && tid < 332) blv[tid - 320] = bl[tid - 320];
    if (tid >= 352 && tid < 364) bwv[tid - 352] = bw[tid - 352];

    size_t base = (size_t)b * NH * NT * NT + (size_t)i0 * NT;  // + h*NT*NT + r*NT
    // load 2 rows x 12 heads (6144 float4)
    for (int t = tid; t < 6144; t += 768) {
        int r = t / 3072, rem = t % 3072;
        int h = rem >> 8, j4 = (rem & 255) * 4;
        *(float4*)&buf[r * 12288 + h * 1024 + j4] =
            *(const float4*)&S[base + (size_t)h * (NT * NT) + (size_t)r * NT + j4];
    }
    __syncthreads();

    // pre-softmax mix
    for (int idx = tid; idx < 2048; idx += 768) {
        int r = idx >> 10, j = idx & 1023;
        float* bf = buf + r * 12288;
        float s[12];
#pragma unroll
        for (int h = 0; h < 12; h++) s[h] = bf[h * 1024 + j];
#pragma unroll
        for (int g = 0; g < 12; g++) {
            float m = blv[g];
#pragma unroll
            for (int h = 0; h < 12; h++) m = fmaf(wl[g * 12 + h], s[h], m);
            bf[g * 1024 + j] = m;
        }
    }
    __syncthreads();

    // per-(row,head) softmax: 24 warps
    {
        int w = tid >> 5, lane = tid & 31;
        int r = (w < 12) ? 0 : 1;
        int h = (w < 12) ? w : w - 12;
        float* row = buf + r * 12288 + h * 1024;
        float mx = -1e30f;
        for (int j = lane; j < 1024; j += 32) mx = fmaxf(mx, row[j]);
#pragma unroll
        for (int o = 16; o; o >>= 1) mx = fmaxf(mx, __shfl_xor_sync(0xffffffffu, mx, o));
        float sum = 0.f;
        float e[32];
        int t = 0;
        for (int j = lane; j < 1024; j += 32, t++) {
            float ev = __expf(row[j] - mx);
            e[t] = ev; sum += ev;
        }
#pragma unroll
        for (int o = 16; o; o >>= 1) sum += __shfl_xor_sync(0xffffffffu, sum, o);
        float rinv = 1.f / sum;
        t = 0;
        for (int j = lane; j < 1024; j += 32, t++) row[j] = e[t] * rinv;
    }
    __syncthreads();

    // post-softmax mix (in place)
    for (int idx = tid; idx < 2048; idx += 768) {
        int r = idx >> 10, j = idx & 1023;
        float* bf = buf + r * 12288;
        float p[12];
#pragma unroll
        for (int h = 0; h < 12; h++) p[h] = bf[h * 1024 + j];
#pragma unroll
        for (int g = 0; g < 12; g++) {
            float m = bwv[g];
#pragma unroll
            for (int h = 0; h < 12; h++) m = fmaf(ww[g * 12 + h], p[h], m);
            bf[g * 1024 + j] = m;
        }
    }
    __syncthreads();

    for (int t = tid; t < 6144; t += 768) {
        int r = t / 3072, rem = t % 3072;
        int g = rem >> 8, j4 = (rem & 255) * 4;
        *(float4*)&S[base + (size_t)g * (NT * NT) + (size_t)r * NT + j4] =
            *(const float4*)&buf[r * 12288 + g * 1024 + j4];
    }
}

// ============================================================
// av_tf32: per (b,h): O(1024x64) = P(1024x1024) @ V(1024x64).
// 64x64 tile, BK=32, 2-stage cp.async, 256 thr, warp 16x32,
// 4 CTAs/SM.
// ============================================================
__global__ __launch_bounds__(256, 4) void av_tf32(
    const float* __restrict__ P, const float* __restrict__ V,
    float* __restrict__ O)
{
    extern __shared__ float sm[];
    float* Ps = sm;                // [2][64][36]
    float* Vs = sm + 2 * 2304;     // [2][32][72]

    int bh = blockIdx.y;
    int b = bh / NH, h = bh % NH;
    const float* Pg = P + (size_t)bh * NT * NT + (size_t)blockIdx.x * 64 * NT;
    const float* Vg = V + (size_t)bh * NT * HD;

    int tid = threadIdx.x, lane = tid & 31, wid = tid >> 5;
    int lr = lane >> 2, lc = lane & 3;
    int m0 = (wid & 3) * 16, n0 = (wid >> 2) * 32;

#define AV_LOAD(s, k0) do {                                            \
    float* Pd = Ps + (s) * 2304;                                       \
    float* Vd = Vs + (s) * 2304;                                       \
    _Pragma("unroll")                                                  \
    for (int i_ = 0; i_ < 2; i_++) {                                   \
        int t_ = tid + i_ * 256;                                       \
        int r_ = t_ >> 3, c_ = (t_ & 7) * 4;                           \
        cp16(&Pd[r_ * 36 + c_], Pg + (size_t)r_ * NT + (k0) + c_);     \
        int vr_ = t_ >> 4, vc_ = (t_ & 15) * 4;                        \
        cp16(&Vd[vr_ * 72 + vc_], Vg + (size_t)((k0) + vr_) * HD + vc_); \
    }                                                                  \
    CP_COMMIT;                                                         \
} while (0)

    AV_LOAD(0, 0);

    float acc[4][4] = {};
    const int NITER = NT / 32;   // 32
    for (int it = 0; it < NITER; it++) {
        if (it + 1 < NITER) AV_LOAD((it + 1) & 1, (it + 1) * 32);
        else CP_COMMIT;
        CP_WAIT1;
        __syncthreads();
        int s = it & 1;
        const float* Pq = Ps + s * 2304;
        const float* Vq = Vs + s * 2304;
#pragma unroll
        for (int kk = 0; kk < 32; kk += 8) {
            unsigned a[4], bfr[4][2];
            {
                int r = m0 + lr;
                a[0] = ld_tf(&Pq[r * 36 + kk + lc]);
                a[1] = ld_tf(&Pq[(r + 8) * 36 + kk + lc]);
                a[2] = ld_tf(&Pq[r * 36 + kk + lc + 4]);
                a[3] = ld_tf(&Pq[(r + 8) * 36 + kk + lc + 4]);
            }
#pragma unroll
            for (int ni = 0; ni < 4; ni++) {
                int c = n0 + ni * 8 + lr;
                bfr[ni][0] = ld_tf(&Vq[(kk + lc) * 72 + c]);
                bfr[ni][1] = ld_tf(&Vq[(kk + lc + 4) * 72 + c]);
            }
#pragma unroll
            for (int ni = 0; ni < 4; ni++)
                mma8(acc[ni], a[0], a[1], a[2], a[3], bfr[ni][0], bfr[ni][1]);
        }
        __syncthreads();
    }
#undef AV_LOAD

#pragma unroll
    for (int ni = 0; ni < 4; ni++) {
        int col = n0 + ni * 8 + 2 * lc;
#pragma unroll
        for (int half = 0; half < 2; half++) {
            int row = blockIdx.x * 64 + m0 + lr + half * 8;
            *(float2*)&O[(size_t)(b * NT + row) * DIMC + h * HD + col] =
                make_float2(acc[ni][half*2], acc[ni][half*2 + 1]);
        }
    }
}

// ============================================================
extern "C" void kernel_launch(void* const* d_in, const int* in_sizes, int n_in,
                              void* d_out, int out_size)
{
    const float* x  = (const float*)d_in[0];
    const float* Wq = (const float*)d_in[1];
    const float* Wk = (const float*)d_in[2];
    const float* Wv = (const float*)d_in[3];
    const float* Wl = (const float*)d_in[4];
    const float* bl = (const float*)d_in[5];
    const float* Ww = (const float*)d_in[6];
    const float* bw = (const float*)d_in[7];
    const float* Wp = (const float*)d_in[8];
    const float* bp = (const float*)d_in[9];
    float* out = (float*)d_out;

    float *gq, *gk, *gv, *gS, *gO;
    cudaGetSymbolAddress((void**)&gq, g_q);
    cudaGetSymbolAddress((void**)&gk, g_k);
    cudaGetSymbolAddress((void**)&gv, g_v);
    cudaGetSymbolAddress((void**)&gS, g_S);
    cudaGetSymbolAddress((void**)&gO, g_O);

    int proj_smem = 3 * (128*20 + 16*136) * (int)sizeof(float);      // 56832
    cudaFuncSetAttribute(qkv_tf32,
                         cudaFuncAttributeMaxDynamicSharedMemorySize, proj_smem);
    cudaFuncSetAttribute(outproj_tf32,
                         cudaFuncAttributeMaxDynamicSharedMemorySize, proj_smem);
    int score_smem = 2 * 128 * 68 * (int)sizeof(float);              // 69632
    cudaFuncSetAttribute(score_tf32,
                         cudaFuncAttributeMaxDynamicSharedMemorySize, score_smem);
    int av_smem = 2 * (64*36 + 32*72) * (int)sizeof(float);          // 36864
    cudaFuncSetAttribute(av_tf32,
                         cudaFuncAttributeMaxDynamicSharedMemorySize, av_smem);
    int smbytes = (2 * 12 * 1024 + 144 + 144 + 12 + 12) * (int)sizeof(float);
    cudaFuncSetAttribute(softmax_mix_kernel,
                         cudaFuncAttributeMaxDynamicSharedMemorySize, smbytes);

    // QKV projections, one launch -> [b,h,n,d]; Q pre-scaled
    qkv_tf32<<<dim3(6, 64, 3), 256, proj_smem>>>(x, Wq, Wk, Wv, gq, gk, gv);

    // raw scores S = Q K^T
    score_tf32<<<dim3(8, 8, 96), 256, score_smem>>>(gq, gk, gS);

    // fused pre-mix + softmax + post-mix (in place on gS), 2 rows/CTA
    softmax_mix_kernel<<<dim3(512, 8), 768, smbytes>>>(gS, Wl, bl, Ww, bw);

    // attn @ V -> [tok, dim]
    av_tf32<<<dim3(16, 96), 256, av_smem>>>(gS, gv, gO);

    // final projection + bias
    outproj_tf32<<<dim3(6, 64), 256, proj_smem>>>(gO, Wp, out, bp);
}

// round 5
// speedup vs baseline: 1.1821x; 1.1821x over previous
#include <cuda_runtime.h>
#include <math.h>

#define DIMC 768
#define NH 12
#define HD 64
#define NB 8
#define NT 1024
#define M_TOK (NB*NT)   // 8192

// ---- scratch (device globals: no allocations allowed) ----
__device__ float g_q[NB*NH*NT*HD];          // [b,h,n,d], Q pre-scaled
__device__ float g_k[NB*NH*NT*HD];
__device__ float g_v[NB*NH*NT*HD];
__device__ float g_S[(size_t)NB*NH*NT*NT];  // 402 MB scores / probs (in place)
__device__ float g_O[(size_t)M_TOK*DIMC];   // [tok, dim]

// ---------- helpers ----------
__device__ __forceinline__ unsigned f2tf(float f) {
    unsigned u; asm("cvt.rna.tf32.f32 %0, %1;" : "=r"(u) : "f"(f)); return u;
}
__device__ __forceinline__ unsigned ld_tf(const float* p) { return f2tf(*p); }
__device__ __forceinline__ void mma8(float* d, unsigned a0, unsigned a1,
                                     unsigned a2, unsigned a3,
                                     unsigned b0, unsigned b1) {
    asm volatile(
        "mma.sync.aligned.m16n8k8.row.col.f32.tf32.tf32.f32 "
        "{%0,%1,%2,%3},{%4,%5,%6,%7},{%8,%9},{%0,%1,%2,%3};"
        : "+f"(d[0]), "+f"(d[1]), "+f"(d[2]), "+f"(d[3])
        : "r"(a0), "r"(a1), "r"(a2), "r"(a3), "r"(b0), "r"(b1));
}
__device__ __forceinline__ void cp16(void* s, const void* g) {
    unsigned sa = (unsigned)__cvta_generic_to_shared(s);
    asm volatile("cp.async.ca.shared.global [%0], [%1], 16;" :: "r"(sa), "l"(g));
}
#define CP_COMMIT asm volatile("cp.async.commit_group;")
#define CP_WAIT1  asm volatile("cp.async.wait_group 1;")

// ============================================================
// proj body: C[.,768] = scale*(A @ B[768,768]) (+bias)
// 128x128 tile, BK=16, 3-stage cp.async, 256 thr, warp 64x32.
// ============================================================
template<int HEAD_SPLIT>
__device__ __forceinline__ void proj_body(
    const float* __restrict__ A, const float* __restrict__ Bm,
    float* __restrict__ C, const float* __restrict__ bias, float scale)
{
    extern __shared__ float sm[];
    float* As = sm;               // [3][128][20]
    float* Bs = sm + 3 * 2560;    // [3][16][136]

    int tid = threadIdx.x, lane = tid & 31, wid = tid >> 5;
    int warp_m = wid & 1, warp_n = wid >> 1;
    int rowBase = blockIdx.y * 128, colBase = blockIdx.x * 128;
    int lr = lane >> 2, lc = lane & 3;
    int m0 = warp_m * 64, n0 = warp_n * 32;

    const float* Ap = A + (size_t)rowBase * DIMC;
    const float* Bp = Bm + colBase;

#define PROJ_LOAD(s, k0) do {                                          \
    float* Ad = As + (s) * 2560;                                       \
    float* Bd = Bs + (s) * 2176;                                       \
    _Pragma("unroll")                                                  \
    for (int i_ = 0; i_ < 2; i_++) {                                   \
        int t_ = tid + i_ * 256;                                       \
        int r_ = t_ >> 2, c_ = (t_ & 3) * 4;                           \
        cp16(&Ad[r_ * 20 + c_], Ap + (size_t)r_ * DIMC + (k0) + c_);   \
        int br_ = t_ >> 5, bc_ = (t_ & 31) * 4;                        \
        cp16(&Bd[br_ * 136 + bc_], Bp + (size_t)((k0) + br_) * DIMC + bc_); \
    }                                                                  \
    CP_COMMIT;                                                         \
} while (0)

    PROJ_LOAD(0, 0);
    PROJ_LOAD(1, 16);

    float acc[4][4][4] = {};
    const int NITER = DIMC / 16;   // 48
    for (int it = 0; it < NITER; it++) {
        CP_WAIT1;
        __syncthreads();
        int s = it % 3;
        const float* Aq = As + s * 2560;
        const float* Bq = Bs + s * 2176;
#pragma unroll
        for (int kk = 0; kk < 16; kk += 8) {
            unsigned a[4][4], b[4][2];
#pragma unroll
            for (int mi = 0; mi < 4; mi++) {
                int r = m0 + mi * 16 + lr;
                a[mi][0] = ld_tf(&Aq[r * 20 + kk + lc]);
                a[mi][1] = ld_tf(&Aq[(r + 8) * 20 + kk + lc]);
                a[mi][2] = ld_tf(&Aq[r * 20 + kk + lc + 4]);
                a[mi][3] = ld_tf(&Aq[(r + 8) * 20 + kk + lc + 4]);
            }
#pragma unroll
            for (int ni = 0; ni < 4; ni++) {
                int c = n0 + ni * 8 + lr;
                b[ni][0] = ld_tf(&Bq[(kk + lc) * 136 + c]);
                b[ni][1] = ld_tf(&Bq[(kk + lc + 4) * 136 + c]);
            }
#pragma unroll
            for (int mi = 0; mi < 4; mi++)
#pragma unroll
                for (int ni = 0; ni < 4; ni++)
                    mma8(acc[mi][ni], a[mi][0], a[mi][1], a[mi][2], a[mi][3],
                         b[ni][0], b[ni][1]);
        }
        __syncthreads();
        if (it + 2 < NITER) PROJ_LOAD((it + 2) % 3, (it + 2) * 16);
        else CP_COMMIT;
    }
#undef PROJ_LOAD

#pragma unroll
    for (int mi = 0; mi < 4; mi++) {
#pragma unroll
        for (int ni = 0; ni < 4; ni++) {
            int col = colBase + n0 + ni * 8 + 2 * lc;
            float bv0 = 0.f, bv1 = 0.f;
            if (bias) { bv0 = bias[col]; bv1 = bias[col + 1]; }
#pragma unroll
            for (int half = 0; half < 2; half++) {
                int row = rowBase + m0 + mi * 16 + lr + half * 8;
                float2 v = make_float2(acc[mi][ni][half*2 + 0] * scale + bv0,
                                       acc[mi][ni][half*2 + 1] * scale + bv1);
                if (HEAD_SPLIT) {
                    int b_ = row >> 10, rr = row & 1023;
                    int h = col >> 6, d = col & 63;
                    *(float2*)&C[(((size_t)(b_ * NH + h) * NT + rr) * HD + d)] = v;
                } else {
                    *(float2*)&C[(size_t)row * DIMC + col] = v;
                }
            }
        }
    }
}

// fused QKV: blockIdx.z selects (W, dst, scale)
__global__ __launch_bounds__(256, 2) void qkv_tf32(
    const float* __restrict__ x,
    const float* __restrict__ Wq, const float* __restrict__ Wk,
    const float* __restrict__ Wv,
    float* __restrict__ q, float* __restrict__ k, float* __restrict__ v)
{
    int z = blockIdx.z;
    const float* Bm = (z == 0) ? Wq : (z == 1) ? Wk : Wv;
    float* C = (z == 0) ? q : (z == 1) ? k : v;
    float scale = (z == 0) ? 0.125f : 1.0f;
    proj_body<1>(x, Bm, C, nullptr, scale);
}

__global__ __launch_bounds__(256, 2) void outproj_tf32(
    const float* __restrict__ A, const float* __restrict__ Bm,
    float* __restrict__ C, const float* __restrict__ bias)
{
    proj_body<0>(A, Bm, C, bias, 1.0f);
}

// ============================================================
// score_tf32: per (b,h): S = Q(1024x64) @ K^T. 128x128 tile,
// whole K=64 resident in smem (tf32 stored once).
// ============================================================
__global__ __launch_bounds__(256, 2) void score_tf32(
    const float* __restrict__ Q, const float* __restrict__ Kp,
    float* __restrict__ S)
{
    extern __shared__ float sm[];
    float (*Qs)[68] = (float(*)[68])sm;
    float (*Ks)[68] = (float(*)[68])(sm + 128 * 68);

    int bh = blockIdx.z;
    const float* Qg = Q + (size_t)bh * NT * HD + (size_t)blockIdx.y * 128 * HD;
    const float* Kg = Kp + (size_t)bh * NT * HD + (size_t)blockIdx.x * 128 * HD;

    int tid = threadIdx.x, lane = tid & 31, wid = tid >> 5;
    int lr = lane >> 2, lc = lane & 3;
    int warp_m = wid & 1, warp_n = wid >> 1;

    int row = tid >> 4, col4 = (tid & 15) * 4;
#pragma unroll
    for (int it = 0; it < 8; it++) {
        int r = it * 16 + row;
        float4 v = *(const float4*)(Qg + (size_t)r * HD + col4);
        Qs[r][col4+0] = __uint_as_float(f2tf(v.x));
        Qs[r][col4+1] = __uint_as_float(f2tf(v.y));
        Qs[r][col4+2] = __uint_as_float(f2tf(v.z));
        Qs[r][col4+3] = __uint_as_float(f2tf(v.w));
        float4 w = *(const float4*)(Kg + (size_t)r * HD + col4);
        Ks[r][col4+0] = __uint_as_float(f2tf(w.x));
        Ks[r][col4+1] = __uint_as_float(f2tf(w.y));
        Ks[r][col4+2] = __uint_as_float(f2tf(w.z));
        Ks[r][col4+3] = __uint_as_float(f2tf(w.w));
    }
    __syncthreads();

    float acc[4][4][4] = {};
    int m0 = warp_m * 64, n0 = warp_n * 32;
#pragma unroll
    for (int kk = 0; kk < 64; kk += 8) {
        unsigned a[4][4], b[4][2];
#pragma unroll
        for (int mi = 0; mi < 4; mi++) {
            int r = m0 + mi * 16 + lr;
            a[mi][0] = __float_as_uint(Qs[r    ][kk + lc]);
            a[mi][1] = __float_as_uint(Qs[r + 8][kk + lc]);
            a[mi][2] = __float_as_uint(Qs[r    ][kk + lc + 4]);
            a[mi][3] = __float_as_uint(Qs[r + 8][kk + lc + 4]);
        }
#pragma unroll
        for (int ni = 0; ni < 4; ni++) {
            int c = n0 + ni * 8 + lr;
            b[ni][0] = __float_as_uint(Ks[c][kk + lc]);
            b[ni][1] = __float_as_uint(Ks[c][kk + lc + 4]);
        }
#pragma unroll
        for (int mi = 0; mi < 4; mi++)
#pragma unroll
            for (int ni = 0; ni < 4; ni++)
                mma8(acc[mi][ni], a[mi][0], a[mi][1], a[mi][2], a[mi][3],
                     b[ni][0], b[ni][1]);
    }

    float* Sg = S + (size_t)bh * NT * NT;
#pragma unroll
    for (int mi = 0; mi < 4; mi++) {
#pragma unroll
        for (int ni = 0; ni < 4; ni++) {
            int c = blockIdx.x * 128 + n0 + ni * 8 + 2 * lc;
#pragma unroll
            for (int half = 0; half < 2; half++) {
                int r = blockIdx.y * 128 + m0 + mi * 16 + lr + half * 8;
                *(float2*)&Sg[(size_t)r * NT + c] =
                    make_float2(acc[mi][ni][half*2], acc[mi][ni][half*2 + 1]);
            }
        }
    }
}

// ============================================================
// Fused talking-heads softmax; 1 query row per CTA, 384 thr
// (round-3 proven configuration), float4 global access.
// ============================================================
__global__ __launch_bounds__(384) void softmax_mix_kernel(
    float* __restrict__ S, const float* __restrict__ Wl,
    const float* __restrict__ bl, const float* __restrict__ Ww,
    const float* __restrict__ bw)
{
    extern __shared__ float sm[];
    float* buf = sm;
    float* wl  = sm + 12288;
    float* ww  = wl + 144;
    float* blv = ww + 144;
    float* bwv = blv + 12;

    int tid = threadIdx.x;
    int i = blockIdx.x, b = blockIdx.y;
    if (tid < 144)               wl[tid]       = Wl[tid];
    if (tid >= 160 && tid < 304) ww[tid - 160] = Ww[tid - 160];
    if (tid >= 320 && tid < 332) blv[tid - 320] = bl[tid - 320];
    if (tid >= 352 && tid < 364) bwv[tid - 352] = bw[tid - 352];

    size_t rowbase = (size_t)b * NH * NT * NT + (size_t)i * NT;
    for (int t = tid; t < 3072; t += 384) {
        int h = t >> 8, j4 = (t & 255) * 4;
        *(float4*)&buf[h * 1024 + j4] =
            *(const float4*)&S[rowbase + (size_t)h * (NT * NT) + j4];
    }
    __syncthreads();

    for (int j = tid; j < NT; j += 384) {
        float s[12];
#pragma unroll
        for (int h = 0; h < 12; h++) s[h] = buf[h * 1024 + j];
#pragma unroll
        for (int g = 0; g < 12; g++) {
            float m = blv[g];
#pragma unroll
            for (int h = 0; h < 12; h++) m = fmaf(wl[g * 12 + h], s[h], m);
            buf[g * 1024 + j] = m;
        }
    }
    __syncthreads();

    {
        int w = tid >> 5, lane = tid & 31;
        float* row = buf + w * 1024;
        float mx = -1e30f;
        for (int j = lane; j < 1024; j += 32) mx = fmaxf(mx, row[j]);
#pragma unroll
        for (int o = 16; o; o >>= 1) mx = fmaxf(mx, __shfl_xor_sync(0xffffffffu, mx, o));
        float sum = 0.f;
        float e[32];
        int t = 0;
        for (int j = lane; j < 1024; j += 32, t++) {
            float ev = __expf(row[j] - mx);
            e[t] = ev; sum += ev;
        }
#pragma unroll
        for (int o = 16; o; o >>= 1) sum += __shfl_xor_sync(0xffffffffu, sum, o);
        float rinv = 1.f / sum;
        t = 0;
        for (int j = lane; j < 1024; j += 32, t++) row[j] = e[t] * rinv;
    }
    __syncthreads();

    for (int j = tid; j < NT; j += 384) {
        float p[12];
#pragma unroll
        for (int h = 0; h < 12; h++) p[h] = buf[h * 1024 + j];
#pragma unroll
        for (int g = 0; g < 12; g++) {
            float m = bwv[g];
#pragma unroll
            for (int h = 0; h < 12; h++) m = fmaf(ww[g * 12 + h], p[h], m);
            buf[g * 1024 + j] = m;
        }
    }
    __syncthreads();

    for (int t = tid; t < 3072; t += 384) {
        int g = t >> 8, j4 = (t & 255) * 4;
        *(float4*)&S[rowbase + (size_t)g * (NT * NT) + j4] =
            *(const float4*)&buf[g * 1024 + j4];
    }
}

// ============================================================
// av_tf32: per (b,h): O(1024x64) = P(1024x1024) @ V(1024x64).
// 64x64 tile, BK=32, 2-stage cp.async, 256 thr, warp 16x32,
// 4 CTAs/SM.
// ============================================================
__global__ __launch_bounds__(256, 4) void av_tf32(
    const float* __restrict__ P, const float* __restrict__ V,
    float* __restrict__ O)
{
    extern __shared__ float sm[];
    float* Ps = sm;                // [2][64][36]
    float* Vs = sm + 2 * 2304;     // [2][32][72]

    int bh = blockIdx.y;
    int b = bh / NH, h = bh % NH;
    const float* Pg = P + (size_t)bh * NT * NT + (size_t)blockIdx.x * 64 * NT;
    const float* Vg = V + (size_t)bh * NT * HD;

    int tid = threadIdx.x, lane = tid & 31, wid = tid >> 5;
    int lr = lane >> 2, lc = lane & 3;
    int m0 = (wid & 3) * 16, n0 = (wid >> 2) * 32;

#define AV_LOAD(s, k0) do {                                            \
    float* Pd = Ps + (s) * 2304;                                       \
    float* Vd = Vs + (s) * 2304;                                       \
    _Pragma("unroll")                                                  \
    for (int i_ = 0; i_ < 2; i_++) {                                   \
        int t_ = tid + i_ * 256;                                       \
        int r_ = t_ >> 3, c_ = (t_ & 7) * 4;                           \
        cp16(&Pd[r_ * 36 + c_], Pg + (size_t)r_ * NT + (k0) + c_);     \
        int vr_ = t_ >> 4, vc_ = (t_ & 15) * 4;                        \
        cp16(&Vd[vr_ * 72 + vc_], Vg + (size_t)((k0) + vr_) * HD + vc_); \
    }                                                                  \
    CP_COMMIT;                                                         \
} while (0)

    AV_LOAD(0, 0);

    float acc[4][4] = {};
    const int NITER = NT / 32;   // 32
    for (int it = 0; it < NITER; it++) {
        if (it + 1 < NITER) AV_LOAD((it + 1) & 1, (it + 1) * 32);
        else CP_COMMIT;
        CP_WAIT1;
        __syncthreads();
        int s = it & 1;
        const float* Pq = Ps + s * 2304;
        const float* Vq = Vs + s * 2304;
#pragma unroll
        for (int kk = 0; kk < 32; kk += 8) {
            unsigned a[4], bfr[4][2];
            {
                int r = m0 + lr;
                a[0] = ld_tf(&Pq[r * 36 + kk + lc]);
                a[1] = ld_tf(&Pq[(r + 8) * 36 + kk + lc]);
                a[2] = ld_tf(&Pq[r * 36 + kk + lc + 4]);
                a[3] = ld_tf(&Pq[(r + 8) * 36 + kk + lc + 4]);
            }
#pragma unroll
            for (int ni = 0; ni < 4; ni++) {
                int c = n0 + ni * 8 + lr;
                bfr[ni][0] = ld_tf(&Vq[(kk + lc) * 72 + c]);
                bfr[ni][1] = ld_tf(&Vq[(kk + lc + 4) * 72 + c]);
            }
#pragma unroll
            for (int ni = 0; ni < 4; ni++)
                mma8(acc[ni], a[0], a[1], a[2], a[3], bfr[ni][0], bfr[ni][1]);
        }
        __syncthreads();
    }
#undef AV_LOAD

#pragma unroll
    for (int ni = 0; ni < 4; ni++) {
        int col = n0 + ni * 8 + 2 * lc;
#pragma unroll
        for (int half = 0; half < 2; half++) {
            int row = blockIdx.x * 64 + m0 + lr + half * 8;
            *(float2*)&O[(size_t)(b * NT + row) * DIMC + h * HD + col] =
                make_float2(acc[ni][half*2], acc[ni][half*2 + 1]);
        }
    }
}

// ============================================================
extern "C" void kernel_launch(void* const* d_in, const int* in_sizes, int n_in,
                              void* d_out, int out_size)
{
    const float* x  = (const float*)d_in[0];
    const float* Wq = (const float*)d_in[1];
    const float* Wk = (const float*)d_in[2];
    const float* Wv = (const float*)d_in[3];
    const float* Wl = (const float*)d_in[4];
    const float* bl = (const float*)d_in[5];
    const float* Ww = (const float*)d_in[6];
    const float* bw = (const float*)d_in[7];
    const float* Wp = (const float*)d_in[8];
    const float* bp = (const float*)d_in[9];
    float* out = (float*)d_out;

    float *gq, *gk, *gv, *gS, *gO;
    cudaGetSymbolAddress((void**)&gq, g_q);
    cudaGetSymbolAddress((void**)&gk, g_k);
    cudaGetSymbolAddress((void**)&gv, g_v);
    cudaGetSymbolAddress((void**)&gS, g_S);
    cudaGetSymbolAddress((void**)&gO, g_O);

    int proj_smem = 3 * (128*20 + 16*136) * (int)sizeof(float);      // 56832
    cudaFuncSetAttribute(qkv_tf32,
                         cudaFuncAttributeMaxDynamicSharedMemorySize, proj_smem);
    cudaFuncSetAttribute(outproj_tf32,
                         cudaFuncAttributeMaxDynamicSharedMemorySize, proj_smem);
    int score_smem = 2 * 128 * 68 * (int)sizeof(float);              // 69632
    cudaFuncSetAttribute(score_tf32,
                         cudaFuncAttributeMaxDynamicSharedMemorySize, score_smem);
    int av_smem = 2 * (64*36 + 32*72) * (int)sizeof(float);          // 36864
    cudaFuncSetAttribute(av_tf32,
                         cudaFuncAttributeMaxDynamicSharedMemorySize, av_smem);
    int smbytes = (12 * 1024 + 144 + 144 + 12 + 12) * (int)sizeof(float);
    cudaFuncSetAttribute(softmax_mix_kernel,
                         cudaFuncAttributeMaxDynamicSharedMemorySize, smbytes);

    // QKV projections, one launch -> [b,h,n,d]; Q pre-scaled
    qkv_tf32<<<dim3(6, 64, 3), 256, proj_smem>>>(x, Wq, Wk, Wv, gq, gk, gv);

    // raw scores S = Q K^T
    score_tf32<<<dim3(8, 8, 96), 256, score_smem>>>(gq, gk, gS);

    // fused pre-mix + softmax + post-mix (in place on gS), 1 row/CTA
    softmax_mix_kernel<<<dim3(1024, 8), 384, smbytes>>>(gS, Wl, bl, Ww, bw);

    // attn @ V -> [tok, dim]
    av_tf32<<<dim3(16, 96), 256, av_smem>>>(gS, gv, gO);

    // final projection + bias
    outproj_tf32<<<dim3(6, 64), 256, proj_smem>>>(gO, Wp, out, bp);
}

// round 6
// speedup vs baseline: 1.2171x; 1.0296x over previous
#include <cuda_runtime.h>
#include <cuda_fp16.h>
#include <math.h>

#define DIMC 768
#define NH 12
#define HD 64
#define NB 8
#define NT 1024
#define M_TOK (NB*NT)   // 8192
#define NTNT (NT*NT)

// ---- scratch (device globals: no allocations allowed) ----
__device__ float  g_q[NB*NH*NT*HD];            // [b,h,n,d], Q pre-scaled, tf32-rounded
__device__ float  g_k[NB*NH*NT*HD];            // [b,h,n,d], tf32-rounded
__device__ __half g_vt[NB*NH*HD*NT];           // [b,h,d,tok] fp16 (transposed V)
__device__ __half g_S[(size_t)NB*NH*NT*NT];    // 201 MB scores / probs fp16 (in place)
__device__ float  g_O[(size_t)M_TOK*DIMC];     // [tok, dim]

// ---------- helpers ----------
__device__ __forceinline__ unsigned f2tf(float f) {
    unsigned u; asm("cvt.rna.tf32.f32 %0, %1;" : "=r"(u) : "f"(f)); return u;
}
__device__ __forceinline__ unsigned ld_tf(const float* p) { return f2tf(*p); }
__device__ __forceinline__ void mma8(float* d, unsigned a0, unsigned a1,
                                     unsigned a2, unsigned a3,
                                     unsigned b0, unsigned b1) {
    asm volatile(
        "mma.sync.aligned.m16n8k8.row.col.f32.tf32.tf32.f32 "
        "{%0,%1,%2,%3},{%4,%5,%6,%7},{%8,%9},{%0,%1,%2,%3};"
        : "+f"(d[0]), "+f"(d[1]), "+f"(d[2]), "+f"(d[3])
        : "r"(a0), "r"(a1), "r"(a2), "r"(a3), "r"(b0), "r"(b1));
}
__device__ __forceinline__ void mma16h(float* d, unsigned a0, unsigned a1,
                                       unsigned a2, unsigned a3,
                                       unsigned b0, unsigned b1) {
    asm volatile(
        "mma.sync.aligned.m16n8k16.row.col.f32.f16.f16.f32 "
        "{%0,%1,%2,%3},{%4,%5,%6,%7},{%8,%9},{%0,%1,%2,%3};"
        : "+f"(d[0]), "+f"(d[1]), "+f"(d[2]), "+f"(d[3])
        : "r"(a0), "r"(a1), "r"(a2), "r"(a3), "r"(b0), "r"(b1));
}
__device__ __forceinline__ void cp16(void* s, const void* g) {
    unsigned sa = (unsigned)__cvta_generic_to_shared(s);
    asm volatile("cp.async.ca.shared.global [%0], [%1], 16;" :: "r"(sa), "l"(g));
}
#define CP_COMMIT asm volatile("cp.async.commit_group;")
#define CP_WAIT1  asm volatile("cp.async.wait_group 1;")

// ============================================================
// proj body: MODE 0: plain fp32 C (+bias). MODE 1: head-split,
// tf32-rounded fp32. MODE 2: head-split TRANSPOSED fp16 ([b,h,d,tok]).
// 128x128 tile, BK=16, 3-stage cp.async, 256 thr, warp 64x32.
// ============================================================
template<int MODE>
__device__ __forceinline__ void proj_body(
    const float* __restrict__ A, const float* __restrict__ Bm,
    float* __restrict__ Cf, __half* __restrict__ Ch,
    const float* __restrict__ bias, float scale)
{
    extern __shared__ float sm[];
    float* As = sm;               // [3][128][20]
    float* Bs = sm + 3 * 2560;    // [3][16][136]

    int tid = threadIdx.x, lane = tid & 31, wid = tid >> 5;
    int warp_m = wid & 1, warp_n = wid >> 1;
    int rowBase = blockIdx.y * 128, colBase = blockIdx.x * 128;
    int lr = lane >> 2, lc = lane & 3;
    int m0 = warp_m * 64, n0 = warp_n * 32;

    const float* Ap = A + (size_t)rowBase * DIMC;
    const float* Bp = Bm + colBase;

#define PROJ_LOAD(s, k0) do {                                          \
    float* Ad = As + (s) * 2560;                                       \
    float* Bd = Bs + (s) * 2176;                                       \
    _Pragma("unroll")                                                  \
    for (int i_ = 0; i_ < 2; i_++) {                                   \
        int t_ = tid + i_ * 256;                                       \
        int r_ = t_ >> 2, c_ = (t_ & 3) * 4;                           \
        cp16(&Ad[r_ * 20 + c_], Ap + (size_t)r_ * DIMC + (k0) + c_);   \
        int br_ = t_ >> 5, bc_ = (t_ & 31) * 4;                        \
        cp16(&Bd[br_ * 136 + bc_], Bp + (size_t)((k0) + br_) * DIMC + bc_); \
    }                                                                  \
    CP_COMMIT;                                                         \
} while (0)

    PROJ_LOAD(0, 0);
    PROJ_LOAD(1, 16);

    float acc[4][4][4] = {};
    const int NITER = DIMC / 16;   // 48
    for (int it = 0; it < NITER; it++) {
        CP_WAIT1;
        __syncthreads();
        int s = it % 3;
        const float* Aq = As + s * 2560;
        const float* Bq = Bs + s * 2176;
#pragma unroll
        for (int kk = 0; kk < 16; kk += 8) {
            unsigned a[4][4], b[4][2];
#pragma unroll
            for (int mi = 0; mi < 4; mi++) {
                int r = m0 + mi * 16 + lr;
                a[mi][0] = ld_tf(&Aq[r * 20 + kk + lc]);
                a[mi][1] = ld_tf(&Aq[(r + 8) * 20 + kk + lc]);
                a[mi][2] = ld_tf(&Aq[r * 20 + kk + lc + 4]);
                a[mi][3] = ld_tf(&Aq[(r + 8) * 20 + kk + lc + 4]);
            }
#pragma unroll
            for (int ni = 0; ni < 4; ni++) {
                int c = n0 + ni * 8 + lr;
                b[ni][0] = ld_tf(&Bq[(kk + lc) * 136 + c]);
                b[ni][1] = ld_tf(&Bq[(kk + lc + 4) * 136 + c]);
            }
#pragma unroll
            for (int mi = 0; mi < 4; mi++)
#pragma unroll
                for (int ni = 0; ni < 4; ni++)
                    mma8(acc[mi][ni], a[mi][0], a[mi][1], a[mi][2], a[mi][3],
                         b[ni][0], b[ni][1]);
        }
        __syncthreads();
        if (it + 2 < NITER) PROJ_LOAD((it + 2) % 3, (it + 2) * 16);
        else CP_COMMIT;
    }
#undef PROJ_LOAD

#pragma unroll
    for (int mi = 0; mi < 4; mi++) {
#pragma unroll
        for (int ni = 0; ni < 4; ni++) {
            int col = colBase + n0 + ni * 8 + 2 * lc;
            float bv0 = 0.f, bv1 = 0.f;
            if (MODE == 0 && bias) { bv0 = bias[col]; bv1 = bias[col + 1]; }
#pragma unroll
            for (int half_ = 0; half_ < 2; half_++) {
                int row = rowBase + m0 + mi * 16 + lr + half_ * 8;
                float v0 = acc[mi][ni][half_*2 + 0] * scale + bv0;
                float v1 = acc[mi][ni][half_*2 + 1] * scale + bv1;
                if (MODE == 0) {
                    *(float2*)&Cf[(size_t)row * DIMC + col] = make_float2(v0, v1);
                } else {
                    int b_ = row >> 10, rr = row & 1023;
                    int h = col >> 6, d = col & 63;
                    if (MODE == 1) {
                        float2 v = make_float2(__uint_as_float(f2tf(v0)),
                                               __uint_as_float(f2tf(v1)));
                        *(float2*)&Cf[(((size_t)(b_ * NH + h) * NT + rr) * HD + d)] = v;
                    } else {  // MODE 2: transposed fp16 V
                        size_t base = ((size_t)(b_ * NH + h) * HD + d) * NT + rr;
                        Ch[base]      = __float2half(v0);
                        Ch[base + NT] = __float2half(v1);
                    }
                }
            }
        }
    }
}

// fused QKV: blockIdx.z selects (W, dst, scale, layout)
__global__ __launch_bounds__(256, 2) void qkv_tf32(
    const float* __restrict__ x,
    const float* __restrict__ Wq, const float* __restrict__ Wk,
    const float* __restrict__ Wv,
    float* __restrict__ q, float* __restrict__ k, __half* __restrict__ vt)
{
    int z = blockIdx.z;
    if (z == 0)      proj_body<1>(x, Wq, q, nullptr, nullptr, 0.125f);
    else if (z == 1) proj_body<1>(x, Wk, k, nullptr, nullptr, 1.0f);
    else             proj_body<2>(x, Wv, nullptr, vt, nullptr, 1.0f);
}

__global__ __launch_bounds__(256, 2) void outproj_tf32(
    const float* __restrict__ A, const float* __restrict__ Bm,
    float* __restrict__ C, const float* __restrict__ bias)
{
    proj_body<0>(A, Bm, C, nullptr, bias, 1.0f);
}

// ============================================================
// score_tf32: per (b,h): S = Q(1024x64) @ K^T. 128x128 tile,
// whole K=64 resident in smem (inputs pre-rounded tf32).
// Writes S as fp16.
// ============================================================
__global__ __launch_bounds__(256, 2) void score_tf32(
    const float* __restrict__ Q, const float* __restrict__ Kp,
    __half* __restrict__ S)
{
    extern __shared__ float sm[];
    float (*Qs)[68] = (float(*)[68])sm;
    float (*Ks)[68] = (float(*)[68])(sm + 128 * 68);

    int bh = blockIdx.z;
    const float* Qg = Q + (size_t)bh * NT * HD + (size_t)blockIdx.y * 128 * HD;
    const float* Kg = Kp + (size_t)bh * NT * HD + (size_t)blockIdx.x * 128 * HD;

    int tid = threadIdx.x, lane = tid & 31, wid = tid >> 5;
    int lr = lane >> 2, lc = lane & 3;
    int warp_m = wid & 1, warp_n = wid >> 1;

    int row = tid >> 4, col4 = (tid & 15) * 4;
#pragma unroll
    for (int it = 0; it < 8; it++) {
        int r = it * 16 + row;
        *(float4*)&Qs[r][col4] = *(const float4*)(Qg + (size_t)r * HD + col4);
        *(float4*)&Ks[r][col4] = *(const float4*)(Kg + (size_t)r * HD + col4);
    }
    __syncthreads();

    float acc[4][4][4] = {};
    int m0 = warp_m * 64, n0 = warp_n * 32;
#pragma unroll
    for (int kk = 0; kk < 64; kk += 8) {
        unsigned a[4][4], b[4][2];
#pragma unroll
        for (int mi = 0; mi < 4; mi++) {
            int r = m0 + mi * 16 + lr;
            a[mi][0] = __float_as_uint(Qs[r    ][kk + lc]);
            a[mi][1] = __float_as_uint(Qs[r + 8][kk + lc]);
            a[mi][2] = __float_as_uint(Qs[r    ][kk + lc + 4]);
            a[mi][3] = __float_as_uint(Qs[r + 8][kk + lc + 4]);
        }
#pragma unroll
        for (int ni = 0; ni < 4; ni++) {
            int c = n0 + ni * 8 + lr;
            b[ni][0] = __float_as_uint(Ks[c][kk + lc]);
            b[ni][1] = __float_as_uint(Ks[c][kk + lc + 4]);
        }
#pragma unroll
        for (int mi = 0; mi < 4; mi++)
#pragma unroll
            for (int ni = 0; ni < 4; ni++)
                mma8(acc[mi][ni], a[mi][0], a[mi][1], a[mi][2], a[mi][3],
                     b[ni][0], b[ni][1]);
    }

    __half* Sg = S + (size_t)bh * NTNT;
#pragma unroll
    for (int mi = 0; mi < 4; mi++) {
#pragma unroll
        for (int ni = 0; ni < 4; ni++) {
            int c = blockIdx.x * 128 + n0 + ni * 8 + 2 * lc;
#pragma unroll
            for (int half_ = 0; half_ < 2; half_++) {
                int r = blockIdx.y * 128 + m0 + mi * 16 + lr + half_ * 8;
                *(__half2*)&Sg[(size_t)r * NT + c] =
                    __floats2half2_rn(acc[mi][ni][half_*2], acc[mi][ni][half_*2 + 1]);
            }
        }
    }
}

// ============================================================
// Fused talking-heads softmax; fp16 in/out, fp32 internal.
// 1 query row per CTA, 384 thr.
// ============================================================
__global__ __launch_bounds__(384) void softmax_mix_kernel(
    __half* __restrict__ S, const float* __restrict__ Wl,
    const float* __restrict__ bl, const float* __restrict__ Ww,
    const float* __restrict__ bw)
{
    extern __shared__ float sm[];
    float* buf = sm;
    float* wl  = sm + 12288;
    float* ww  = wl + 144;
    float* blv = ww + 144;
    float* bwv = blv + 12;

    int tid = threadIdx.x;
    int i = blockIdx.x, b = blockIdx.y;
    if (tid < 144)               wl[tid]       = Wl[tid];
    if (tid >= 160 && tid < 304) ww[tid - 160] = Ww[tid - 160];
    if (tid >= 320 && tid < 332) blv[tid - 320] = bl[tid - 320];
    if (tid >= 352 && tid < 364) bwv[tid - 352] = bw[tid - 352];

    size_t rowbase = (size_t)b * NH * NTNT + (size_t)i * NT;
    // load 12 x 1024 halves (uint4 = 8 halves)
    for (int t = tid; t < 1536; t += 384) {
        int h = t >> 7, j8 = (t & 127) * 8;
        uint4 r4 = *(const uint4*)&S[rowbase + (size_t)h * NTNT + j8];
        const __half2* hp = (const __half2*)&r4;
        float* dst = buf + h * 1024 + j8;
#pragma unroll
        for (int q = 0; q < 4; q++) {
            float2 f = __half22float2(hp[q]);
            dst[2*q] = f.x; dst[2*q + 1] = f.y;
        }
    }
    __syncthreads();

    for (int j = tid; j < NT; j += 384) {
        float s[12];
#pragma unroll
        for (int h = 0; h < 12; h++) s[h] = buf[h * 1024 + j];
#pragma unroll
        for (int g = 0; g < 12; g++) {
            float m = blv[g];
#pragma unroll
            for (int h = 0; h < 12; h++) m = fmaf(wl[g * 12 + h], s[h], m);
            buf[g * 1024 + j] = m;
        }
    }
    __syncthreads();

    {
        int w = tid >> 5, lane = tid & 31;
        float* row = buf + w * 1024;
        float mx = -1e30f;
        for (int j = lane; j < 1024; j += 32) mx = fmaxf(mx, row[j]);
#pragma unroll
        for (int o = 16; o; o >>= 1) mx = fmaxf(mx, __shfl_xor_sync(0xffffffffu, mx, o));
        float sum = 0.f;
        float e[32];
        int t = 0;
        for (int j = lane; j < 1024; j += 32, t++) {
            float ev = __expf(row[j] - mx);
            e[t] = ev; sum += ev;
        }
#pragma unroll
        for (int o = 16; o; o >>= 1) sum += __shfl_xor_sync(0xffffffffu, sum, o);
        float rinv = 1.f / sum;
        t = 0;
        for (int j = lane; j < 1024; j += 32, t++) row[j] = e[t] * rinv;
    }
    __syncthreads();

    for (int j = tid; j < NT; j += 384) {
        float p[12];
#pragma unroll
        for (int h = 0; h < 12; h++) p[h] = buf[h * 1024 + j];
#pragma unroll
        for (int g = 0; g < 12; g++) {
            float m = bwv[g];
#pragma unroll
            for (int h = 0; h < 12; h++) m = fmaf(ww[g * 12 + h], p[h], m);
            buf[g * 1024 + j] = m;
        }
    }
    __syncthreads();

    for (int t = tid; t < 1536; t += 384) {
        int g = t >> 7, j8 = (t & 127) * 8;
        const float* src = buf + g * 1024 + j8;
        uint4 outv;
        __half2* hp = (__half2*)&outv;
#pragma unroll
        for (int q = 0; q < 4; q++)
            hp[q] = __floats2half2_rn(src[2*q], src[2*q + 1]);
        *(uint4*)&S[rowbase + (size_t)g * NTNT + j8] = outv;
    }
}

// ============================================================
// av_f16: per (b,h): O(1024x64) = P(1024x1024) @ V(1024x64),
// fp16 MMA m16n8k16, fp32 accum. V pre-transposed [d][tok].
// 64x64 tile, BK=32, 2-stage cp.async, 256 thr.
// smem: Ps[2][64][40]h, Vs[2][64][40]h (20.5 KB).
// ============================================================
__global__ __launch_bounds__(256, 4) void av_f16(
    const __half* __restrict__ P, const __half* __restrict__ Vt,
    float* __restrict__ O)
{
    extern __shared__ float sm[];
    __half* Ps = (__half*)sm;            // [2][64][40]
    __half* Vs = Ps + 2 * 2560;          // [2][64][40]

    int bh = blockIdx.y;
    int b = bh / NH, h = bh % NH;
    const __half* Pg = P + (size_t)bh * NTNT + (size_t)blockIdx.x * 64 * NT;
    const __half* Vg = Vt + (size_t)bh * HD * NT;   // [d][tok]

    int tid = threadIdx.x, lane = tid & 31, wid = tid >> 5;
    int lr = lane >> 2, lc = lane & 3;
    int m0 = (wid & 3) * 16, n0 = (wid >> 2) * 32;

    int ldr = tid >> 2, ldc = (tid & 3) * 8;   // row 0..63, col chunk of 8 halves

#define AV_LOAD(s, k0) do {                                             \
    __half* Pd = Ps + (s) * 2560;                                       \
    __half* Vd = Vs + (s) * 2560;                                       \
    cp16(&Pd[ldr * 40 + ldc], Pg + (size_t)ldr * NT + (k0) + ldc);      \
    cp16(&Vd[ldr * 40 + ldc], Vg + (size_t)ldr * NT + (k0) + ldc);      \
    CP_COMMIT;                                                          \
} while (0)

    AV_LOAD(0, 0);

    float acc[4][4] = {};
    const int NITER = NT / 32;   // 32
    for (int it = 0; it < NITER; it++) {
        if (it + 1 < NITER) AV_LOAD((it + 1) & 1, (it + 1) * 32);
        else CP_COMMIT;
        CP_WAIT1;
        __syncthreads();
        int s = it & 1;
        const __half* Pq = Ps + s * 2560;
        const __half* Vq = Vs + s * 2560;
#pragma unroll
        for (int kk = 0; kk < 32; kk += 16) {
            unsigned a0, a1, a2, a3;
            {
                int rb = (m0 + lr) * 40 + kk + 2 * lc;
                a0 = *(const unsigned*)&Pq[rb];
                a1 = *(const unsigned*)&Pq[rb + 8 * 40];
                a2 = *(const unsigned*)&Pq[rb + 8];
                a3 = *(const unsigned*)&Pq[rb + 8 * 40 + 8];
            }
#pragma unroll
            for (int ni = 0; ni < 4; ni++) {
                int nb = (n0 + ni * 8 + lr) * 40 + kk + 2 * lc;
                unsigned b0 = *(const unsigned*)&Vq[nb];
                unsigned b1 = *(const unsigned*)&Vq[nb + 8];
                mma16h(acc[ni], a0, a1, a2, a3, b0, b1);
            }
        }
        __syncthreads();
    }
#undef AV_LOAD

#pragma unroll
    for (int ni = 0; ni < 4; ni++) {
        int col = n0 + ni * 8 + 2 * lc;
#pragma unroll
        for (int half_ = 0; half_ < 2; half_++) {
            int row = blockIdx.x * 64 + m0 + lr + half_ * 8;
            *(float2*)&O[(size_t)(b * NT + row) * DIMC + h * HD + col] =
                make_float2(acc[ni][half_*2], acc[ni][half_*2 + 1]);
        }
    }
}

// ============================================================
extern "C" void kernel_launch(void* const* d_in, const int* in_sizes, int n_in,
                              void* d_out, int out_size)
{
    const float* x  = (const float*)d_in[0];
    const float* Wq = (const float*)d_in[1];
    const float* Wk = (const float*)d_in[2];
    const float* Wv = (const float*)d_in[3];
    const float* Wl = (const float*)d_in[4];
    const float* bl = (const float*)d_in[5];
    const float* Ww = (const float*)d_in[6];
    const float* bw = (const float*)d_in[7];
    const float* Wp = (const float*)d_in[8];
    const float* bp = (const float*)d_in[9];
    float* out = (float*)d_out;

    float *gq, *gk, *gO;
    __half *gvt, *gS;
    cudaGetSymbolAddress((void**)&gq, g_q);
    cudaGetSymbolAddress((void**)&gk, g_k);
    cudaGetSymbolAddress((void**)&gvt, g_vt);
    cudaGetSymbolAddress((void**)&gS, g_S);
    cudaGetSymbolAddress((void**)&gO, g_O);

    int proj_smem = 3 * (128*20 + 16*136) * (int)sizeof(float);      // 56832
    cudaFuncSetAttribute(qkv_tf32,
                         cudaFuncAttributeMaxDynamicSharedMemorySize, proj_smem);
    cudaFuncSetAttribute(outproj_tf32,
                         cudaFuncAttributeMaxDynamicSharedMemorySize, proj_smem);
    int score_smem = 2 * 128 * 68 * (int)sizeof(float);              // 69632
    cudaFuncSetAttribute(score_tf32,
                         cudaFuncAttributeMaxDynamicSharedMemorySize, score_smem);
    int av_smem = 2 * 2 * 2560 * (int)sizeof(__half);                // 20480
    cudaFuncSetAttribute(av_f16,
                         cudaFuncAttributeMaxDynamicSharedMemorySize, av_smem);
    int smbytes = (12 * 1024 + 144 + 144 + 12 + 12) * (int)sizeof(float);
    cudaFuncSetAttribute(softmax_mix_kernel,
                         cudaFuncAttributeMaxDynamicSharedMemorySize, smbytes);

    // QKV projections, one launch; Q pre-scaled; q/k tf32-rounded; V fp16 transposed
    qkv_tf32<<<dim3(6, 64, 3), 256, proj_smem>>>(x, Wq, Wk, Wv, gq, gk, gvt);

    // raw scores S = Q K^T -> fp16
    score_tf32<<<dim3(8, 8, 96), 256, score_smem>>>(gq, gk, gS);

    // fused pre-mix + softmax + post-mix (in place on gS, fp16)
    softmax_mix_kernel<<<dim3(1024, 8), 384, smbytes>>>(gS, Wl, bl, Ww, bw);

    // attn @ V -> [tok, dim], fp16 MMA
    av_f16<<<dim3(16, 96), 256, av_smem>>>(gS, gvt, gO);

    // final projection + bias
    outproj_tf32<<<dim3(6, 64), 256, proj_smem>>>(gO, Wp, out, bp);
}

// round 7
// speedup vs baseline: 1.2511x; 1.0279x over previous
#include <cuda_runtime.h>
#include <cuda_fp16.h>
#include <math.h>

#define DIMC 768
#define NH 12
#define HD 64
#define NB 8
#define NT 1024
#define M_TOK (NB*NT)   // 8192
#define NTNT (NT*NT)

// ---- scratch (device globals: no allocations allowed) ----
__device__ float  g_q[NB*NH*NT*HD];            // [b,h,n,d], Q pre-scaled, tf32-rounded
__device__ float  g_k[NB*NH*NT*HD];            // [b,h,n,d], tf32-rounded
__device__ __half g_vt[NB*NH*HD*NT];           // [b,h,d,tok] fp16 (transposed V)
__device__ __half g_S[(size_t)NB*NH*NT*NT];    // 201 MB scores / probs fp16 (in place)
__device__ float  g_O[(size_t)M_TOK*DIMC];     // [tok, dim]

// ---------- helpers ----------
__device__ __forceinline__ unsigned f2tf(float f) {
    unsigned u; asm("cvt.rna.tf32.f32 %0, %1;" : "=r"(u) : "f"(f)); return u;
}
__device__ __forceinline__ unsigned ld_tf(const float* p) { return f2tf(*p); }
__device__ __forceinline__ void mma8(float* d, unsigned a0, unsigned a1,
                                     unsigned a2, unsigned a3,
                                     unsigned b0, unsigned b1) {
    asm volatile(
        "mma.sync.aligned.m16n8k8.row.col.f32.tf32.tf32.f32 "
        "{%0,%1,%2,%3},{%4,%5,%6,%7},{%8,%9},{%0,%1,%2,%3};"
        : "+f"(d[0]), "+f"(d[1]), "+f"(d[2]), "+f"(d[3])
        : "r"(a0), "r"(a1), "r"(a2), "r"(a3), "r"(b0), "r"(b1));
}
__device__ __forceinline__ void mma16h(float* d, unsigned a0, unsigned a1,
                                       unsigned a2, unsigned a3,
                                       unsigned b0, unsigned b1) {
    asm volatile(
        "mma.sync.aligned.m16n8k16.row.col.f32.f16.f16.f32 "
        "{%0,%1,%2,%3},{%4,%5,%6,%7},{%8,%9},{%0,%1,%2,%3};"
        : "+f"(d[0]), "+f"(d[1]), "+f"(d[2]), "+f"(d[3])
        : "r"(a0), "r"(a1), "r"(a2), "r"(a3), "r"(b0), "r"(b1));
}
__device__ __forceinline__ void cp16(void* s, const void* g) {
    unsigned sa = (unsigned)__cvta_generic_to_shared(s);
    asm volatile("cp.async.ca.shared.global [%0], [%1], 16;" :: "r"(sa), "l"(g));
}
#define CP_COMMIT asm volatile("cp.async.commit_group;")
#define CP_WAIT1  asm volatile("cp.async.wait_group 1;")

// ============================================================
// proj body: MODE 0: plain fp32 C (+bias). MODE 1: head-split,
// tf32-rounded fp32. MODE 2: head-split TRANSPOSED fp16
// ([b,h,d,tok]) via smem staging for coalesced stores.
// 128x128 tile, BK=16, 3-stage cp.async, 256 thr, warp 64x32.
// ============================================================
template<int MODE>
__device__ __forceinline__ void proj_body(
    const float* __restrict__ A, const float* __restrict__ Bm,
    float* __restrict__ Cf, __half* __restrict__ Ch,
    const float* __restrict__ bias, float scale)
{
    extern __shared__ float sm[];
    float* As = sm;               // [3][128][20]
    float* Bs = sm + 3 * 2560;    // [3][16][136]

    int tid = threadIdx.x, lane = tid & 31, wid = tid >> 5;
    int warp_m = wid & 1, warp_n = wid >> 1;
    int rowBase = blockIdx.y * 128, colBase = blockIdx.x * 128;
    int lr = lane >> 2, lc = lane & 3;
    int m0 = warp_m * 64, n0 = warp_n * 32;

    const float* Ap = A + (size_t)rowBase * DIMC;
    const float* Bp = Bm + colBase;

#define PROJ_LOAD(s, k0) do {                                          \
    float* Ad = As + (s) * 2560;                                       \
    float* Bd = Bs + (s) * 2176;                                       \
    _Pragma("unroll")                                                  \
    for (int i_ = 0; i_ < 2; i_++) {                                   \
        int t_ = tid + i_ * 256;                                       \
        int r_ = t_ >> 2, c_ = (t_ & 3) * 4;                           \
        cp16(&Ad[r_ * 20 + c_], Ap + (size_t)r_ * DIMC + (k0) + c_);   \
        int br_ = t_ >> 5, bc_ = (t_ & 31) * 4;                        \
        cp16(&Bd[br_ * 136 + bc_], Bp + (size_t)((k0) + br_) * DIMC + bc_); \
    }                                                                  \
    CP_COMMIT;                                                         \
} while (0)

    PROJ_LOAD(0, 0);
    PROJ_LOAD(1, 16);

    float acc[4][4][4] = {};
    const int NITER = DIMC / 16;   // 48
    for (int it = 0; it < NITER; it++) {
        CP_WAIT1;
        __syncthreads();
        int s = it % 3;
        const float* Aq = As + s * 2560;
        const float* Bq = Bs + s * 2176;
#pragma unroll
        for (int kk = 0; kk < 16; kk += 8) {
            unsigned a[4][4], b[4][2];
#pragma unroll
            for (int mi = 0; mi < 4; mi++) {
                int r = m0 + mi * 16 + lr;
                a[mi][0] = ld_tf(&Aq[r * 20 + kk + lc]);
                a[mi][1] = ld_tf(&Aq[(r + 8) * 20 + kk + lc]);
                a[mi][2] = ld_tf(&Aq[r * 20 + kk + lc + 4]);
                a[mi][3] = ld_tf(&Aq[(r + 8) * 20 + kk + lc + 4]);
            }
#pragma unroll
            for (int ni = 0; ni < 4; ni++) {
                int c = n0 + ni * 8 + lr;
                b[ni][0] = ld_tf(&Bq[(kk + lc) * 136 + c]);
                b[ni][1] = ld_tf(&Bq[(kk + lc + 4) * 136 + c]);
            }
#pragma unroll
            for (int mi = 0; mi < 4; mi++)
#pragma unroll
                for (int ni = 0; ni < 4; ni++)
                    mma8(acc[mi][ni], a[mi][0], a[mi][1], a[mi][2], a[mi][3],
                         b[ni][0], b[ni][1]);
        }
        __syncthreads();
        if (it + 2 < NITER) PROJ_LOAD((it + 2) % 3, (it + 2) * 16);
        else CP_COMMIT;
    }
#undef PROJ_LOAD

    if (MODE == 2) {
        // stage transposed tile in smem: stg[local_col][local_row], stride 136
        __half* stg = (__half*)sm;   // 128*136 halves = 34816 B <= 56832 B
#pragma unroll
        for (int mi = 0; mi < 4; mi++) {
#pragma unroll
            for (int ni = 0; ni < 4; ni++) {
                int col = n0 + ni * 8 + 2 * lc;       // local 0..127
#pragma unroll
                for (int half_ = 0; half_ < 2; half_++) {
                    int row = m0 + mi * 16 + lr + half_ * 8;   // local 0..127
                    stg[col * 136 + row]       = __float2half(acc[mi][ni][half_*2 + 0]);
                    stg[(col + 1) * 136 + row] = __float2half(acc[mi][ni][half_*2 + 1]);
                }
            }
        }
        __syncthreads();
        int b_ = rowBase >> 10;
        int rloc = rowBase & 1023;
        // coalesced copy-out: 128 cols x 16 uint4 (8 halves) each
        for (int t = tid; t < 128 * 16; t += 256) {
            int col = t >> 4;
            int r8 = (t & 15) * 8;
            int gcol = colBase + col;
            int hh = gcol >> 6, d = gcol & 63;
            size_t dst = ((size_t)(b_ * NH + hh) * HD + d) * NT + rloc + r8;
            *(uint4*)&Ch[dst] = *(const uint4*)&stg[col * 136 + r8];
        }
        return;
    }

#pragma unroll
    for (int mi = 0; mi < 4; mi++) {
#pragma unroll
        for (int ni = 0; ni < 4; ni++) {
            int col = colBase + n0 + ni * 8 + 2 * lc;
            float bv0 = 0.f, bv1 = 0.f;
            if (MODE == 0 && bias) { bv0 = bias[col]; bv1 = bias[col + 1]; }
#pragma unroll
            for (int half_ = 0; half_ < 2; half_++) {
                int row = rowBase + m0 + mi * 16 + lr + half_ * 8;
                float v0 = acc[mi][ni][half_*2 + 0] * scale + bv0;
                float v1 = acc[mi][ni][half_*2 + 1] * scale + bv1;
                if (MODE == 0) {
                    *(float2*)&Cf[(size_t)row * DIMC + col] = make_float2(v0, v1);
                } else {    // MODE 1
                    int b_ = row >> 10, rr = row & 1023;
                    int h = col >> 6, d = col & 63;
                    float2 v = make_float2(__uint_as_float(f2tf(v0)),
                                           __uint_as_float(f2tf(v1)));
                    *(float2*)&Cf[(((size_t)(b_ * NH + h) * NT + rr) * HD + d)] = v;
                }
            }
        }
    }
}

// fused QKV: blockIdx.z selects (W, dst, scale, layout)
__global__ __launch_bounds__(256, 2) void qkv_tf32(
    const float* __restrict__ x,
    const float* __restrict__ Wq, const float* __restrict__ Wk,
    const float* __restrict__ Wv,
    float* __restrict__ q, float* __restrict__ k, __half* __restrict__ vt)
{
    int z = blockIdx.z;
    if (z == 0)      proj_body<1>(x, Wq, q, nullptr, nullptr, 0.125f);
    else if (z == 1) proj_body<1>(x, Wk, k, nullptr, nullptr, 1.0f);
    else             proj_body<2>(x, Wv, nullptr, vt, nullptr, 1.0f);
}

__global__ __launch_bounds__(256, 2) void outproj_tf32(
    const float* __restrict__ A, const float* __restrict__ Bm,
    float* __restrict__ C, const float* __restrict__ bias)
{
    proj_body<0>(A, Bm, C, nullptr, bias, 1.0f);
}

// ============================================================
// score_tf32: per (b,h): S = Q(1024x64) @ K^T. 128x128 tile,
// whole K=64 resident in smem (inputs pre-rounded tf32).
// Writes S as fp16.
// ============================================================
__global__ __launch_bounds__(256, 2) void score_tf32(
    const float* __restrict__ Q, const float* __restrict__ Kp,
    __half* __restrict__ S)
{
    extern __shared__ float sm[];
    float (*Qs)[68] = (float(*)[68])sm;
    float (*Ks)[68] = (float(*)[68])(sm + 128 * 68);

    int bh = blockIdx.z;
    const float* Qg = Q + (size_t)bh * NT * HD + (size_t)blockIdx.y * 128 * HD;
    const float* Kg = Kp + (size_t)bh * NT * HD + (size_t)blockIdx.x * 128 * HD;

    int tid = threadIdx.x, lane = tid & 31, wid = tid >> 5;
    int lr = lane >> 2, lc = lane & 3;
    int warp_m = wid & 1, warp_n = wid >> 1;

    int row = tid >> 4, col4 = (tid & 15) * 4;
#pragma unroll
    for (int it = 0; it < 8; it++) {
        int r = it * 16 + row;
        *(float4*)&Qs[r][col4] = *(const float4*)(Qg + (size_t)r * HD + col4);
        *(float4*)&Ks[r][col4] = *(const float4*)(Kg + (size_t)r * HD + col4);
    }
    __syncthreads();

    float acc[4][4][4] = {};
    int m0 = warp_m * 64, n0 = warp_n * 32;
#pragma unroll
    for (int kk = 0; kk < 64; kk += 8) {
        unsigned a[4][4], b[4][2];
#pragma unroll
        for (int mi = 0; mi < 4; mi++) {
            int r = m0 + mi * 16 + lr;
            a[mi][0] = __float_as_uint(Qs[r    ][kk + lc]);
            a[mi][1] = __float_as_uint(Qs[r + 8][kk + lc]);
            a[mi][2] = __float_as_uint(Qs[r    ][kk + lc + 4]);
            a[mi][3] = __float_as_uint(Qs[r + 8][kk + lc + 4]);
        }
#pragma unroll
        for (int ni = 0; ni < 4; ni++) {
            int c = n0 + ni * 8 + lr;
            b[ni][0] = __float_as_uint(Ks[c][kk + lc]);
            b[ni][1] = __float_as_uint(Ks[c][kk + lc + 4]);
        }
#pragma unroll
        for (int mi = 0; mi < 4; mi++)
#pragma unroll
            for (int ni = 0; ni < 4; ni++)
                mma8(acc[mi][ni], a[mi][0], a[mi][1], a[mi][2], a[mi][3],
                     b[ni][0], b[ni][1]);
    }

    __half* Sg = S + (size_t)bh * NTNT;
#pragma unroll
    for (int mi = 0; mi < 4; mi++) {
#pragma unroll
        for (int ni = 0; ni < 4; ni++) {
            int c = blockIdx.x * 128 + n0 + ni * 8 + 2 * lc;
#pragma unroll
            for (int half_ = 0; half_ < 2; half_++) {
                int r = blockIdx.y * 128 + m0 + mi * 16 + lr + half_ * 8;
                *(__half2*)&Sg[(size_t)r * NT + c] =
                    __floats2half2_rn(acc[mi][ni][half_*2], acc[mi][ni][half_*2 + 1]);
            }
        }
    }
}

// ============================================================
// Fused talking-heads softmax; fp16 in/out, fp32 internal.
// 1 query row per CTA, 384 thr.
// ============================================================
__global__ __launch_bounds__(384) void softmax_mix_kernel(
    __half* __restrict__ S, const float* __restrict__ Wl,
    const float* __restrict__ bl, const float* __restrict__ Ww,
    const float* __restrict__ bw)
{
    extern __shared__ float sm[];
    float* buf = sm;
    float* wl  = sm + 12288;
    float* ww  = wl + 144;
    float* blv = ww + 144;
    float* bwv = blv + 12;

    int tid = threadIdx.x;
    int i = blockIdx.x, b = blockIdx.y;
    if (tid < 144)               wl[tid]       = Wl[tid];
    if (tid >= 160 && tid < 304) ww[tid - 160] = Ww[tid - 160];
    if (tid >= 320 && tid < 332) blv[tid - 320] = bl[tid - 320];
    if (tid >= 352 && tid < 364) bwv[tid - 352] = bw[tid - 352];

    size_t rowbase = (size_t)b * NH * NTNT + (size_t)i * NT;
    for (int t = tid; t < 1536; t += 384) {
        int h = t >> 7, j8 = (t & 127) * 8;
        uint4 r4 = *(const uint4*)&S[rowbase + (size_t)h * NTNT + j8];
        const __half2* hp = (const __half2*)&r4;
        float* dst = buf + h * 1024 + j8;
#pragma unroll
        for (int q = 0; q < 4; q++) {
            float2 f = __half22float2(hp[q]);
            dst[2*q] = f.x; dst[2*q + 1] = f.y;
        }
    }
    __syncthreads();

    for (int j = tid; j < NT; j += 384) {
        float s[12];
#pragma unroll
        for (int h = 0; h < 12; h++) s[h] = buf[h * 1024 + j];
#pragma unroll
        for (int g = 0; g < 12; g++) {
            float m = blv[g];
#pragma unroll
            for (int h = 0; h < 12; h++) m = fmaf(wl[g * 12 + h], s[h], m);
            buf[g * 1024 + j] = m;
        }
    }
    __syncthreads();

    {
        int w = tid >> 5, lane = tid & 31;
        float* row = buf + w * 1024;
        float mx = -1e30f;
        for (int j = lane; j < 1024; j += 32) mx = fmaxf(mx, row[j]);
#pragma unroll
        for (int o = 16; o; o >>= 1) mx = fmaxf(mx, __shfl_xor_sync(0xffffffffu, mx, o));
        float sum = 0.f;
        float e[32];
        int t = 0;
        for (int j = lane; j < 1024; j += 32, t++) {
            float ev = __expf(row[j] - mx);
            e[t] = ev; sum += ev;
        }
#pragma unroll
        for (int o = 16; o; o >>= 1) sum += __shfl_xor_sync(0xffffffffu, sum, o);
        float rinv = 1.f / sum;
        t = 0;
        for (int j = lane; j < 1024; j += 32, t++) row[j] = e[t] * rinv;
    }
    __syncthreads();

    for (int j = tid; j < NT; j += 384) {
        float p[12];
#pragma unroll
        for (int h = 0; h < 12; h++) p[h] = buf[h * 1024 + j];
#pragma unroll
        for (int g = 0; g < 12; g++) {
            float m = bwv[g];
#pragma unroll
            for (int h = 0; h < 12; h++) m = fmaf(ww[g * 12 + h], p[h], m);
            buf[g * 1024 + j] = m;
        }
    }
    __syncthreads();

    for (int t = tid; t < 1536; t += 384) {
        int g = t >> 7, j8 = (t & 127) * 8;
        const float* src = buf + g * 1024 + j8;
        uint4 outv;
        __half2* hp = (__half2*)&outv;
#pragma unroll
        for (int q = 0; q < 4; q++)
            hp[q] = __floats2half2_rn(src[2*q], src[2*q + 1]);
        *(uint4*)&S[rowbase + (size_t)g * NTNT + j8] = outv;
    }
}

// ============================================================
// av_f16: per (b,h): O(1024x64) = P(1024x1024) @ V(1024x64),
// fp16 MMA m16n8k16, fp32 accum. V pre-transposed [d][tok].
// 64x64 tile, BK=32, 3-stage cp.async, 256 thr.
// smem: Ps[3][64][40]h, Vs[3][64][40]h (30 KB).
// ============================================================
__global__ __launch_bounds__(256, 4) void av_f16(
    const __half* __restrict__ P, const __half* __restrict__ Vt,
    float* __restrict__ O)
{
    extern __shared__ float sm[];
    __half* Ps = (__half*)sm;            // [3][64][40]
    __half* Vs = Ps + 3 * 2560;          // [3][64][40]

    int bh = blockIdx.y;
    int b = bh / NH, h = bh % NH;
    const __half* Pg = P + (size_t)bh * NTNT + (size_t)blockIdx.x * 64 * NT;
    const __half* Vg = Vt + (size_t)bh * HD * NT;   // [d][tok]

    int tid = threadIdx.x, lane = tid & 31, wid = tid >> 5;
    int lr = lane >> 2, lc = lane & 3;
    int m0 = (wid & 3) * 16, n0 = (wid >> 2) * 32;

    int ldr = tid >> 2, ldc = (tid & 3) * 8;   // row 0..63, col chunk of 8 halves

#define AV_LOAD(s, k0) do {                                             \
    __half* Pd = Ps + (s) * 2560;                                       \
    __half* Vd = Vs + (s) * 2560;                                       \
    cp16(&Pd[ldr * 40 + ldc], Pg + (size_t)ldr * NT + (k0) + ldc);      \
    cp16(&Vd[ldr * 40 + ldc], Vg + (size_t)ldr * NT + (k0) + ldc);      \
    CP_COMMIT;                                                          \
} while (0)

    AV_LOAD(0, 0);
    AV_LOAD(1, 32);

    float acc[4][4] = {};
    const int NITER = NT / 32;   // 32
    for (int it = 0; it < NITER; it++) {
        CP_WAIT1;
        __syncthreads();
        int s = it % 3;
        const __half* Pq = Ps + s * 2560;
        const __half* Vq = Vs + s * 2560;
#pragma unroll
        for (int kk = 0; kk < 32; kk += 16) {
            unsigned a0, a1, a2, a3;
            {
                int rb = (m0 + lr) * 40 + kk + 2 * lc;
                a0 = *(const unsigned*)&Pq[rb];
                a1 = *(const unsigned*)&Pq[rb + 8 * 40];
                a2 = *(const unsigned*)&Pq[rb + 8];
                a3 = *(const unsigned*)&Pq[rb + 8 * 40 + 8];
            }
#pragma unroll
            for (int ni = 0; ni < 4; ni++) {
                int nb = (n0 + ni * 8 + lr) * 40 + kk + 2 * lc;
                unsigned b0 = *(const unsigned*)&Vq[nb];
                unsigned b1 = *(const unsigned*)&Vq[nb + 8];
                mma16h(acc[ni], a0, a1, a2, a3, b0, b1);
            }
        }
        __syncthreads();
        if (it + 2 < NITER) AV_LOAD((it + 2) % 3, (it + 2) * 32);
        else CP_COMMIT;
    }
#undef AV_LOAD

#pragma unroll
    for (int ni = 0; ni < 4; ni++) {
        int col = n0 + ni * 8 + 2 * lc;
#pragma unroll
        for (int half_ = 0; half_ < 2; half_++) {
            int row = blockIdx.x * 64 + m0 + lr + half_ * 8;
            *(float2*)&O[(size_t)(b * NT + row) * DIMC + h * HD + col] =
                make_float2(acc[ni][half_*2], acc[ni][half_*2 + 1]);
        }
    }
}

// ============================================================
extern "C" void kernel_launch(void* const* d_in, const int* in_sizes, int n_in,
                              void* d_out, int out_size)
{
    const float* x  = (const float*)d_in[0];
    const float* Wq = (const float*)d_in[1];
    const float* Wk = (const float*)d_in[2];
    const float* Wv = (const float*)d_in[3];
    const float* Wl = (const float*)d_in[4];
    const float* bl = (const float*)d_in[5];
    const float* Ww = (const float*)d_in[6];
    const float* bw = (const float*)d_in[7];
    const float* Wp = (const float*)d_in[8];
    const float* bp = (const float*)d_in[9];
    float* out = (float*)d_out;

    float *gq, *gk, *gO;
    __half *gvt, *gS;
    cudaGetSymbolAddress((void**)&gq, g_q);
    cudaGetSymbolAddress((void**)&gk, g_k);
    cudaGetSymbolAddress((void**)&gvt, g_vt);
    cudaGetSymbolAddress((void**)&gS, g_S);
    cudaGetSymbolAddress((void**)&gO, g_O);

    int proj_smem = 3 * (128*20 + 16*136) * (int)sizeof(float);      // 56832
    cudaFuncSetAttribute(qkv_tf32,
                         cudaFuncAttributeMaxDynamicSharedMemorySize, proj_smem);
    cudaFuncSetAttribute(outproj_tf32,
                         cudaFuncAttributeMaxDynamicSharedMemorySize, proj_smem);
    int score_smem = 2 * 128 * 68 * (int)sizeof(float);              // 69632
    cudaFuncSetAttribute(score_tf32,
                         cudaFuncAttributeMaxDynamicSharedMemorySize, score_smem);
    int av_smem = 3 * 2 * 2560 * (int)sizeof(__half);                // 30720
    cudaFuncSetAttribute(av_f16,
                         cudaFuncAttributeMaxDynamicSharedMemorySize, av_smem);
    int smbytes = (12 * 1024 + 144 + 144 + 12 + 12) * (int)sizeof(float);
    cudaFuncSetAttribute(softmax_mix_kernel,
                         cudaFuncAttributeMaxDynamicSharedMemorySize, smbytes);

    // QKV projections, one launch; Q pre-scaled; q/k tf32-rounded; V fp16 transposed
    qkv_tf32<<<dim3(6, 64, 3), 256, proj_smem>>>(x, Wq, Wk, Wv, gq, gk, gvt);

    // raw scores S = Q K^T -> fp16
    score_tf32<<<dim3(8, 8, 96), 256, score_smem>>>(gq, gk, gS);

    // fused pre-mix + softmax + post-mix (in place on gS, fp16)
    softmax_mix_kernel<<<dim3(1024, 8), 384, smbytes>>>(gS, Wl, bl, Ww, bw);

    // attn @ V -> [tok, dim], fp16 MMA
    av_f16<<<dim3(16, 96), 256, av_smem>>>(gS, gvt, gO);

    // final projection + bias
    outproj_tf32<<<dim3(6, 64), 256, proj_smem>>>(gO, Wp, out, bp);
}

// round 8
// speedup vs baseline: 1.4781x; 1.1815x over previous
#include <cuda_runtime.h>
#include <cuda_fp16.h>
#include <math.h>

#define DIMC 768
#define NH 12
#define HD 64
#define NB 8
#define NT 1024
#define M_TOK (NB*NT)   // 8192
#define NTNT (NT*NT)

// ---- scratch (device globals: no allocations allowed) ----
__device__ __half g_xh[M_TOK*DIMC];            // x in fp16
__device__ __half g_wt[3*DIMC*DIMC];           // Wq,Wk,Wv fp16 TRANSPOSED [n][k]
__device__ __half g_q[NB*NH*NT*HD];            // [b,h,n,d] fp16, Q pre-scaled
__device__ __half g_k[NB*NH*NT*HD];            // [b,h,n,d] fp16
__device__ __half g_vt[NB*NH*HD*NT];           // [b,h,d,tok] fp16 (transposed V)
__device__ __half g_S[(size_t)NB*NH*NT*NT];    // 201 MB scores / probs fp16 (in place)
__device__ float  g_O[(size_t)M_TOK*DIMC];     // [tok, dim] fp32

// ---------- helpers ----------
__device__ __forceinline__ unsigned f2tf(float f) {
    unsigned u; asm("cvt.rna.tf32.f32 %0, %1;" : "=r"(u) : "f"(f)); return u;
}
__device__ __forceinline__ unsigned ld_tf(const float* p) { return f2tf(*p); }
__device__ __forceinline__ void mma8(float* d, unsigned a0, unsigned a1,
                                     unsigned a2, unsigned a3,
                                     unsigned b0, unsigned b1) {
    asm volatile(
        "mma.sync.aligned.m16n8k8.row.col.f32.tf32.tf32.f32 "
        "{%0,%1,%2,%3},{%4,%5,%6,%7},{%8,%9},{%0,%1,%2,%3};"
        : "+f"(d[0]), "+f"(d[1]), "+f"(d[2]), "+f"(d[3])
        : "r"(a0), "r"(a1), "r"(a2), "r"(a3), "r"(b0), "r"(b1));
}
__device__ __forceinline__ void mma16h(float* d, unsigned a0, unsigned a1,
                                       unsigned a2, unsigned a3,
                                       unsigned b0, unsigned b1) {
    asm volatile(
        "mma.sync.aligned.m16n8k16.row.col.f32.f16.f16.f32 "
        "{%0,%1,%2,%3},{%4,%5,%6,%7},{%8,%9},{%0,%1,%2,%3};"
        : "+f"(d[0]), "+f"(d[1]), "+f"(d[2]), "+f"(d[3])
        : "r"(a0), "r"(a1), "r"(a2), "r"(a3), "r"(b0), "r"(b1));
}
__device__ __forceinline__ void cp16(void* s, const void* g) {
    unsigned sa = (unsigned)__cvta_generic_to_shared(s);
    asm volatile("cp.async.ca.shared.global [%0], [%1], 16;" :: "r"(sa), "l"(g));
}
#define CP_COMMIT asm volatile("cp.async.commit_group;")
#define CP_WAIT1  asm volatile("cp.async.wait_group 1;")
#define CP_WAIT0  asm volatile("cp.async.wait_group 0;")

// ============================================================
// conversion kernels
// ============================================================
__global__ __launch_bounds__(256) void conv_x(
    const float* __restrict__ x, __half* __restrict__ xh)
{
    int i = (blockIdx.x * 256 + threadIdx.x) * 4;
    float4 v = *(const float4*)&x[i];
    *(__half2*)&xh[i]     = __floats2half2_rn(v.x, v.y);
    *(__half2*)&xh[i + 2] = __floats2half2_rn(v.z, v.w);
}

// transpose+convert: out[n][k] = in[k][n], 32x32 tiles, z selects W
__global__ __launch_bounds__(256) void conv_wt(
    const float* __restrict__ Wq, const float* __restrict__ Wk,
    const float* __restrict__ Wv, __half* __restrict__ Wt)
{
    __shared__ float t[32][33];
    int z = blockIdx.z;
    const float* W = (z == 0) ? Wq : (z == 1) ? Wk : Wv;
    __half* out = Wt + (size_t)z * DIMC * DIMC;
    int n0 = blockIdx.x * 32, k0 = blockIdx.y * 32;
    int tx = threadIdx.x & 31, ty = threadIdx.x >> 5;   // 32 x 8
#pragma unroll
    for (int i = ty; i < 32; i += 8)
        t[i][tx] = W[(size_t)(k0 + i) * DIMC + n0 + tx];
    __syncthreads();
#pragma unroll
    for (int i = ty; i < 32; i += 8)
        out[(size_t)(n0 + i) * DIMC + k0 + tx] = __float2half(t[tx][i]);
}

// ============================================================
// qkv_f16: fp16 GEMM C[8192,768] = xh @ Wt^T (Wt is [n][k]).
// 128x128 tile, BK=32, 3-stage cp.async, 256 thr, warp 64x32.
// MODE 1: head-split fp16 [b,h,n,d] (scale). MODE 2: transposed
// fp16 V [b,h,d,tok] via smem staging.
// ============================================================
template<int MODE>
__device__ __forceinline__ void projh_body(
    const __half* __restrict__ A, const __half* __restrict__ Bm,
    __half* __restrict__ C, float scale)
{
    extern __shared__ float smf[];
    __half* As = (__half*)smf;        // [3][128][40]
    __half* Bs = As + 3 * 5120;       // [3][128][40]

    int tid = threadIdx.x, lane = tid & 31, wid = tid >> 5;
    int warp_m = wid & 1, warp_n = wid >> 1;
    int rowBase = blockIdx.y * 128, colBase = blockIdx.x * 128;
    int lr = lane >> 2, lc = lane & 3;
    int m0 = warp_m * 64, n0 = warp_n * 32;

    const __half* Ap = A + (size_t)rowBase * DIMC;
    const __half* Bp = Bm + (size_t)colBase * DIMC;

#define QKV_LOAD(s, k0) do {                                            \
    __half* Ad = As + (s) * 5120;                                       \
    __half* Bd = Bs + (s) * 5120;                                       \
    _Pragma("unroll")                                                   \
    for (int i_ = 0; i_ < 2; i_++) {                                    \
        int t_ = tid + i_ * 256;                                        \
        int r_ = t_ >> 2, c_ = (t_ & 3) * 8;                            \
        cp16(&Ad[r_ * 40 + c_], Ap + (size_t)r_ * DIMC + (k0) + c_);    \
        cp16(&Bd[r_ * 40 + c_], Bp + (size_t)r_ * DIMC + (k0) + c_);    \
    }                                                                   \
    CP_COMMIT;                                                          \
} while (0)

    QKV_LOAD(0, 0);
    QKV_LOAD(1, 32);

    float acc[4][4][4] = {};
    const int NITER = DIMC / 32;   // 24
    for (int it = 0; it < NITER; it++) {
        CP_WAIT1;
        __syncthreads();
        int s = it % 3;
        const __half* Aq = As + s * 5120;
        const __half* Bq = Bs + s * 5120;
#pragma unroll
        for (int kk = 0; kk < 32; kk += 16) {
            unsigned a[4][4], b[4][2];
#pragma unroll
            for (int mi = 0; mi < 4; mi++) {
                int rb = (m0 + mi * 16 + lr) * 40 + kk + 2 * lc;
                a[mi][0] = *(const unsigned*)&Aq[rb];
                a[mi][1] = *(const unsigned*)&Aq[rb + 8 * 40];
                a[mi][2] = *(const unsigned*)&Aq[rb + 8];
                a[mi][3] = *(const unsigned*)&Aq[rb + 8 * 40 + 8];
            }
#pragma unroll
            for (int ni = 0; ni < 4; ni++) {
                int nb = (n0 + ni * 8 + lr) * 40 + kk + 2 * lc;
                b[ni][0] = *(const unsigned*)&Bq[nb];
                b[ni][1] = *(const unsigned*)&Bq[nb + 8];
            }
#pragma unroll
            for (int mi = 0; mi < 4; mi++)
#pragma unroll
                for (int ni = 0; ni < 4; ni++)
                    mma16h(acc[mi][ni], a[mi][0], a[mi][1], a[mi][2], a[mi][3],
                           b[ni][0], b[ni][1]);
        }
        __syncthreads();
        if (it + 2 < NITER) QKV_LOAD((it + 2) % 3, (it + 2) * 32);
        else CP_COMMIT;
    }
#undef QKV_LOAD

    if (MODE == 2) {
        // stage transposed fp16 tile: stg[local_col][local_row], stride 136
        __half* stg = (__half*)smf;   // 34816 B <= 61440 B
#pragma unroll
        for (int mi = 0; mi < 4; mi++) {
#pragma unroll
            for (int ni = 0; ni < 4; ni++) {
                int col = n0 + ni * 8 + 2 * lc;
#pragma unroll
                for (int half_ = 0; half_ < 2; half_++) {
                    int row = m0 + mi * 16 + lr + half_ * 8;
                    stg[col * 136 + row]       = __float2half(acc[mi][ni][half_*2 + 0]);
                    stg[(col + 1) * 136 + row] = __float2half(acc[mi][ni][half_*2 + 1]);
                }
            }
        }
        __syncthreads();
        int b_ = rowBase >> 10;
        int rloc = rowBase & 1023;
        for (int t = tid; t < 128 * 16; t += 256) {
            int col = t >> 4;
            int r8 = (t & 15) * 8;
            int gcol = colBase + col;
            int hh = gcol >> 6, d = gcol & 63;
            size_t dst = ((size_t)(b_ * NH + hh) * HD + d) * NT + rloc + r8;
            *(uint4*)&C[dst] = *(const uint4*)&stg[col * 136 + r8];
        }
        return;
    }

    // MODE 1: fp16 head-split [b,h,n,d]
#pragma unroll
    for (int mi = 0; mi < 4; mi++) {
#pragma unroll
        for (int ni = 0; ni < 4; ni++) {
            int col = colBase + n0 + ni * 8 + 2 * lc;
            int h = col >> 6, d = col & 63;
#pragma unroll
            for (int half_ = 0; half_ < 2; half_++) {
                int row = rowBase + m0 + mi * 16 + lr + half_ * 8;
                int b_ = row >> 10, rr = row & 1023;
                *(__half2*)&C[(((size_t)(b_ * NH + h) * NT + rr) * HD + d)] =
                    __floats2half2_rn(acc[mi][ni][half_*2 + 0] * scale,
                                      acc[mi][ni][half_*2 + 1] * scale);
            }
        }
    }
}

__global__ __launch_bounds__(256, 2) void qkv_f16(
    const __half* __restrict__ xh, const __half* __restrict__ Wt,
    __half* __restrict__ q, __half* __restrict__ k, __half* __restrict__ vt)
{
    int z = blockIdx.z;
    const __half* Bm = Wt + (size_t)z * DIMC * DIMC;
    if (z == 0)      projh_body<1>(xh, Bm, q, 0.125f);
    else if (z == 1) projh_body<1>(xh, Bm, k, 1.0f);
    else             projh_body<2>(xh, Bm, vt, 1.0f);
}

// ============================================================
// outproj (tf32, fp32 inputs) — numerics firewall kept intact
// ============================================================
__global__ __launch_bounds__(256, 2) void outproj_tf32(
    const float* __restrict__ A, const float* __restrict__ Bm,
    float* __restrict__ C, const float* __restrict__ bias)
{
    extern __shared__ float sm[];
    float* As = sm;               // [3][128][20]
    float* Bs = sm + 3 * 2560;    // [3][16][136]

    int tid = threadIdx.x, lane = tid & 31, wid = tid >> 5;
    int warp_m = wid & 1, warp_n = wid >> 1;
    int rowBase = blockIdx.y * 128, colBase = blockIdx.x * 128;
    int lr = lane >> 2, lc = lane & 3;
    int m0 = warp_m * 64, n0 = warp_n * 32;

    const float* Ap = A + (size_t)rowBase * DIMC;
    const float* Bp = Bm + colBase;

#define PROJ_LOAD(s, k0) do {                                          \
    float* Ad = As + (s) * 2560;                                       \
    float* Bd = Bs + (s) * 2176;                                       \
    _Pragma("unroll")                                                  \
    for (int i_ = 0; i_ < 2; i_++) {                                   \
        int t_ = tid + i_ * 256;                                       \
        int r_ = t_ >> 2, c_ = (t_ & 3) * 4;                           \
        cp16(&Ad[r_ * 20 + c_], Ap + (size_t)r_ * DIMC + (k0) + c_);   \
        int br_ = t_ >> 5, bc_ = (t_ & 31) * 4;                        \
        cp16(&Bd[br_ * 136 + bc_], Bp + (size_t)((k0) + br_) * DIMC + bc_); \
    }                                                                  \
    CP_COMMIT;                                                         \
} while (0)

    PROJ_LOAD(0, 0);
    PROJ_LOAD(1, 16);

    float acc[4][4][4] = {};
    const int NITER = DIMC / 16;   // 48
    for (int it = 0; it < NITER; it++) {
        CP_WAIT1;
        __syncthreads();
        int s = it % 3;
        const float* Aq = As + s * 2560;
        const float* Bq = Bs + s * 2176;
#pragma unroll
        for (int kk = 0; kk < 16; kk += 8) {
            unsigned a[4][4], b[4][2];
#pragma unroll
            for (int mi = 0; mi < 4; mi++) {
                int r = m0 + mi * 16 + lr;
                a[mi][0] = ld_tf(&Aq[r * 20 + kk + lc]);
                a[mi][1] = ld_tf(&Aq[(r + 8) * 20 + kk + lc]);
                a[mi][2] = ld_tf(&Aq[r * 20 + kk + lc + 4]);
                a[mi][3] = ld_tf(&Aq[(r + 8) * 20 + kk + lc + 4]);
            }
#pragma unroll
            for (int ni = 0; ni < 4; ni++) {
                int c = n0 + ni * 8 + lr;
                b[ni][0] = ld_tf(&Bq[(kk + lc) * 136 + c]);
                b[ni][1] = ld_tf(&Bq[(kk + lc + 4) * 136 + c]);
            }
#pragma unroll
            for (int mi = 0; mi < 4; mi++)
#pragma unroll
                for (int ni = 0; ni < 4; ni++)
                    mma8(acc[mi][ni], a[mi][0], a[mi][1], a[mi][2], a[mi][3],
                         b[ni][0], b[ni][1]);
        }
        __syncthreads();
        if (it + 2 < NITER) PROJ_LOAD((it + 2) % 3, (it + 2) * 16);
        else CP_COMMIT;
    }
#undef PROJ_LOAD

#pragma unroll
    for (int mi = 0; mi < 4; mi++) {
#pragma unroll
        for (int ni = 0; ni < 4; ni++) {
            int col = colBase + n0 + ni * 8 + 2 * lc;
            float bv0 = bias[col], bv1 = bias[col + 1];
#pragma unroll
            for (int half_ = 0; half_ < 2; half_++) {
                int row = rowBase + m0 + mi * 16 + lr + half_ * 8;
                *(float2*)&C[(size_t)row * DIMC + col] =
                    make_float2(acc[mi][ni][half_*2 + 0] + bv0,
                                acc[mi][ni][half_*2 + 1] + bv1);
            }
        }
    }
}

// ============================================================
// score_f16: per (b,h): S = Q(1024x64) @ K^T, fp16 MMA.
// 128x128 tile, whole K=64 in smem. Writes S fp16.
// ============================================================
__global__ __launch_bounds__(256, 2) void score_f16(
    const __half* __restrict__ Q, const __half* __restrict__ Kp,
    __half* __restrict__ S)
{
    extern __shared__ float smf[];
    __half* Qs = (__half*)smf;        // [128][72]
    __half* Ks = Qs + 128 * 72;       // [128][72]

    int bh = blockIdx.z;
    const __half* Qg = Q + (size_t)bh * NT * HD + (size_t)blockIdx.y * 128 * HD;
    const __half* Kg = Kp + (size_t)bh * NT * HD + (size_t)blockIdx.x * 128 * HD;

    int tid = threadIdx.x, lane = tid & 31, wid = tid >> 5;
    int lr = lane >> 2, lc = lane & 3;
    int warp_m = wid & 1, warp_n = wid >> 1;
    int m0 = warp_m * 64, n0 = warp_n * 32;

#pragma unroll
    for (int i = 0; i < 4; i++) {
        int t = tid + i * 256;
        int r = t >> 3, c = (t & 7) * 8;
        cp16(&Qs[r * 72 + c], Qg + (size_t)r * HD + c);
        cp16(&Ks[r * 72 + c], Kg + (size_t)r * HD + c);
    }
    CP_COMMIT;
    CP_WAIT0;
    __syncthreads();

    float acc[4][4][4] = {};
#pragma unroll
    for (int kk = 0; kk < 64; kk += 16) {
        unsigned a[4][4], b[4][2];
#pragma unroll
        for (int mi = 0; mi < 4; mi++) {
            int rb = (m0 + mi * 16 + lr) * 72 + kk + 2 * lc;
            a[mi][0] = *(const unsigned*)&Qs[rb];
            a[mi][1] = *(const unsigned*)&Qs[rb + 8 * 72];
            a[mi][2] = *(const unsigned*)&Qs[rb + 8];
            a[mi][3] = *(const unsigned*)&Qs[rb + 8 * 72 + 8];
        }
#pragma unroll
        for (int ni = 0; ni < 4; ni++) {
            int nb = (n0 + ni * 8 + lr) * 72 + kk + 2 * lc;
            b[ni][0] = *(const unsigned*)&Ks[nb];
            b[ni][1] = *(const unsigned*)&Ks[nb + 8];
        }
#pragma unroll
        for (int mi = 0; mi < 4; mi++)
#pragma unroll
            for (int ni = 0; ni < 4; ni++)
                mma16h(acc[mi][ni], a[mi][0], a[mi][1], a[mi][2], a[mi][3],
                       b[ni][0], b[ni][1]);
    }

    __half* Sg = S + (size_t)bh * NTNT;
#pragma unroll
    for (int mi = 0; mi < 4; mi++) {
#pragma unroll
        for (int ni = 0; ni < 4; ni++) {
            int c = blockIdx.x * 128 + n0 + ni * 8 + 2 * lc;
#pragma unroll
            for (int half_ = 0; half_ < 2; half_++) {
                int r = blockIdx.y * 128 + m0 + mi * 16 + lr + half_ * 8;
                *(__half2*)&Sg[(size_t)r * NT + c] =
                    __floats2half2_rn(acc[mi][ni][half_*2], acc[mi][ni][half_*2 + 1]);
            }
        }
    }
}

// ============================================================
// Fused talking-heads softmax; fp16 in/out, fp32 internal.
// 1 query row per CTA, 384 thr.
// ============================================================
__global__ __launch_bounds__(384) void softmax_mix_kernel(
    __half* __restrict__ S, const float* __restrict__ Wl,
    const float* __restrict__ bl, const float* __restrict__ Ww,
    const float* __restrict__ bw)
{
    extern __shared__ float sm[];
    float* buf = sm;
    float* wl  = sm + 12288;
    float* ww  = wl + 144;
    float* blv = ww + 144;
    float* bwv = blv + 12;

    int tid = threadIdx.x;
    int i = blockIdx.x, b = blockIdx.y;
    if (tid < 144)               wl[tid]       = Wl[tid];
    if (tid >= 160 && tid < 304) ww[tid - 160] = Ww[tid - 160];
    if (tid >= 320 && tid < 332) blv[tid - 320] = bl[tid - 320];
    if (tid >= 352 && tid < 364) bwv[tid - 352] = bw[tid - 352];

    size_t rowbase = (size_t)b * NH * NTNT + (size_t)i * NT;
    for (int t = tid; t < 1536; t += 384) {
        int h = t >> 7, j8 = (t & 127) * 8;
        uint4 r4 = *(const uint4*)&S[rowbase + (size_t)h * NTNT + j8];
        const __half2* hp = (const __half2*)&r4;
        float* dst = buf + h * 1024 + j8;
#pragma unroll
        for (int q = 0; q < 4; q++) {
            float2 f = __half22float2(hp[q]);
            dst[2*q] = f.x; dst[2*q + 1] = f.y;
        }
    }
    __syncthreads();

    for (int j = tid; j < NT; j += 384) {
        float s[12];
#pragma unroll
        for (int h = 0; h < 12; h++) s[h] = buf[h * 1024 + j];
#pragma unroll
        for (int g = 0; g < 12; g++) {
            float m = blv[g];
#pragma unroll
            for (int h = 0; h < 12; h++) m = fmaf(wl[g * 12 + h], s[h], m);
            buf[g * 1024 + j] = m;
        }
    }
    __syncthreads();

    {
        int w = tid >> 5, lane = tid & 31;
        float* row = buf + w * 1024;
        float mx = -1e30f;
        for (int j = lane; j < 1024; j += 32) mx = fmaxf(mx, row[j]);
#pragma unroll
        for (int o = 16; o; o >>= 1) mx = fmaxf(mx, __shfl_xor_sync(0xffffffffu, mx, o));
        float sum = 0.f;
        float e[32];
        int t = 0;
        for (int j = lane; j < 1024; j += 32, t++) {
            float ev = __expf(row[j] - mx);
            e[t] = ev; sum += ev;
        }
#pragma unroll
        for (int o = 16; o; o >>= 1) sum += __shfl_xor_sync(0xffffffffu, sum, o);
        float rinv = 1.f / sum;
        t = 0;
        for (int j = lane; j < 1024; j += 32, t++) row[j] = e[t] * rinv;
    }
    __syncthreads();

    for (int j = tid; j < NT; j += 384) {
        float p[12];
#pragma unroll
        for (int h = 0; h < 12; h++) p[h] = buf[h * 1024 + j];
#pragma unroll
        for (int g = 0; g < 12; g++) {
            float m = bwv[g];
#pragma unroll
            for (int h = 0; h < 12; h++) m = fmaf(ww[g * 12 + h], p[h], m);
            buf[g * 1024 + j] = m;
        }
    }
    __syncthreads();

    for (int t = tid; t < 1536; t += 384) {
        int g = t >> 7, j8 = (t & 127) * 8;
        const float* src = buf + g * 1024 + j8;
        uint4 outv;
        __half2* hp = (__half2*)&outv;
#pragma unroll
        for (int q = 0; q < 4; q++)
            hp[q] = __floats2half2_rn(src[2*q], src[2*q + 1]);
        *(uint4*)&S[rowbase + (size_t)g * NTNT + j8] = outv;
    }
}

// ============================================================
// av_f16: per (b,h): O(1024x64) = P(1024x1024) @ V(1024x64),
// fp16 MMA m16n8k16, fp32 accum. V pre-transposed [d][tok].
// 64x64 tile, BK=32, 3-stage cp.async, 256 thr.
// ============================================================
__global__ __launch_bounds__(256, 4) void av_f16(
    const __half* __restrict__ P, const __half* __restrict__ Vt,
    float* __restrict__ O)
{
    extern __shared__ float sm[];
    __half* Ps = (__half*)sm;            // [3][64][40]
    __half* Vs = Ps + 3 * 2560;          // [3][64][40]

    int bh = blockIdx.y;
    int b = bh / NH, h = bh % NH;
    const __half* Pg = P + (size_t)bh * NTNT + (size_t)blockIdx.x * 64 * NT;
    const __half* Vg = Vt + (size_t)bh * HD * NT;   // [d][tok]

    int tid = threadIdx.x, lane = tid & 31, wid = tid >> 5;
    int lr = lane >> 2, lc = lane & 3;
    int m0 = (wid & 3) * 16, n0 = (wid >> 2) * 32;

    int ldr = tid >> 2, ldc = (tid & 3) * 8;

#define AV_LOAD(s, k0) do {                                             \
    __half* Pd = Ps + (s) * 2560;                                       \
    __half* Vd = Vs + (s) * 2560;                                       \
    cp16(&Pd[ldr * 40 + ldc], Pg + (size_t)ldr * NT + (k0) + ldc);      \
    cp16(&Vd[ldr * 40 + ldc], Vg + (size_t)ldr * NT + (k0) + ldc);      \
    CP_COMMIT;                                                          \
} while (0)

    AV_LOAD(0, 0);
    AV_LOAD(1, 32);

    float acc[4][4] = {};
    const int NITER = NT / 32;   // 32
    for (int it = 0; it < NITER; it++) {
        CP_WAIT1;
        __syncthreads();
        int s = it % 3;
        const __half* Pq = Ps + s * 2560;
        const __half* Vq = Vs + s * 2560;
#pragma unroll
        for (int kk = 0; kk < 32; kk += 16) {
            unsigned a0, a1, a2, a3;
            {
                int rb = (m0 + lr) * 40 + kk + 2 * lc;
                a0 = *(const unsigned*)&Pq[rb];
                a1 = *(const unsigned*)&Pq[rb + 8 * 40];
                a2 = *(const unsigned*)&Pq[rb + 8];
                a3 = *(const unsigned*)&Pq[rb + 8 * 40 + 8];
            }
#pragma unroll
            for (int ni = 0; ni < 4; ni++) {
                int nb = (n0 + ni * 8 + lr) * 40 + kk + 2 * lc;
                unsigned b0 = *(const unsigned*)&Vq[nb];
                unsigned b1 = *(const unsigned*)&Vq[nb + 8];
                mma16h(acc[ni], a0, a1, a2, a3, b0, b1);
            }
        }
        __syncthreads();
        if (it + 2 < NITER) AV_LOAD((it + 2) % 3, (it + 2) * 32);
        else CP_COMMIT;
    }
#undef AV_LOAD

#pragma unroll
    for (int ni = 0; ni < 4; ni++) {
        int col = n0 + ni * 8 + 2 * lc;
#pragma unroll
        for (int half_ = 0; half_ < 2; half_++) {
            int row = blockIdx.x * 64 + m0 + lr + half_ * 8;
            *(float2*)&O[(size_t)(b * NT + row) * DIMC + h * HD + col] =
                make_float2(acc[ni][half_*2], acc[ni][half_*2 + 1]);
        }
    }
}

// ============================================================
extern "C" void kernel_launch(void* const* d_in, const int* in_sizes, int n_in,
                              void* d_out, int out_size)
{
    const float* x  = (const float*)d_in[0];
    const float* Wq = (const float*)d_in[1];
    const float* Wk = (const float*)d_in[2];
    const float* Wv = (const float*)d_in[3];
    const float* Wl = (const float*)d_in[4];
    const float* bl = (const float*)d_in[5];
    const float* Ww = (const float*)d_in[6];
    const float* bw = (const float*)d_in[7];
    const float* Wp = (const float*)d_in[8];
    const float* bp = (const float*)d_in[9];
    float* out = (float*)d_out;

    __half *gxh, *gwt, *gq, *gk, *gvt, *gS;
    float *gO;
    cudaGetSymbolAddress((void**)&gxh, g_xh);
    cudaGetSymbolAddress((void**)&gwt, g_wt);
    cudaGetSymbolAddress((void**)&gq, g_q);
    cudaGetSymbolAddress((void**)&gk, g_k);
    cudaGetSymbolAddress((void**)&gvt, g_vt);
    cudaGetSymbolAddress((void**)&gS, g_S);
    cudaGetSymbolAddress((void**)&gO, g_O);

    int qkv_smem = 3 * 2 * 5120 * (int)sizeof(__half);               // 61440
    cudaFuncSetAttribute(qkv_f16,
                         cudaFuncAttributeMaxDynamicSharedMemorySize, qkv_smem);
    int proj_smem = 3 * (128*20 + 16*136) * (int)sizeof(float);      // 56832
    cudaFuncSetAttribute(outproj_tf32,
                         cudaFuncAttributeMaxDynamicSharedMemorySize, proj_smem);
    int score_smem = 2 * 128 * 72 * (int)sizeof(__half);             // 36864
    cudaFuncSetAttribute(score_f16,
                         cudaFuncAttributeMaxDynamicSharedMemorySize, score_smem);
    int av_smem = 3 * 2 * 2560 * (int)sizeof(__half);                // 30720
    cudaFuncSetAttribute(av_f16,
                         cudaFuncAttributeMaxDynamicSharedMemorySize, av_smem);
    int smbytes = (12 * 1024 + 144 + 144 + 12 + 12) * (int)sizeof(float);
    cudaFuncSetAttribute(softmax_mix_kernel,
                         cudaFuncAttributeMaxDynamicSharedMemorySize, smbytes);

    // fp16 conversions
    conv_x<<<M_TOK * DIMC / 1024, 256>>>(x, gxh);
    conv_wt<<<dim3(24, 24, 3), 256>>>(Wq, Wk, Wv, gwt);

    // QKV projections (fp16), one launch; Q pre-scaled; V fp16 transposed
    qkv_f16<<<dim3(6, 64, 3), 256, qkv_smem>>>(gxh, gwt, gq, gk, gvt);

    // raw scores S = Q K^T -> fp16
    score_f16<<<dim3(8, 8, 96), 256, score_smem>>>(gq, gk, gS);

    // fused pre-mix + softmax + post-mix (in place on gS, fp16)
    softmax_mix_kernel<<<dim3(1024, 8), 384, smbytes>>>(gS, Wl, bl, Ww, bw);

    // attn @ V -> [tok, dim], fp16 MMA
    av_f16<<<dim3(16, 96), 256, av_smem>>>(gS, gvt, gO);

    // final projection + bias (tf32 firewall)
    outproj_tf32<<<dim3(6, 64), 256, proj_smem>>>(gO, Wp, out, bp);
}

// round 9
// speedup vs baseline: 1.6549x; 1.1196x over previous
#include <cuda_runtime.h>
#include <cuda_fp16.h>
#include <math.h>

#define DIMC 768
#define NH 12
#define HD 64
#define NB 8
#define NT 1024
#define M_TOK (NB*NT)   // 8192
#define NTNT (NT*NT)

// ---- scratch (device globals: no allocations allowed) ----
__device__ __half g_xh[M_TOK*DIMC];            // x in fp16
__device__ __half g_wt[3*DIMC*DIMC];           // Wq,Wk,Wv fp16 TRANSPOSED [n][k]
__device__ __half g_q[NB*NH*NT*HD];            // [b,h,n,d] fp16, Q pre-scaled
__device__ __half g_k[NB*NH*NT*HD];            // [b,h,n,d] fp16
__device__ __half g_vt[NB*NH*HD*NT];           // [b,h,d,tok] fp16 (transposed V)
__device__ __half g_S[(size_t)NB*NH*NT*NT];    // 201 MB scores / probs fp16 (in place)
__device__ float  g_O[(size_t)M_TOK*DIMC];     // [tok, dim] fp32

// ---------- helpers ----------
__device__ __forceinline__ unsigned f2tf(float f) {
    unsigned u; asm("cvt.rna.tf32.f32 %0, %1;" : "=r"(u) : "f"(f)); return u;
}
__device__ __forceinline__ unsigned ld_tf(const float* p) { return f2tf(*p); }
__device__ __forceinline__ void mma8(float* d, unsigned a0, unsigned a1,
                                     unsigned a2, unsigned a3,
                                     unsigned b0, unsigned b1) {
    asm volatile(
        "mma.sync.aligned.m16n8k8.row.col.f32.tf32.tf32.f32 "
        "{%0,%1,%2,%3},{%4,%5,%6,%7},{%8,%9},{%0,%1,%2,%3};"
        : "+f"(d[0]), "+f"(d[1]), "+f"(d[2]), "+f"(d[3])
        : "r"(a0), "r"(a1), "r"(a2), "r"(a3), "r"(b0), "r"(b1));
}
__device__ __forceinline__ void mma16h(float* d, unsigned a0, unsigned a1,
                                       unsigned a2, unsigned a3,
                                       unsigned b0, unsigned b1) {
    asm volatile(
        "mma.sync.aligned.m16n8k16.row.col.f32.f16.f16.f32 "
        "{%0,%1,%2,%3},{%4,%5,%6,%7},{%8,%9},{%0,%1,%2,%3};"
        : "+f"(d[0]), "+f"(d[1]), "+f"(d[2]), "+f"(d[3])
        : "r"(a0), "r"(a1), "r"(a2), "r"(a3), "r"(b0), "r"(b1));
}
__device__ __forceinline__ void cp16(void* s, const void* g) {
    unsigned sa = (unsigned)__cvta_generic_to_shared(s);
    asm volatile("cp.async.ca.shared.global [%0], [%1], 16;" :: "r"(sa), "l"(g));
}
#define CP_COMMIT asm volatile("cp.async.commit_group;")
#define CP_WAIT1  asm volatile("cp.async.wait_group 1;")
#define CP_WAIT0  asm volatile("cp.async.wait_group 0;")

// ============================================================
// conversion kernels
// ============================================================
__global__ __launch_bounds__(256) void conv_x(
    const float* __restrict__ x, __half* __restrict__ xh)
{
    int i = (blockIdx.x * 256 + threadIdx.x) * 4;
    float4 v = *(const float4*)&x[i];
    *(__half2*)&xh[i]     = __floats2half2_rn(v.x, v.y);
    *(__half2*)&xh[i + 2] = __floats2half2_rn(v.z, v.w);
}

// transpose+convert: out[n][k] = in[k][n], 32x32 tiles, z selects W
__global__ __launch_bounds__(256) void conv_wt(
    const float* __restrict__ Wq, const float* __restrict__ Wk,
    const float* __restrict__ Wv, __half* __restrict__ Wt)
{
    __shared__ float t[32][33];
    int z = blockIdx.z;
    const float* W = (z == 0) ? Wq : (z == 1) ? Wk : Wv;
    __half* out = Wt + (size_t)z * DIMC * DIMC;
    int n0 = blockIdx.x * 32, k0 = blockIdx.y * 32;
    int tx = threadIdx.x & 31, ty = threadIdx.x >> 5;   // 32 x 8
#pragma unroll
    for (int i = ty; i < 32; i += 8)
        t[i][tx] = W[(size_t)(k0 + i) * DIMC + n0 + tx];
    __syncthreads();
#pragma unroll
    for (int i = ty; i < 32; i += 8)
        out[(size_t)(n0 + i) * DIMC + k0 + tx] = __float2half(t[tx][i]);
}

// ============================================================
// qkv_f16: fp16 GEMM C[8192,768] = xh @ Wt^T (Wt is [n][k]).
// 128x128 tile, BK=32, 3-stage cp.async, 256 thr, warp 64x32.
// MODE 1: head-split fp16 [b,h,n,d] (scale). MODE 2: transposed
// fp16 V [b,h,d,tok] via smem staging.
// ============================================================
template<int MODE>
__device__ __forceinline__ void projh_body(
    const __half* __restrict__ A, const __half* __restrict__ Bm,
    __half* __restrict__ C, float scale)
{
    extern __shared__ float smf[];
    __half* As = (__half*)smf;        // [3][128][40]
    __half* Bs = As + 3 * 5120;       // [3][128][40]

    int tid = threadIdx.x, lane = tid & 31, wid = tid >> 5;
    int warp_m = wid & 1, warp_n = wid >> 1;
    int rowBase = blockIdx.y * 128, colBase = blockIdx.x * 128;
    int lr = lane >> 2, lc = lane & 3;
    int m0 = warp_m * 64, n0 = warp_n * 32;

    const __half* Ap = A + (size_t)rowBase * DIMC;
    const __half* Bp = Bm + (size_t)colBase * DIMC;

#define QKV_LOAD(s, k0) do {                                            \
    __half* Ad = As + (s) * 5120;                                       \
    __half* Bd = Bs + (s) * 5120;                                       \
    _Pragma("unroll")                                                   \
    for (int i_ = 0; i_ < 2; i_++) {                                    \
        int t_ = tid + i_ * 256;                                        \
        int r_ = t_ >> 2, c_ = (t_ & 3) * 8;                            \
        cp16(&Ad[r_ * 40 + c_], Ap + (size_t)r_ * DIMC + (k0) + c_);    \
        cp16(&Bd[r_ * 40 + c_], Bp + (size_t)r_ * DIMC + (k0) + c_);    \
    }                                                                   \
    CP_COMMIT;                                                          \
} while (0)

    QKV_LOAD(0, 0);
    QKV_LOAD(1, 32);

    float acc[4][4][4] = {};
    const int NITER = DIMC / 32;   // 24
    for (int it = 0; it < NITER; it++) {
        CP_WAIT1;
        __syncthreads();
        int s = it % 3;
        const __half* Aq = As + s * 5120;
        const __half* Bq = Bs + s * 5120;
#pragma unroll
        for (int kk = 0; kk < 32; kk += 16) {
            unsigned a[4][4], b[4][2];
#pragma unroll
            for (int mi = 0; mi < 4; mi++) {
                int rb = (m0 + mi * 16 + lr) * 40 + kk + 2 * lc;
                a[mi][0] = *(const unsigned*)&Aq[rb];
                a[mi][1] = *(const unsigned*)&Aq[rb + 8 * 40];
                a[mi][2] = *(const unsigned*)&Aq[rb + 8];
                a[mi][3] = *(const unsigned*)&Aq[rb + 8 * 40 + 8];
            }
#pragma unroll
            for (int ni = 0; ni < 4; ni++) {
                int nb = (n0 + ni * 8 + lr) * 40 + kk + 2 * lc;
                b[ni][0] = *(const unsigned*)&Bq[nb];
                b[ni][1] = *(const unsigned*)&Bq[nb + 8];
            }
#pragma unroll
            for (int mi = 0; mi < 4; mi++)
#pragma unroll
                for (int ni = 0; ni < 4; ni++)
                    mma16h(acc[mi][ni], a[mi][0], a[mi][1], a[mi][2], a[mi][3],
                           b[ni][0], b[ni][1]);
        }
        __syncthreads();
        if (it + 2 < NITER) QKV_LOAD((it + 2) % 3, (it + 2) * 32);
        else CP_COMMIT;
    }
#undef QKV_LOAD

    if (MODE == 2) {
        // stage transposed fp16 tile: stg[local_col][local_row], stride 136
        __half* stg = (__half*)smf;   // 34816 B <= 61440 B
#pragma unroll
        for (int mi = 0; mi < 4; mi++) {
#pragma unroll
            for (int ni = 0; ni < 4; ni++) {
                int col = n0 + ni * 8 + 2 * lc;
#pragma unroll
                for (int half_ = 0; half_ < 2; half_++) {
                    int row = m0 + mi * 16 + lr + half_ * 8;
                    stg[col * 136 + row]       = __float2half(acc[mi][ni][half_*2 + 0]);
                    stg[(col + 1) * 136 + row] = __float2half(acc[mi][ni][half_*2 + 1]);
                }
            }
        }
        __syncthreads();
        int b_ = rowBase >> 10;
        int rloc = rowBase & 1023;
        for (int t = tid; t < 128 * 16; t += 256) {
            int col = t >> 4;
            int r8 = (t & 15) * 8;
            int gcol = colBase + col;
            int hh = gcol >> 6, d = gcol & 63;
            size_t dst = ((size_t)(b_ * NH + hh) * HD + d) * NT + rloc + r8;
            *(uint4*)&C[dst] = *(const uint4*)&stg[col * 136 + r8];
        }
        return;
    }

    // MODE 1: fp16 head-split [b,h,n,d]
#pragma unroll
    for (int mi = 0; mi < 4; mi++) {
#pragma unroll
        for (int ni = 0; ni < 4; ni++) {
            int col = colBase + n0 + ni * 8 + 2 * lc;
            int h = col >> 6, d = col & 63;
#pragma unroll
            for (int half_ = 0; half_ < 2; half_++) {
                int row = rowBase + m0 + mi * 16 + lr + half_ * 8;
                int b_ = row >> 10, rr = row & 1023;
                *(__half2*)&C[(((size_t)(b_ * NH + h) * NT + rr) * HD + d)] =
                    __floats2half2_rn(acc[mi][ni][half_*2 + 0] * scale,
                                      acc[mi][ni][half_*2 + 1] * scale);
            }
        }
    }
}

__global__ __launch_bounds__(256, 2) void qkv_f16(
    const __half* __restrict__ xh, const __half* __restrict__ Wt,
    __half* __restrict__ q, __half* __restrict__ k, __half* __restrict__ vt)
{
    int z = blockIdx.z;
    const __half* Bm = Wt + (size_t)z * DIMC * DIMC;
    if (z == 0)      projh_body<1>(xh, Bm, q, 0.125f);
    else if (z == 1) projh_body<1>(xh, Bm, k, 1.0f);
    else             projh_body<2>(xh, Bm, vt, 1.0f);
}

// ============================================================
// outproj (tf32, fp32 inputs) — numerics firewall kept intact
// ============================================================
__global__ __launch_bounds__(256, 2) void outproj_tf32(
    const float* __restrict__ A, const float* __restrict__ Bm,
    float* __restrict__ C, const float* __restrict__ bias)
{
    extern __shared__ float sm[];
    float* As = sm;               // [3][128][20]
    float* Bs = sm + 3 * 2560;    // [3][16][136]

    int tid = threadIdx.x, lane = tid & 31, wid = tid >> 5;
    int warp_m = wid & 1, warp_n = wid >> 1;
    int rowBase = blockIdx.y * 128, colBase = blockIdx.x * 128;
    int lr = lane >> 2, lc = lane & 3;
    int m0 = warp_m * 64, n0 = warp_n * 32;

    const float* Ap = A + (size_t)rowBase * DIMC;
    const float* Bp = Bm + colBase;

#define PROJ_LOAD(s, k0) do {                                          \
    float* Ad = As + (s) * 2560;                                       \
    float* Bd = Bs + (s) * 2176;                                       \
    _Pragma("unroll")                                                  \
    for (int i_ = 0; i_ < 2; i_++) {                                   \
        int t_ = tid + i_ * 256;                                       \
        int r_ = t_ >> 2, c_ = (t_ & 3) * 4;                           \
        cp16(&Ad[r_ * 20 + c_], Ap + (size_t)r_ * DIMC + (k0) + c_);   \
        int br_ = t_ >> 5, bc_ = (t_ & 31) * 4;                        \
        cp16(&Bd[br_ * 136 + bc_], Bp + (size_t)((k0) + br_) * DIMC + bc_); \
    }                                                                  \
    CP_COMMIT;                                                         \
} while (0)

    PROJ_LOAD(0, 0);
    PROJ_LOAD(1, 16);

    float acc[4][4][4] = {};
    const int NITER = DIMC / 16;   // 48
    for (int it = 0; it < NITER; it++) {
        CP_WAIT1;
        __syncthreads();
        int s = it % 3;
        const float* Aq = As + s * 2560;
        const float* Bq = Bs + s * 2176;
#pragma unroll
        for (int kk = 0; kk < 16; kk += 8) {
            unsigned a[4][4], b[4][2];
#pragma unroll
            for (int mi = 0; mi < 4; mi++) {
                int r = m0 + mi * 16 + lr;
                a[mi][0] = ld_tf(&Aq[r * 20 + kk + lc]);
                a[mi][1] = ld_tf(&Aq[(r + 8) * 20 + kk + lc]);
                a[mi][2] = ld_tf(&Aq[r * 20 + kk + lc + 4]);
                a[mi][3] = ld_tf(&Aq[(r + 8) * 20 + kk + lc + 4]);
            }
#pragma unroll
            for (int ni = 0; ni < 4; ni++) {
                int c = n0 + ni * 8 + lr;
                b[ni][0] = ld_tf(&Bq[(kk + lc) * 136 + c]);
                b[ni][1] = ld_tf(&Bq[(kk + lc + 4) * 136 + c]);
            }
#pragma unroll
            for (int mi = 0; mi < 4; mi++)
#pragma unroll
                for (int ni = 0; ni < 4; ni++)
                    mma8(acc[mi][ni], a[mi][0], a[mi][1], a[mi][2], a[mi][3],
                         b[ni][0], b[ni][1]);
        }
        __syncthreads();
        if (it + 2 < NITER) PROJ_LOAD((it + 2) % 3, (it + 2) * 16);
        else CP_COMMIT;
    }
#undef PROJ_LOAD

#pragma unroll
    for (int mi = 0; mi < 4; mi++) {
#pragma unroll
        for (int ni = 0; ni < 4; ni++) {
            int col = colBase + n0 + ni * 8 + 2 * lc;
            float bv0 = bias[col], bv1 = bias[col + 1];
#pragma unroll
            for (int half_ = 0; half_ < 2; half_++) {
                int row = rowBase + m0 + mi * 16 + lr + half_ * 8;
                *(float2*)&C[(size_t)row * DIMC + col] =
                    make_float2(acc[mi][ni][half_*2 + 0] + bv0,
                                acc[mi][ni][half_*2 + 1] + bv1);
            }
        }
    }
}

// ============================================================
// score_f16: per (b,h): S = Q(1024x64) @ K^T, fp16 MMA.
// 128x128 tile, whole K=64 in smem. Writes S fp16.
// ============================================================
__global__ __launch_bounds__(256, 2) void score_f16(
    const __half* __restrict__ Q, const __half* __restrict__ Kp,
    __half* __restrict__ S)
{
    extern __shared__ float smf[];
    __half* Qs = (__half*)smf;        // [128][72]
    __half* Ks = Qs + 128 * 72;       // [128][72]

    int bh = blockIdx.z;
    const __half* Qg = Q + (size_t)bh * NT * HD + (size_t)blockIdx.y * 128 * HD;
    const __half* Kg = Kp + (size_t)bh * NT * HD + (size_t)blockIdx.x * 128 * HD;

    int tid = threadIdx.x, lane = tid & 31, wid = tid >> 5;
    int lr = lane >> 2, lc = lane & 3;
    int warp_m = wid & 1, warp_n = wid >> 1;
    int m0 = warp_m * 64, n0 = warp_n * 32;

#pragma unroll
    for (int i = 0; i < 4; i++) {
        int t = tid + i * 256;
        int r = t >> 3, c = (t & 7) * 8;
        cp16(&Qs[r * 72 + c], Qg + (size_t)r * HD + c);
        cp16(&Ks[r * 72 + c], Kg + (size_t)r * HD + c);
    }
    CP_COMMIT;
    CP_WAIT0;
    __syncthreads();

    float acc[4][4][4] = {};
#pragma unroll
    for (int kk = 0; kk < 64; kk += 16) {
        unsigned a[4][4], b[4][2];
#pragma unroll
        for (int mi = 0; mi < 4; mi++) {
            int rb = (m0 + mi * 16 + lr) * 72 + kk + 2 * lc;
            a[mi][0] = *(const unsigned*)&Qs[rb];
            a[mi][1] = *(const unsigned*)&Qs[rb + 8 * 72];
            a[mi][2] = *(const unsigned*)&Qs[rb + 8];
            a[mi][3] = *(const unsigned*)&Qs[rb + 8 * 72 + 8];
        }
#pragma unroll
        for (int ni = 0; ni < 4; ni++) {
            int nb = (n0 + ni * 8 + lr) * 72 + kk + 2 * lc;
            b[ni][0] = *(const unsigned*)&Ks[nb];
            b[ni][1] = *(const unsigned*)&Ks[nb + 8];
        }
#pragma unroll
        for (int mi = 0; mi < 4; mi++)
#pragma unroll
            for (int ni = 0; ni < 4; ni++)
                mma16h(acc[mi][ni], a[mi][0], a[mi][1], a[mi][2], a[mi][3],
                       b[ni][0], b[ni][1]);
    }

    __half* Sg = S + (size_t)bh * NTNT;
#pragma unroll
    for (int mi = 0; mi < 4; mi++) {
#pragma unroll
        for (int ni = 0; ni < 4; ni++) {
            int c = blockIdx.x * 128 + n0 + ni * 8 + 2 * lc;
#pragma unroll
            for (int half_ = 0; half_ < 2; half_++) {
                int r = blockIdx.y * 128 + m0 + mi * 16 + lr + half_ * 8;
                *(__half2*)&Sg[(size_t)r * NT + c] =
                    __floats2half2_rn(acc[mi][ni][half_*2], acc[mi][ni][half_*2 + 1]);
            }
        }
    }
}

// ============================================================
// softmax_mix_reg: register-resident talking-heads softmax.
// 1 query row per CTA, 256 thr; each thread owns 4 consecutive
// j columns x all 12 heads, fully in registers. Two 12-value
// block reductions (max, sum) via shfl + tiny smem matrix.
// ============================================================
__global__ __launch_bounds__(256) void softmax_mix_reg(
    __half* __restrict__ S, const float* __restrict__ Wl,
    const float* __restrict__ bl, const float* __restrict__ Ww,
    const float* __restrict__ bw)
{
    __shared__ float wl[144], ww[144], blv[12], bwv[12];
    __shared__ float red[8][12];

    int tid = threadIdx.x, lane = tid & 31, wid = tid >> 5;
    int i = blockIdx.x, b = blockIdx.y;
    if (tid < 144) { wl[tid] = Wl[tid]; ww[tid] = Ww[tid]; }
    if (tid < 12)  { blv[tid] = bl[tid]; bwv[tid] = bw[tid]; }
    __syncthreads();

    size_t rowbase = (size_t)b * NH * NTNT + (size_t)i * NT;
    int j0 = tid * 4;

    // load raw scores: 12 heads x 4 j (half2 pairs), MLP=12
    __half2 raw[12][2];
#pragma unroll
    for (int h = 0; h < 12; h++) {
        uint2 u = *(const uint2*)&S[rowbase + (size_t)h * NTNT + j0];
        raw[h][0] = *(__half2*)&u.x;
        raw[h][1] = *(__half2*)&u.y;
    }

    // pre-softmax talking-heads mix -> m[g][j] (fp32 regs)
    float m[12][4];
#pragma unroll
    for (int jj = 0; jj < 4; jj++) {
        float s[12];
#pragma unroll
        for (int h = 0; h < 12; h++) {
            float2 f = __half22float2(raw[h][jj >> 1]);
            s[h] = (jj & 1) ? f.y : f.x;
        }
#pragma unroll
        for (int g = 0; g < 12; g++) {
            float a = blv[g];
#pragma unroll
            for (int h = 0; h < 12; h++) a = fmaf(wl[g * 12 + h], s[h], a);
            m[g][jj] = a;
        }
    }

    // block max per head
#pragma unroll
    for (int h = 0; h < 12; h++) {
        float a = fmaxf(fmaxf(m[h][0], m[h][1]), fmaxf(m[h][2], m[h][3]));
#pragma unroll
        for (int o = 16; o; o >>= 1) a = fmaxf(a, __shfl_xor_sync(0xffffffffu, a, o));
        if (lane == 0) red[wid][h] = a;
    }
    __syncthreads();
    float mxv[12];
#pragma unroll
    for (int h = 0; h < 12; h++) {
        float a = red[0][h];
#pragma unroll
        for (int w = 1; w < 8; w++) a = fmaxf(a, red[w][h]);
        mxv[h] = a;
    }
    __syncthreads();   // before reusing red

    // exp + block sum per head
#pragma unroll
    for (int h = 0; h < 12; h++) {
        float s0 = 0.f;
#pragma unroll
        for (int jj = 0; jj < 4; jj++) {
            float e = __expf(m[h][jj] - mxv[h]);
            m[h][jj] = e;
            s0 += e;
        }
#pragma unroll
        for (int o = 16; o; o >>= 1) s0 += __shfl_xor_sync(0xffffffffu, s0, o);
        if (lane == 0) red[wid][h] = s0;
    }
    __syncthreads();
#pragma unroll
    for (int h = 0; h < 12; h++) {
        float s0 = red[0][h];
#pragma unroll
        for (int w = 1; w < 8; w++) s0 += red[w][h];
        float rinv = 1.f / s0;
#pragma unroll
        for (int jj = 0; jj < 4; jj++) m[h][jj] *= rinv;
    }

    // post-softmax mix + fp16 store
#pragma unroll
    for (int g = 0; g < 12; g++) {
        float o0 = bwv[g], o1 = bwv[g], o2 = bwv[g], o3 = bwv[g];
#pragma unroll
        for (int h = 0; h < 12; h++) {
            float w = ww[g * 12 + h];
            o0 = fmaf(w, m[h][0], o0);
            o1 = fmaf(w, m[h][1], o1);
            o2 = fmaf(w, m[h][2], o2);
            o3 = fmaf(w, m[h][3], o3);
        }
        uint2 u;
        *(__half2*)&u.x = __floats2half2_rn(o0, o1);
        *(__half2*)&u.y = __floats2half2_rn(o2, o3);
        *(uint2*)&S[rowbase + (size_t)g * NTNT + j0] = u;
    }
}

// ============================================================
// av_f16: per (b,h): O(1024x64) = P(1024x1024) @ V(1024x64),
// fp16 MMA m16n8k16, fp32 accum. V pre-transposed [d][tok].
// 64x64 tile, BK=32, 3-stage cp.async, 256 thr.
// ============================================================
__global__ __launch_bounds__(256, 4) void av_f16(
    const __half* __restrict__ P, const __half* __restrict__ Vt,
    float* __restrict__ O)
{
    extern __shared__ float sm[];
    __half* Ps = (__half*)sm;            // [3][64][40]
    __half* Vs = Ps + 3 * 2560;          // [3][64][40]

    int bh = blockIdx.y;
    int b = bh / NH, h = bh % NH;
    const __half* Pg = P + (size_t)bh * NTNT + (size_t)blockIdx.x * 64 * NT;
    const __half* Vg = Vt + (size_t)bh * HD * NT;   // [d][tok]

    int tid = threadIdx.x, lane = tid & 31, wid = tid >> 5;
    int lr = lane >> 2, lc = lane & 3;
    int m0 = (wid & 3) * 16, n0 = (wid >> 2) * 32;

    int ldr = tid >> 2, ldc = (tid & 3) * 8;

#define AV_LOAD(s, k0) do {                                             \
    __half* Pd = Ps + (s) * 2560;                                       \
    __half* Vd = Vs + (s) * 2560;                                       \
    cp16(&Pd[ldr * 40 + ldc], Pg + (size_t)ldr * NT + (k0) + ldc);      \
    cp16(&Vd[ldr * 40 + ldc], Vg + (size_t)ldr * NT + (k0) + ldc);      \
    CP_COMMIT;                                                          \
} while (0)

    AV_LOAD(0, 0);
    AV_LOAD(1, 32);

    float acc[4][4] = {};
    const int NITER = NT / 32;   // 32
    for (int it = 0; it < NITER; it++) {
        CP_WAIT1;
        __syncthreads();
        int s = it % 3;
        const __half* Pq = Ps + s * 2560;
        const __half* Vq = Vs + s * 2560;
#pragma unroll
        for (int kk = 0; kk < 32; kk += 16) {
            unsigned a0, a1, a2, a3;
            {
                int rb = (m0 + lr) * 40 + kk + 2 * lc;
                a0 = *(const unsigned*)&Pq[rb];
                a1 = *(const unsigned*)&Pq[rb + 8 * 40];
                a2 = *(const unsigned*)&Pq[rb + 8];
                a3 = *(const unsigned*)&Pq[rb + 8 * 40 + 8];
            }
#pragma unroll
            for (int ni = 0; ni < 4; ni++) {
                int nb = (n0 + ni * 8 + lr) * 40 + kk + 2 * lc;
                unsigned b0 = *(const unsigned*)&Vq[nb];
                unsigned b1 = *(const unsigned*)&Vq[nb + 8];
                mma16h(acc[ni], a0, a1, a2, a3, b0, b1);
            }
        }
        __syncthreads();
        if (it + 2 < NITER) AV_LOAD((it + 2) % 3, (it + 2) * 32);
        else CP_COMMIT;
    }
#undef AV_LOAD

#pragma unroll
    for (int ni = 0; ni < 4; ni++) {
        int col = n0 + ni * 8 + 2 * lc;
#pragma unroll
        for (int half_ = 0; half_ < 2; half_++) {
            int row = blockIdx.x * 64 + m0 + lr + half_ * 8;
            *(float2*)&O[(size_t)(b * NT + row) * DIMC + h * HD + col] =
                make_float2(acc[ni][half_*2], acc[ni][half_*2 + 1]);
        }
    }
}

// ============================================================
extern "C" void kernel_launch(void* const* d_in, const int* in_sizes, int n_in,
                              void* d_out, int out_size)
{
    const float* x  = (const float*)d_in[0];
    const float* Wq = (const float*)d_in[1];
    const float* Wk = (const float*)d_in[2];
    const float* Wv = (const float*)d_in[3];
    const float* Wl = (const float*)d_in[4];
    const float* bl = (const float*)d_in[5];
    const float* Ww = (const float*)d_in[6];
    const float* bw = (const float*)d_in[7];
    const float* Wp = (const float*)d_in[8];
    const float* bp = (const float*)d_in[9];
    float* out = (float*)d_out;

    __half *gxh, *gwt, *gq, *gk, *gvt, *gS;
    float *gO;
    cudaGetSymbolAddress((void**)&gxh, g_xh);
    cudaGetSymbolAddress((void**)&gwt, g_wt);
    cudaGetSymbolAddress((void**)&gq, g_q);
    cudaGetSymbolAddress((void**)&gk, g_k);
    cudaGetSymbolAddress((void**)&gvt, g_vt);
    cudaGetSymbolAddress((void**)&gS, g_S);
    cudaGetSymbolAddress((void**)&gO, g_O);

    int qkv_smem = 3 * 2 * 5120 * (int)sizeof(__half);               // 61440
    cudaFuncSetAttribute(qkv_f16,
                         cudaFuncAttributeMaxDynamicSharedMemorySize, qkv_smem);
    int proj_smem = 3 * (128*20 + 16*136) * (int)sizeof(float);      // 56832
    cudaFuncSetAttribute(outproj_tf32,
                         cudaFuncAttributeMaxDynamicSharedMemorySize, proj_smem);
    int score_smem = 2 * 128 * 72 * (int)sizeof(__half);             // 36864
    cudaFuncSetAttribute(score_f16,
                         cudaFuncAttributeMaxDynamicSharedMemorySize, score_smem);
    int av_smem = 3 * 2 * 2560 * (int)sizeof(__half);                // 30720
    cudaFuncSetAttribute(av_f16,
                         cudaFuncAttributeMaxDynamicSharedMemorySize, av_smem);

    // fp16 conversions
    conv_x<<<M_TOK * DIMC / 1024, 256>>>(x, gxh);
    conv_wt<<<dim3(24, 24, 3), 256>>>(Wq, Wk, Wv, gwt);

    // QKV projections (fp16), one launch; Q pre-scaled; V fp16 transposed
    qkv_f16<<<dim3(6, 64, 3), 256, qkv_smem>>>(gxh, gwt, gq, gk, gvt);

    // raw scores S = Q K^T -> fp16
    score_f16<<<dim3(8, 8, 96), 256, score_smem>>>(gq, gk, gS);

    // register-resident fused pre-mix + softmax + post-mix (in place on gS)
    softmax_mix_reg<<<dim3(1024, 8), 256>>>(gS, Wl, bl, Ww, bw);

    // attn @ V -> [tok, dim], fp16 MMA
    av_f16<<<dim3(16, 96), 256, av_smem>>>(gS, gvt, gO);

    // final projection + bias (tf32 firewall)
    outproj_tf32<<<dim3(6, 64), 256, proj_smem>>>(gO, Wp, out, bp);
}

// round 10
// speedup vs baseline: 1.7369x; 1.0496x over previous
#include <cuda_runtime.h>
#include <cuda_fp16.h>
#include <math.h>

#define DIMC 768
#define NH 12
#define HD 64
#define NB 8
#define NT 1024
#define M_TOK (NB*NT)   // 8192
#define NTNT (NT*NT)

// ---- scratch (device globals: no allocations allowed) ----
__device__ __half g_xh[M_TOK*DIMC];            // x in fp16
__device__ __half g_wt[4*DIMC*DIMC];           // Wq,Wk,Wv,Wp fp16 TRANSPOSED [n][k]
__device__ __half g_q[NB*NH*NT*HD];            // [b,h,n,d] fp16, Q pre-scaled
__device__ __half g_k[NB*NH*NT*HD];            // [b,h,n,d] fp16
__device__ __half g_vt[NB*NH*HD*NT];           // [b,h,d,tok] fp16 (transposed V)
__device__ __half g_S[(size_t)NB*NH*NT*NT];    // 201 MB scores / probs fp16 (in place)
__device__ __half g_Oh[(size_t)M_TOK*DIMC];    // [tok, dim] fp16

// ---------- helpers ----------
__device__ __forceinline__ void mma16h(float* d, unsigned a0, unsigned a1,
                                       unsigned a2, unsigned a3,
                                       unsigned b0, unsigned b1) {
    asm volatile(
        "mma.sync.aligned.m16n8k16.row.col.f32.f16.f16.f32 "
        "{%0,%1,%2,%3},{%4,%5,%6,%7},{%8,%9},{%0,%1,%2,%3};"
        : "+f"(d[0]), "+f"(d[1]), "+f"(d[2]), "+f"(d[3])
        : "r"(a0), "r"(a1), "r"(a2), "r"(a3), "r"(b0), "r"(b1));
}
__device__ __forceinline__ void cp16(void* s, const void* g) {
    unsigned sa = (unsigned)__cvta_generic_to_shared(s);
    asm volatile("cp.async.ca.shared.global [%0], [%1], 16;" :: "r"(sa), "l"(g));
}
#define CP_COMMIT asm volatile("cp.async.commit_group;")
#define CP_WAIT1  asm volatile("cp.async.wait_group 1;")
#define CP_WAIT0  asm volatile("cp.async.wait_group 0;")

// ============================================================
// conversion kernels
// ============================================================
__global__ __launch_bounds__(256) void conv_x(
    const float* __restrict__ x, __half* __restrict__ xh)
{
    int i = (blockIdx.x * 256 + threadIdx.x) * 4;
    float4 v = *(const float4*)&x[i];
    *(__half2*)&xh[i]     = __floats2half2_rn(v.x, v.y);
    *(__half2*)&xh[i + 2] = __floats2half2_rn(v.z, v.w);
}

// transpose+convert: out[n][k] = in[k][n], 32x32 tiles, z selects W
__global__ __launch_bounds__(256) void conv_wt(
    const float* __restrict__ Wq, const float* __restrict__ Wk,
    const float* __restrict__ Wv, const float* __restrict__ Wp,
    __half* __restrict__ Wt)
{
    __shared__ float t[32][33];
    int z = blockIdx.z;
    const float* W = (z == 0) ? Wq : (z == 1) ? Wk : (z == 2) ? Wv : Wp;
    __half* out = Wt + (size_t)z * DIMC * DIMC;
    int n0 = blockIdx.x * 32, k0 = blockIdx.y * 32;
    int tx = threadIdx.x & 31, ty = threadIdx.x >> 5;   // 32 x 8
#pragma unroll
    for (int i = ty; i < 32; i += 8)
        t[i][tx] = W[(size_t)(k0 + i) * DIMC + n0 + tx];
    __syncthreads();
#pragma unroll
    for (int i = ty; i < 32; i += 8)
        out[(size_t)(n0 + i) * DIMC + k0 + tx] = __float2half(t[tx][i]);
}

// ============================================================
// fp16 GEMM body: C[8192,768] = A @ Bm^T (Bm is [n][k] fp16).
// 128x128 tile, BK=32, 3-stage cp.async, 256 thr, warp 64x32.
// MODE 1: head-split fp16 [b,h,n,d] (scale).
// MODE 2: transposed fp16 V [b,h,d,tok] via smem staging.
// MODE 3: plain fp32 out + bias.
// ============================================================
template<int MODE>
__device__ __forceinline__ void projh_body(
    const __half* __restrict__ A, const __half* __restrict__ Bm,
    float* __restrict__ Cf, __half* __restrict__ Ch,
    const float* __restrict__ bias, float scale)
{
    extern __shared__ float smf[];
    __half* As = (__half*)smf;        // [3][128][40]
    __half* Bs = As + 3 * 5120;       // [3][128][40]

    int tid = threadIdx.x, lane = tid & 31, wid = tid >> 5;
    int warp_m = wid & 1, warp_n = wid >> 1;
    int rowBase = blockIdx.y * 128, colBase = blockIdx.x * 128;
    int lr = lane >> 2, lc = lane & 3;
    int m0 = warp_m * 64, n0 = warp_n * 32;

    const __half* Ap = A + (size_t)rowBase * DIMC;
    const __half* Bp = Bm + (size_t)colBase * DIMC;

#define QKV_LOAD(s, k0) do {                                            \
    __half* Ad = As + (s) * 5120;                                       \
    __half* Bd = Bs + (s) * 5120;                                       \
    _Pragma("unroll")                                                   \
    for (int i_ = 0; i_ < 2; i_++) {                                    \
        int t_ = tid + i_ * 256;                                        \
        int r_ = t_ >> 2, c_ = (t_ & 3) * 8;                            \
        cp16(&Ad[r_ * 40 + c_], Ap + (size_t)r_ * DIMC + (k0) + c_);    \
        cp16(&Bd[r_ * 40 + c_], Bp + (size_t)r_ * DIMC + (k0) + c_);    \
    }                                                                   \
    CP_COMMIT;                                                          \
} while (0)

    QKV_LOAD(0, 0);
    QKV_LOAD(1, 32);

    float acc[4][4][4] = {};
    const int NITER = DIMC / 32;   // 24
    for (int it = 0; it < NITER; it++) {
        CP_WAIT1;
        __syncthreads();
        int s = it % 3;
        const __half* Aq = As + s * 5120;
        const __half* Bq = Bs + s * 5120;
#pragma unroll
        for (int kk = 0; kk < 32; kk += 16) {
            unsigned a[4][4], b[4][2];
#pragma unroll
            for (int mi = 0; mi < 4; mi++) {
                int rb = (m0 + mi * 16 + lr) * 40 + kk + 2 * lc;
                a[mi][0] = *(const unsigned*)&Aq[rb];
                a[mi][1] = *(const unsigned*)&Aq[rb + 8 * 40];
                a[mi][2] = *(const unsigned*)&Aq[rb + 8];
                a[mi][3] = *(const unsigned*)&Aq[rb + 8 * 40 + 8];
            }
#pragma unroll
            for (int ni = 0; ni < 4; ni++) {
                int nb = (n0 + ni * 8 + lr) * 40 + kk + 2 * lc;
                b[ni][0] = *(const unsigned*)&Bq[nb];
                b[ni][1] = *(const unsigned*)&Bq[nb + 8];
            }
#pragma unroll
            for (int mi = 0; mi < 4; mi++)
#pragma unroll
                for (int ni = 0; ni < 4; ni++)
                    mma16h(acc[mi][ni], a[mi][0], a[mi][1], a[mi][2], a[mi][3],
                           b[ni][0], b[ni][1]);
        }
        __syncthreads();
        if (it + 2 < NITER) QKV_LOAD((it + 2) % 3, (it + 2) * 32);
        else CP_COMMIT;
    }
#undef QKV_LOAD

    if (MODE == 2) {
        // stage transposed fp16 tile: stg[local_col][local_row], stride 136
        __half* stg = (__half*)smf;   // 34816 B <= 61440 B
#pragma unroll
        for (int mi = 0; mi < 4; mi++) {
#pragma unroll
            for (int ni = 0; ni < 4; ni++) {
                int col = n0 + ni * 8 + 2 * lc;
#pragma unroll
                for (int half_ = 0; half_ < 2; half_++) {
                    int row = m0 + mi * 16 + lr + half_ * 8;
                    stg[col * 136 + row]       = __float2half(acc[mi][ni][half_*2 + 0]);
                    stg[(col + 1) * 136 + row] = __float2half(acc[mi][ni][half_*2 + 1]);
                }
            }
        }
        __syncthreads();
        int b_ = rowBase >> 10;
        int rloc = rowBase & 1023;
        for (int t = tid; t < 128 * 16; t += 256) {
            int col = t >> 4;
            int r8 = (t & 15) * 8;
            int gcol = colBase + col;
            int hh = gcol >> 6, d = gcol & 63;
            size_t dst = ((size_t)(b_ * NH + hh) * HD + d) * NT + rloc + r8;
            *(uint4*)&Ch[dst] = *(const uint4*)&stg[col * 136 + r8];
        }
        return;
    }

#pragma unroll
    for (int mi = 0; mi < 4; mi++) {
#pragma unroll
        for (int ni = 0; ni < 4; ni++) {
            int col = colBase + n0 + ni * 8 + 2 * lc;
            float bv0 = 0.f, bv1 = 0.f;
            if (MODE == 3) { bv0 = bias[col]; bv1 = bias[col + 1]; }
#pragma unroll
            for (int half_ = 0; half_ < 2; half_++) {
                int row = rowBase + m0 + mi * 16 + lr + half_ * 8;
                if (MODE == 3) {
                    *(float2*)&Cf[(size_t)row * DIMC + col] =
                        make_float2(acc[mi][ni][half_*2 + 0] + bv0,
                                    acc[mi][ni][half_*2 + 1] + bv1);
                } else {    // MODE 1: fp16 head-split [b,h,n,d]
                    int b_ = row >> 10, rr = row & 1023;
                    int h = col >> 6, d = col & 63;
                    *(__half2*)&Ch[(((size_t)(b_ * NH + h) * NT + rr) * HD + d)] =
                        __floats2half2_rn(acc[mi][ni][half_*2 + 0] * scale,
                                          acc[mi][ni][half_*2 + 1] * scale);
                }
            }
        }
    }
}

__global__ __launch_bounds__(256, 2) void qkv_f16(
    const __half* __restrict__ xh, const __half* __restrict__ Wt,
    __half* __restrict__ q, __half* __restrict__ k, __half* __restrict__ vt)
{
    int z = blockIdx.z;
    const __half* Bm = Wt + (size_t)z * DIMC * DIMC;
    if (z == 0)      projh_body<1>(xh, Bm, nullptr, q, nullptr, 0.125f);
    else if (z == 1) projh_body<1>(xh, Bm, nullptr, k, nullptr, 1.0f);
    else             projh_body<2>(xh, Bm, nullptr, vt, nullptr, 1.0f);
}

__global__ __launch_bounds__(256, 2) void outproj_f16(
    const __half* __restrict__ Oh, const __half* __restrict__ Wt,
    float* __restrict__ C, const float* __restrict__ bias)
{
    projh_body<3>(Oh, Wt + (size_t)3 * DIMC * DIMC, C, nullptr, bias, 1.0f);
}

// ============================================================
// score_f16: per (b,h): S = Q(1024x64) @ K^T, fp16 MMA.
// 128x128 tile, whole K=64 in smem. Writes S fp16.
// ============================================================
__global__ __launch_bounds__(256, 2) void score_f16(
    const __half* __restrict__ Q, const __half* __restrict__ Kp,
    __half* __restrict__ S)
{
    extern __shared__ float smf[];
    __half* Qs = (__half*)smf;        // [128][72]
    __half* Ks = Qs + 128 * 72;       // [128][72]

    int bh = blockIdx.z;
    const __half* Qg = Q + (size_t)bh * NT * HD + (size_t)blockIdx.y * 128 * HD;
    const __half* Kg = Kp + (size_t)bh * NT * HD + (size_t)blockIdx.x * 128 * HD;

    int tid = threadIdx.x, lane = tid & 31, wid = tid >> 5;
    int lr = lane >> 2, lc = lane & 3;
    int warp_m = wid & 1, warp_n = wid >> 1;
    int m0 = warp_m * 64, n0 = warp_n * 32;

#pragma unroll
    for (int i = 0; i < 4; i++) {
        int t = tid + i * 256;
        int r = t >> 3, c = (t & 7) * 8;
        cp16(&Qs[r * 72 + c], Qg + (size_t)r * HD + c);
        cp16(&Ks[r * 72 + c], Kg + (size_t)r * HD + c);
    }
    CP_COMMIT;
    CP_WAIT0;
    __syncthreads();

    float acc[4][4][4] = {};
#pragma unroll
    for (int kk = 0; kk < 64; kk += 16) {
        unsigned a[4][4], b[4][2];
#pragma unroll
        for (int mi = 0; mi < 4; mi++) {
            int rb = (m0 + mi * 16 + lr) * 72 + kk + 2 * lc;
            a[mi][0] = *(const unsigned*)&Qs[rb];
            a[mi][1] = *(const unsigned*)&Qs[rb + 8 * 72];
            a[mi][2] = *(const unsigned*)&Qs[rb + 8];
            a[mi][3] = *(const unsigned*)&Qs[rb + 8 * 72 + 8];
        }
#pragma unroll
        for (int ni = 0; ni < 4; ni++) {
            int nb = (n0 + ni * 8 + lr) * 72 + kk + 2 * lc;
            b[ni][0] = *(const unsigned*)&Ks[nb];
            b[ni][1] = *(const unsigned*)&Ks[nb + 8];
        }
#pragma unroll
        for (int mi = 0; mi < 4; mi++)
#pragma unroll
            for (int ni = 0; ni < 4; ni++)
                mma16h(acc[mi][ni], a[mi][0], a[mi][1], a[mi][2], a[mi][3],
                       b[ni][0], b[ni][1]);
    }

    __half* Sg = S + (size_t)bh * NTNT;
#pragma unroll
    for (int mi = 0; mi < 4; mi++) {
#pragma unroll
        for (int ni = 0; ni < 4; ni++) {
            int c = blockIdx.x * 128 + n0 + ni * 8 + 2 * lc;
#pragma unroll
            for (int half_ = 0; half_ < 2; half_++) {
                int r = blockIdx.y * 128 + m0 + mi * 16 + lr + half_ * 8;
                *(__half2*)&Sg[(size_t)r * NT + c] =
                    __floats2half2_rn(acc[mi][ni][half_*2], acc[mi][ni][half_*2 + 1]);
            }
        }
    }
}

// ============================================================
// softmax_mix_reg: register-resident talking-heads softmax.
// 1 query row per CTA, 256 thr; each thread owns 4 consecutive
// j columns x all 12 heads, fully in registers.
// ============================================================
__global__ __launch_bounds__(256) void softmax_mix_reg(
    __half* __restrict__ S, const float* __restrict__ Wl,
    const float* __restrict__ bl, const float* __restrict__ Ww,
    const float* __restrict__ bw)
{
    __shared__ float wl[144], ww[144], blv[12], bwv[12];
    __shared__ float red[8][12];

    int tid = threadIdx.x, lane = tid & 31, wid = tid >> 5;
    int i = blockIdx.x, b = blockIdx.y;
    if (tid < 144) { wl[tid] = Wl[tid]; ww[tid] = Ww[tid]; }
    if (tid < 12)  { blv[tid] = bl[tid]; bwv[tid] = bw[tid]; }
    __syncthreads();

    size_t rowbase = (size_t)b * NH * NTNT + (size_t)i * NT;
    int j0 = tid * 4;

    __half2 raw[12][2];
#pragma unroll
    for (int h = 0; h < 12; h++) {
        uint2 u = *(const uint2*)&S[rowbase + (size_t)h * NTNT + j0];
        raw[h][0] = *(__half2*)&u.x;
        raw[h][1] = *(__half2*)&u.y;
    }

    float m[12][4];
#pragma unroll
    for (int jj = 0; jj < 4; jj++) {
        float s[12];
#pragma unroll
        for (int h = 0; h < 12; h++) {
            float2 f = __half22float2(raw[h][jj >> 1]);
            s[h] = (jj & 1) ? f.y : f.x;
        }
#pragma unroll
        for (int g = 0; g < 12; g++) {
            float a = blv[g];
#pragma unroll
            for (int h = 0; h < 12; h++) a = fmaf(wl[g * 12 + h], s[h], a);
            m[g][jj] = a;
        }
    }

#pragma unroll
    for (int h = 0; h < 12; h++) {
        float a = fmaxf(fmaxf(m[h][0], m[h][1]), fmaxf(m[h][2], m[h][3]));
#pragma unroll
        for (int o = 16; o; o >>= 1) a = fmaxf(a, __shfl_xor_sync(0xffffffffu, a, o));
        if (lane == 0) red[wid][h] = a;
    }
    __syncthreads();
    float mxv[12];
#pragma unroll
    for (int h = 0; h < 12; h++) {
        float a = red[0][h];
#pragma unroll
        for (int w = 1; w < 8; w++) a = fmaxf(a, red[w][h]);
        mxv[h] = a;
    }
    __syncthreads();

#pragma unroll
    for (int h = 0; h < 12; h++) {
        float s0 = 0.f;
#pragma unroll
        for (int jj = 0; jj < 4; jj++) {
            float e = __expf(m[h][jj] - mxv[h]);
            m[h][jj] = e;
            s0 += e;
        }
#pragma unroll
        for (int o = 16; o; o >>= 1) s0 += __shfl_xor_sync(0xffffffffu, s0, o);
        if (lane == 0) red[wid][h] = s0;
    }
    __syncthreads();
#pragma unroll
    for (int h = 0; h < 12; h++) {
        float s0 = red[0][h];
#pragma unroll
        for (int w = 1; w < 8; w++) s0 += red[w][h];
        float rinv = 1.f / s0;
#pragma unroll
        for (int jj = 0; jj < 4; jj++) m[h][jj] *= rinv;
    }

#pragma unroll
    for (int g = 0; g < 12; g++) {
        float o0 = bwv[g], o1 = bwv[g], o2 = bwv[g], o3 = bwv[g];
#pragma unroll
        for (int h = 0; h < 12; h++) {
            float w = ww[g * 12 + h];
            o0 = fmaf(w, m[h][0], o0);
            o1 = fmaf(w, m[h][1], o1);
            o2 = fmaf(w, m[h][2], o2);
            o3 = fmaf(w, m[h][3], o3);
        }
        uint2 u;
        *(__half2*)&u.x = __floats2half2_rn(o0, o1);
        *(__half2*)&u.y = __floats2half2_rn(o2, o3);
        *(uint2*)&S[rowbase + (size_t)g * NTNT + j0] = u;
    }
}

// ============================================================
// av_f16: per (b,h): O(1024x64) = P(1024x1024) @ V(1024x64),
// fp16 MMA, fp32 accum, fp16 O output. 64x64 tile, BK=32,
// 3-stage cp.async, 256 thr.
// ============================================================
__global__ __launch_bounds__(256, 4) void av_f16(
    const __half* __restrict__ P, const __half* __restrict__ Vt,
    __half* __restrict__ O)
{
    extern __shared__ float sm[];
    __half* Ps = (__half*)sm;            // [3][64][40]
    __half* Vs = Ps + 3 * 2560;          // [3][64][40]

    int bh = blockIdx.y;
    int b = bh / NH, h = bh % NH;
    const __half* Pg = P + (size_t)bh * NTNT + (size_t)blockIdx.x * 64 * NT;
    const __half* Vg = Vt + (size_t)bh * HD * NT;   // [d][tok]

    int tid = threadIdx.x, lane = tid & 31, wid = tid >> 5;
    int lr = lane >> 2, lc = lane & 3;
    int m0 = (wid & 3) * 16, n0 = (wid >> 2) * 32;

    int ldr = tid >> 2, ldc = (tid & 3) * 8;

#define AV_LOAD(s, k0) do {                                             \
    __half* Pd = Ps + (s) * 2560;                                       \
    __half* Vd = Vs + (s) * 2560;                                       \
    cp16(&Pd[ldr * 40 + ldc], Pg + (size_t)ldr * NT + (k0) + ldc);      \
    cp16(&Vd[ldr * 40 + ldc], Vg + (size_t)ldr * NT + (k0) + ldc);      \
    CP_COMMIT;                                                          \
} while (0)

    AV_LOAD(0, 0);
    AV_LOAD(1, 32);

    float acc[4][4] = {};
    const int NITER = NT / 32;   // 32
    for (int it = 0; it < NITER; it++) {
        CP_WAIT1;
        __syncthreads();
        int s = it % 3;
        const __half* Pq = Ps + s * 2560;
        const __half* Vq = Vs + s * 2560;
#pragma unroll
        for (int kk = 0; kk < 32; kk += 16) {
            unsigned a0, a1, a2, a3;
            {
                int rb = (m0 + lr) * 40 + kk + 2 * lc;
                a0 = *(const unsigned*)&Pq[rb];
                a1 = *(const unsigned*)&Pq[rb + 8 * 40];
                a2 = *(const unsigned*)&Pq[rb + 8];
                a3 = *(const unsigned*)&Pq[rb + 8 * 40 + 8];
            }
#pragma unroll
            for (int ni = 0; ni < 4; ni++) {
                int nb = (n0 + ni * 8 + lr) * 40 + kk + 2 * lc;
                unsigned b0 = *(const unsigned*)&Vq[nb];
                unsigned b1 = *(const unsigned*)&Vq[nb + 8];
                mma16h(acc[ni], a0, a1, a2, a3, b0, b1);
            }
        }
        __syncthreads();
        if (it + 2 < NITER) AV_LOAD((it + 2) % 3, (it + 2) * 32);
        else CP_COMMIT;
    }
#undef AV_LOAD

#pragma unroll
    for (int ni = 0; ni < 4; ni++) {
        int col = n0 + ni * 8 + 2 * lc;
#pragma unroll
        for (int half_ = 0; half_ < 2; half_++) {
            int row = blockIdx.x * 64 + m0 + lr + half_ * 8;
            *(__half2*)&O[(size_t)(b * NT + row) * DIMC + h * HD + col] =
                __floats2half2_rn(acc[ni][half_*2], acc[ni][half_*2 + 1]);
        }
    }
}

// ============================================================
extern "C" void kernel_launch(void* const* d_in, const int* in_sizes, int n_in,
                              void* d_out, int out_size)
{
    const float* x  = (const float*)d_in[0];
    const float* Wq = (const float*)d_in[1];
    const float* Wk = (const float*)d_in[2];
    const float* Wv = (const float*)d_in[3];
    const float* Wl = (const float*)d_in[4];
    const float* bl = (const float*)d_in[5];
    const float* Ww = (const float*)d_in[6];
    const float* bw = (const float*)d_in[7];
    const float* Wp = (const float*)d_in[8];
    const float* bp = (const float*)d_in[9];
    float* out = (float*)d_out;

    __half *gxh, *gwt, *gq, *gk, *gvt, *gS, *gOh;
    cudaGetSymbolAddress((void**)&gxh, g_xh);
    cudaGetSymbolAddress((void**)&gwt, g_wt);
    cudaGetSymbolAddress((void**)&gq, g_q);
    cudaGetSymbolAddress((void**)&gk, g_k);
    cudaGetSymbolAddress((void**)&gvt, g_vt);
    cudaGetSymbolAddress((void**)&gS, g_S);
    cudaGetSymbolAddress((void**)&gOh, g_Oh);

    int qkv_smem = 3 * 2 * 5120 * (int)sizeof(__half);               // 61440
    cudaFuncSetAttribute(qkv_f16,
                         cudaFuncAttributeMaxDynamicSharedMemorySize, qkv_smem);
    cudaFuncSetAttribute(outproj_f16,
                         cudaFuncAttributeMaxDynamicSharedMemorySize, qkv_smem);
    int score_smem = 2 * 128 * 72 * (int)sizeof(__half);             // 36864
    cudaFuncSetAttribute(score_f16,
                         cudaFuncAttributeMaxDynamicSharedMemorySize, score_smem);
    int av_smem = 3 * 2 * 2560 * (int)sizeof(__half);                // 30720
    cudaFuncSetAttribute(av_f16,
                         cudaFuncAttributeMaxDynamicSharedMemorySize, av_smem);

    // fp16 conversions (x + 4 weight matrices)
    conv_x<<<M_TOK * DIMC / 1024, 256>>>(x, gxh);
    conv_wt<<<dim3(24, 24, 4), 256>>>(Wq, Wk, Wv, Wp, gwt);

    // QKV projections (fp16), one launch; Q pre-scaled; V fp16 transposed
    qkv_f16<<<dim3(6, 64, 3), 256, qkv_smem>>>(gxh, gwt, gq, gk, gvt);

    // raw scores S = Q K^T -> fp16
    score_f16<<<dim3(8, 8, 96), 256, score_smem>>>(gq, gk, gS);

    // register-resident fused pre-mix + softmax + post-mix (in place on gS)
    softmax_mix_reg<<<dim3(1024, 8), 256>>>(gS, Wl, bl, Ww, bw);

    // attn @ V -> [tok, dim] fp16
    av_f16<<<dim3(16, 96), 256, av_smem>>>(gS, gvt, gOh);

    // final projection + bias (fp16 GEMM, fp32 accum/out)
    outproj_f16<<<dim3(6, 64), 256, qkv_smem>>>(gOh, gwt, out, bp);
}

// round 11
// speedup vs baseline: 1.8292x; 1.0531x over previous
#include <cuda_runtime.h>
#include <cuda_fp16.h>
#include <math.h>

#define DIMC 768
#define NH 12
#define HD 64
#define NB 8
#define NT 1024
#define M_TOK (NB*NT)   // 8192
#define NTNT (NT*NT)

// ---- scratch (device globals: no allocations allowed) ----
__device__ __half g_xh[M_TOK*DIMC];            // x in fp16
__device__ __half g_wt[4*DIMC*DIMC];           // Wq,Wk,Wv,Wp fp16 TRANSPOSED [n][k]
__device__ __half g_q[NB*NH*NT*HD];            // [b,h,n,d] fp16, Q pre-scaled
__device__ __half g_k[NB*NH*NT*HD];            // [b,h,n,d] fp16
__device__ __half g_vt[NB*NH*HD*NT];           // [b,h,d,tok] fp16 (transposed V)
__device__ __half g_S[(size_t)NB*NH*NT*NT];    // 201 MB scores / probs fp16 (in place)
__device__ __half g_Oh[(size_t)M_TOK*DIMC];    // [tok, dim] fp16

// ---------- helpers ----------
__device__ __forceinline__ void mma16h(float* d, unsigned a0, unsigned a1,
                                       unsigned a2, unsigned a3,
                                       unsigned b0, unsigned b1) {
    asm volatile(
        "mma.sync.aligned.m16n8k16.row.col.f32.f16.f16.f32 "
        "{%0,%1,%2,%3},{%4,%5,%6,%7},{%8,%9},{%0,%1,%2,%3};"
        : "+f"(d[0]), "+f"(d[1]), "+f"(d[2]), "+f"(d[3])
        : "r"(a0), "r"(a1), "r"(a2), "r"(a3), "r"(b0), "r"(b1));
}
__device__ __forceinline__ void cp16(void* s, const void* g) {
    unsigned sa = (unsigned)__cvta_generic_to_shared(s);
    asm volatile("cp.async.ca.shared.global [%0], [%1], 16;" :: "r"(sa), "l"(g));
}
#define CP_COMMIT asm volatile("cp.async.commit_group;")
#define CP_WAIT1  asm volatile("cp.async.wait_group 1;")
#define CP_WAIT0  asm volatile("cp.async.wait_group 0;")

// packed f32x2 (FFMA2) helpers — bit-identical to two scalar fmaf's
typedef unsigned long long ull;
__device__ __forceinline__ ull pack2(float lo, float hi) {
    ull r; asm("mov.b64 %0, {%1, %2};" : "=l"(r) : "f"(lo), "f"(hi)); return r;
}
__device__ __forceinline__ float2 unpack2(ull v) {
    float2 f; asm("mov.b64 {%0, %1}, %2;" : "=f"(f.x), "=f"(f.y) : "l"(v)); return f;
}
__device__ __forceinline__ void fma2(ull& d, ull a, ull b) {
    asm("fma.rn.f32x2 %0, %1, %2, %0;" : "+l"(d) : "l"(a), "l"(b));
}
__device__ __forceinline__ void mul2(ull& d, ull a, ull b) {
    asm("mul.rn.f32x2 %0, %1, %2;" : "=l"(d) : "l"(a), "l"(b));
}

// ============================================================
// conversion kernels
// ============================================================
__global__ __launch_bounds__(256) void conv_x(
    const float* __restrict__ x, __half* __restrict__ xh)
{
    int i = (blockIdx.x * 256 + threadIdx.x) * 4;
    float4 v = *(const float4*)&x[i];
    *(__half2*)&xh[i]     = __floats2half2_rn(v.x, v.y);
    *(__half2*)&xh[i + 2] = __floats2half2_rn(v.z, v.w);
}

// transpose+convert: out[n][k] = in[k][n], 32x32 tiles, z selects W
__global__ __launch_bounds__(256) void conv_wt(
    const float* __restrict__ Wq, const float* __restrict__ Wk,
    const float* __restrict__ Wv, const float* __restrict__ Wp,
    __half* __restrict__ Wt)
{
    __shared__ float t[32][33];
    int z = blockIdx.z;
    const float* W = (z == 0) ? Wq : (z == 1) ? Wk : (z == 2) ? Wv : Wp;
    __half* out = Wt + (size_t)z * DIMC * DIMC;
    int n0 = blockIdx.x * 32, k0 = blockIdx.y * 32;
    int tx = threadIdx.x & 31, ty = threadIdx.x >> 5;   // 32 x 8
#pragma unroll
    for (int i = ty; i < 32; i += 8)
        t[i][tx] = W[(size_t)(k0 + i) * DIMC + n0 + tx];
    __syncthreads();
#pragma unroll
    for (int i = ty; i < 32; i += 8)
        out[(size_t)(n0 + i) * DIMC + k0 + tx] = __float2half(t[tx][i]);
}

// ============================================================
// fp16 GEMM body: C[8192,768] = A @ Bm^T (Bm is [n][k] fp16).
// 128x128 tile, BK=32, 3-stage cp.async, 256 thr, warp 64x32.
// MODE 1: head-split fp16 [b,h,n,d] (scale).
// MODE 2: transposed fp16 V [b,h,d,tok] via smem staging.
// MODE 3: plain fp32 out + bias.
// ============================================================
template<int MODE>
__device__ __forceinline__ void projh_body(
    const __half* __restrict__ A, const __half* __restrict__ Bm,
    float* __restrict__ Cf, __half* __restrict__ Ch,
    const float* __restrict__ bias, float scale)
{
    extern __shared__ float smf[];
    __half* As = (__half*)smf;        // [3][128][40]
    __half* Bs = As + 3 * 5120;       // [3][128][40]

    int tid = threadIdx.x, lane = tid & 31, wid = tid >> 5;
    int warp_m = wid & 1, warp_n = wid >> 1;
    int rowBase = blockIdx.y * 128, colBase = blockIdx.x * 128;
    int lr = lane >> 2, lc = lane & 3;
    int m0 = warp_m * 64, n0 = warp_n * 32;

    const __half* Ap = A + (size_t)rowBase * DIMC;
    const __half* Bp = Bm + (size_t)colBase * DIMC;

#define QKV_LOAD(s, k0) do {                                            \
    __half* Ad = As + (s) * 5120;                                       \
    __half* Bd = Bs + (s) * 5120;                                       \
    _Pragma("unroll")                                                   \
    for (int i_ = 0; i_ < 2; i_++) {                                    \
        int t_ = tid + i_ * 256;                                        \
        int r_ = t_ >> 2, c_ = (t_ & 3) * 8;                            \
        cp16(&Ad[r_ * 40 + c_], Ap + (size_t)r_ * DIMC + (k0) + c_);    \
        cp16(&Bd[r_ * 40 + c_], Bp + (size_t)r_ * DIMC + (k0) + c_);    \
    }                                                                   \
    CP_COMMIT;                                                          \
} while (0)

    QKV_LOAD(0, 0);
    QKV_LOAD(1, 32);

    float acc[4][4][4] = {};
    const int NITER = DIMC / 32;   // 24
    for (int it = 0; it < NITER; it++) {
        CP_WAIT1;
        __syncthreads();
        int s = it % 3;
        const __half* Aq = As + s * 5120;
        const __half* Bq = Bs + s * 5120;
#pragma unroll
        for (int kk = 0; kk < 32; kk += 16) {
            unsigned a[4][4], b[4][2];
#pragma unroll
            for (int mi = 0; mi < 4; mi++) {
                int rb = (m0 + mi * 16 + lr) * 40 + kk + 2 * lc;
                a[mi][0] = *(const unsigned*)&Aq[rb];
                a[mi][1] = *(const unsigned*)&Aq[rb + 8 * 40];
                a[mi][2] = *(const unsigned*)&Aq[rb + 8];
                a[mi][3] = *(const unsigned*)&Aq[rb + 8 * 40 + 8];
            }
#pragma unroll
            for (int ni = 0; ni < 4; ni++) {
                int nb = (n0 + ni * 8 + lr) * 40 + kk + 2 * lc;
                b[ni][0] = *(const unsigned*)&Bq[nb];
                b[ni][1] = *(const unsigned*)&Bq[nb + 8];
            }
#pragma unroll
            for (int mi = 0; mi < 4; mi++)
#pragma unroll
                for (int ni = 0; ni < 4; ni++)
                    mma16h(acc[mi][ni], a[mi][0], a[mi][1], a[mi][2], a[mi][3],
                           b[ni][0], b[ni][1]);
        }
        __syncthreads();
        if (it + 2 < NITER) QKV_LOAD((it + 2) % 3, (it + 2) * 32);
        else CP_COMMIT;
    }
#undef QKV_LOAD

    if (MODE == 2) {
        // stage transposed fp16 tile: stg[local_col][local_row], stride 136
        __half* stg = (__half*)smf;   // 34816 B <= 61440 B
#pragma unroll
        for (int mi = 0; mi < 4; mi++) {
#pragma unroll
            for (int ni = 0; ni < 4; ni++) {
                int col = n0 + ni * 8 + 2 * lc;
#pragma unroll
                for (int half_ = 0; half_ < 2; half_++) {
                    int row = m0 + mi * 16 + lr + half_ * 8;
                    stg[col * 136 + row]       = __float2half(acc[mi][ni][half_*2 + 0]);
                    stg[(col + 1) * 136 + row] = __float2half(acc[mi][ni][half_*2 + 1]);
                }
            }
        }
        __syncthreads();
        int b_ = rowBase >> 10;
        int rloc = rowBase & 1023;
        for (int t = tid; t < 128 * 16; t += 256) {
            int col = t >> 4;
            int r8 = (t & 15) * 8;
            int gcol = colBase + col;
            int hh = gcol >> 6, d = gcol & 63;
            size_t dst = ((size_t)(b_ * NH + hh) * HD + d) * NT + rloc + r8;
            *(uint4*)&Ch[dst] = *(const uint4*)&stg[col * 136 + r8];
        }
        return;
    }

#pragma unroll
    for (int mi = 0; mi < 4; mi++) {
#pragma unroll
        for (int ni = 0; ni < 4; ni++) {
            int col = colBase + n0 + ni * 8 + 2 * lc;
            float bv0 = 0.f, bv1 = 0.f;
            if (MODE == 3) { bv0 = bias[col]; bv1 = bias[col + 1]; }
#pragma unroll
            for (int half_ = 0; half_ < 2; half_++) {
                int row = rowBase + m0 + mi * 16 + lr + half_ * 8;
                if (MODE == 3) {
                    *(float2*)&Cf[(size_t)row * DIMC + col] =
                        make_float2(acc[mi][ni][half_*2 + 0] + bv0,
                                    acc[mi][ni][half_*2 + 1] + bv1);
                } else {    // MODE 1: fp16 head-split [b,h,n,d]
                    int b_ = row >> 10, rr = row & 1023;
                    int h = col >> 6, d = col & 63;
                    *(__half2*)&Ch[(((size_t)(b_ * NH + h) * NT + rr) * HD + d)] =
                        __floats2half2_rn(acc[mi][ni][half_*2 + 0] * scale,
                                          acc[mi][ni][half_*2 + 1] * scale);
                }
            }
        }
    }
}

__global__ __launch_bounds__(256, 2) void qkv_f16(
    const __half* __restrict__ xh, const __half* __restrict__ Wt,
    __half* __restrict__ q, __half* __restrict__ k, __half* __restrict__ vt)
{
    int z = blockIdx.z;
    const __half* Bm = Wt + (size_t)z * DIMC * DIMC;
    if (z == 0)      projh_body<1>(xh, Bm, nullptr, q, nullptr, 0.125f);
    else if (z == 1) projh_body<1>(xh, Bm, nullptr, k, nullptr, 1.0f);
    else             projh_body<2>(xh, Bm, nullptr, vt, nullptr, 1.0f);
}

__global__ __launch_bounds__(256, 2) void outproj_f16(
    const __half* __restrict__ Oh, const __half* __restrict__ Wt,
    float* __restrict__ C, const float* __restrict__ bias)
{
    projh_body<3>(Oh, Wt + (size_t)3 * DIMC * DIMC, C, nullptr, bias, 1.0f);
}

// ============================================================
// score_f16: per (b,h): S = Q(1024x64) @ K^T, fp16 MMA.
// 128x128 tile, whole K=64 in smem. Smem-staged coalesced
// fp16 store epilogue (uint4 rows).
// ============================================================
__global__ __launch_bounds__(256, 2) void score_f16(
    const __half* __restrict__ Q, const __half* __restrict__ Kp,
    __half* __restrict__ S)
{
    extern __shared__ float smf[];
    __half* Qs = (__half*)smf;        // [128][72]
    __half* Ks = Qs + 128 * 72;       // [128][72]

    int bh = blockIdx.z;
    const __half* Qg = Q + (size_t)bh * NT * HD + (size_t)blockIdx.y * 128 * HD;
    const __half* Kg = Kp + (size_t)bh * NT * HD + (size_t)blockIdx.x * 128 * HD;

    int tid = threadIdx.x, lane = tid & 31, wid = tid >> 5;
    int lr = lane >> 2, lc = lane & 3;
    int warp_m = wid & 1, warp_n = wid >> 1;
    int m0 = warp_m * 64, n0 = warp_n * 32;

#pragma unroll
    for (int i = 0; i < 4; i++) {
        int t = tid + i * 256;
        int r = t >> 3, c = (t & 7) * 8;
        cp16(&Qs[r * 72 + c], Qg + (size_t)r * HD + c);
        cp16(&Ks[r * 72 + c], Kg + (size_t)r * HD + c);
    }
    CP_COMMIT;
    CP_WAIT0;
    __syncthreads();

    float acc[4][4][4] = {};
#pragma unroll
    for (int kk = 0; kk < 64; kk += 16) {
        unsigned a[4][4], b[4][2];
#pragma unroll
        for (int mi = 0; mi < 4; mi++) {
            int rb = (m0 + mi * 16 + lr) * 72 + kk + 2 * lc;
            a[mi][0] = *(const unsigned*)&Qs[rb];
            a[mi][1] = *(const unsigned*)&Qs[rb + 8 * 72];
            a[mi][2] = *(const unsigned*)&Qs[rb + 8];
            a[mi][3] = *(const unsigned*)&Qs[rb + 8 * 72 + 8];
        }
#pragma unroll
        for (int ni = 0; ni < 4; ni++) {
            int nb = (n0 + ni * 8 + lr) * 72 + kk + 2 * lc;
            b[ni][0] = *(const unsigned*)&Ks[nb];
            b[ni][1] = *(const unsigned*)&Ks[nb + 8];
        }
#pragma unroll
        for (int mi = 0; mi < 4; mi++)
#pragma unroll
            for (int ni = 0; ni < 4; ni++)
                mma16h(acc[mi][ni], a[mi][0], a[mi][1], a[mi][2], a[mi][3],
                       b[ni][0], b[ni][1]);
    }

    // stage fp16 tile in smem (reuse Qs/Ks), then coalesced uint4 flush
    __syncthreads();
    __half* stg = (__half*)smf;   // [128][136] halves = 34816 B <= 36864 B
#pragma unroll
    for (int mi = 0; mi < 4; mi++) {
#pragma unroll
        for (int ni = 0; ni < 4; ni++) {
            int c = n0 + ni * 8 + 2 * lc;
#pragma unroll
            for (int half_ = 0; half_ < 2; half_++) {
                int r = m0 + mi * 16 + lr + half_ * 8;
                *(__half2*)&stg[r * 136 + c] =
                    __floats2half2_rn(acc[mi][ni][half_*2], acc[mi][ni][half_*2 + 1]);
            }
        }
    }
    __syncthreads();

    __half* Sg = S + (size_t)bh * NTNT +
                 (size_t)(blockIdx.y * 128) * NT + blockIdx.x * 128;
#pragma unroll
    for (int t = tid; t < 2048; t += 256) {
        int r = t >> 4, c8 = (t & 15) * 8;
        *(uint4*)&Sg[(size_t)r * NT + c8] = *(const uint4*)&stg[r * 136 + c8];
    }
}

// ============================================================
// softmax_mix_reg: register-resident talking-heads softmax with
// packed f32x2 (FFMA2) mixing — bit-identical math, half the
// fp32 FMA issue count. 1 row/CTA, 256 thr, 4 j-cols/thread.
// ============================================================
__global__ __launch_bounds__(256) void softmax_mix_reg(
    __half* __restrict__ S, const float* __restrict__ Wl,
    const float* __restrict__ bl, const float* __restrict__ Ww,
    const float* __restrict__ bw)
{
    __shared__ ull wl2[144], ww2[144];
    __shared__ float blv[12], bwv[12];
    __shared__ float red[8][12];

    int tid = threadIdx.x, lane = tid & 31, wid = tid >> 5;
    int i = blockIdx.x, b = blockIdx.y;
    if (tid < 144) {
        float a = Wl[tid]; wl2[tid] = pack2(a, a);
        float c = Ww[tid]; ww2[tid] = pack2(c, c);
    }
    if (tid < 12)  { blv[tid] = bl[tid]; bwv[tid] = bw[tid]; }
    __syncthreads();

    size_t rowbase = (size_t)b * NH * NTNT + (size_t)i * NT;
    int j0 = tid * 4;

    // load raw scores (12 heads x 4 j) and pack to f32x2 pairs
    ull s2[12][2];
#pragma unroll
    for (int h = 0; h < 12; h++) {
        uint2 u = *(const uint2*)&S[rowbase + (size_t)h * NTNT + j0];
        float2 f0 = __half22float2(*(__half2*)&u.x);
        float2 f1 = __half22float2(*(__half2*)&u.y);
        s2[h][0] = pack2(f0.x, f0.y);
        s2[h][1] = pack2(f1.x, f1.y);
    }

    // pre-softmax mix (packed)
    ull m2[12][2];
#pragma unroll
    for (int g = 0; g < 12; g++) {
        ull b2 = pack2(blv[g], blv[g]);
        m2[g][0] = b2; m2[g][1] = b2;
#pragma unroll
        for (int h = 0; h < 12; h++) {
            ull w = wl2[g * 12 + h];
            fma2(m2[g][0], w, s2[h][0]);
            fma2(m2[g][1], w, s2[h][1]);
        }
    }

    // block max per head
#pragma unroll
    for (int h = 0; h < 12; h++) {
        float2 a0 = unpack2(m2[h][0]), a1 = unpack2(m2[h][1]);
        float a = fmaxf(fmaxf(a0.x, a0.y), fmaxf(a1.x, a1.y));
#pragma unroll
        for (int o = 16; o; o >>= 1) a = fmaxf(a, __shfl_xor_sync(0xffffffffu, a, o));
        if (lane == 0) red[wid][h] = a;
    }
    __syncthreads();
    float mxv[12];
#pragma unroll
    for (int h = 0; h < 12; h++) {
        float a = red[0][h];
#pragma unroll
        for (int w = 1; w < 8; w++) a = fmaxf(a, red[w][h]);
        mxv[h] = a;
    }
    __syncthreads();

    // exp + block sum per head; repack exp values into m2
#pragma unroll
    for (int h = 0; h < 12; h++) {
        float2 a0 = unpack2(m2[h][0]), a1 = unpack2(m2[h][1]);
        float e0 = __expf(a0.x - mxv[h]);
        float e1 = __expf(a0.y - mxv[h]);
        float e2 = __expf(a1.x - mxv[h]);
        float e3 = __expf(a1.y - mxv[h]);
        m2[h][0] = pack2(e0, e1);
        m2[h][1] = pack2(e2, e3);
        float s0 = (e0 + e1) + (e2 + e3);
#pragma unroll
        for (int o = 16; o; o >>= 1) s0 += __shfl_xor_sync(0xffffffffu, s0, o);
        if (lane == 0) red[wid][h] = s0;
    }
    __syncthreads();
#pragma unroll
    for (int h = 0; h < 12; h++) {
        float s0 = red[0][h];
#pragma unroll
        for (int w = 1; w < 8; w++) s0 += red[w][h];
        float rinv = 1.f / s0;
        ull r2 = pack2(rinv, rinv);
        mul2(m2[h][0], m2[h][0], r2);
        mul2(m2[h][1], m2[h][1], r2);
    }

    // post-softmax mix (packed) + fp16 store
#pragma unroll
    for (int g = 0; g < 12; g++) {
        ull o0 = pack2(bwv[g], bwv[g]);
        ull o1 = o0;
#pragma unroll
        for (int h = 0; h < 12; h++) {
            ull w = ww2[g * 12 + h];
            fma2(o0, w, m2[h][0]);
            fma2(o1, w, m2[h][1]);
        }
        float2 f0 = unpack2(o0), f1 = unpack2(o1);
        uint2 u;
        *(__half2*)&u.x = __floats2half2_rn(f0.x, f0.y);
        *(__half2*)&u.y = __floats2half2_rn(f1.x, f1.y);
        *(uint2*)&S[rowbase + (size_t)g * NTNT + j0] = u;
    }
}

// ============================================================
// av_f16: per (b,h): O(1024x64) = P(1024x1024) @ V(1024x64),
// fp16 MMA, fp32 accum, fp16 O output. 64x64 tile, BK=32,
// 3-stage cp.async, 256 thr.
// ============================================================
__global__ __launch_bounds__(256, 4) void av_f16(
    const __half* __restrict__ P, const __half* __restrict__ Vt,
    __half* __restrict__ O)
{
    extern __shared__ float sm[];
    __half* Ps = (__half*)sm;            // [3][64][40]
    __half* Vs = Ps + 3 * 2560;          // [3][64][40]

    int bh = blockIdx.y;
    int b = bh / NH, h = bh % NH;
    const __half* Pg = P + (size_t)bh * NTNT + (size_t)blockIdx.x * 64 * NT;
    const __half* Vg = Vt + (size_t)bh * HD * NT;   // [d][tok]

    int tid = threadIdx.x, lane = tid & 31, wid = tid >> 5;
    int lr = lane >> 2, lc = lane & 3;
    int m0 = (wid & 3) * 16, n0 = (wid >> 2) * 32;

    int ldr = tid >> 2, ldc = (tid & 3) * 8;

#define AV_LOAD(s, k0) do {                                             \
    __half* Pd = Ps + (s) * 2560;                                       \
    __half* Vd = Vs + (s) * 2560;                                       \
    cp16(&Pd[ldr * 40 + ldc], Pg + (size_t)ldr * NT + (k0) + ldc);      \
    cp16(&Vd[ldr * 40 + ldc], Vg + (size_t)ldr * NT + (k0) + ldc);      \
    CP_COMMIT;                                                          \
} while (0)

    AV_LOAD(0, 0);
    AV_LOAD(1, 32);

    float acc[4][4] = {};
    const int NITER = NT / 32;   // 32
    for (int it = 0; it < NITER; it++) {
        CP_WAIT1;
        __syncthreads();
        int s = it % 3;
        const __half* Pq = Ps + s * 2560;
        const __half* Vq = Vs + s * 2560;
#pragma unroll
        for (int kk = 0; kk < 32; kk += 16) {
            unsigned a0, a1, a2, a3;
            {
                int rb = (m0 + lr) * 40 + kk + 2 * lc;
                a0 = *(const unsigned*)&Pq[rb];
                a1 = *(const unsigned*)&Pq[rb + 8 * 40];
                a2 = *(const unsigned*)&Pq[rb + 8];
                a3 = *(const unsigned*)&Pq[rb + 8 * 40 + 8];
            }
#pragma unroll
            for (int ni = 0; ni < 4; ni++) {
                int nb = (n0 + ni * 8 + lr) * 40 + kk + 2 * lc;
                unsigned b0 = *(const unsigned*)&Vq[nb];
                unsigned b1 = *(const unsigned*)&Vq[nb + 8];
                mma16h(acc[ni], a0, a1, a2, a3, b0, b1);
            }
        }
        __syncthreads();
        if (it + 2 < NITER) AV_LOAD((it + 2) % 3, (it + 2) * 32);
        else CP_COMMIT;
    }
#undef AV_LOAD

#pragma unroll
    for (int ni = 0; ni < 4; ni++) {
        int col = n0 + ni * 8 + 2 * lc;
#pragma unroll
        for (int half_ = 0; half_ < 2; half_++) {
            int row = blockIdx.x * 64 + m0 + lr + half_ * 8;
            *(__half2*)&O[(size_t)(b * NT + row) * DIMC + h * HD + col] =
                __floats2half2_rn(acc[ni][half_*2], acc[ni][half_*2 + 1]);
        }
    }
}

// ============================================================
extern "C" void kernel_launch(void* const* d_in, const int* in_sizes, int n_in,
                              void* d_out, int out_size)
{
    const float* x  = (const float*)d_in[0];
    const float* Wq = (const float*)d_in[1];
    const float* Wk = (const float*)d_in[2];
    const float* Wv = (const float*)d_in[3];
    const float* Wl = (const float*)d_in[4];
    const float* bl = (const float*)d_in[5];
    const float* Ww = (const float*)d_in[6];
    const float* bw = (const float*)d_in[7];
    const float* Wp = (const float*)d_in[8];
    const float* bp = (const float*)d_in[9];
    float* out = (float*)d_out;

    __half *gxh, *gwt, *gq, *gk, *gvt, *gS, *gOh;
    cudaGetSymbolAddress((void**)&gxh, g_xh);
    cudaGetSymbolAddress((void**)&gwt, g_wt);
    cudaGetSymbolAddress((void**)&gq, g_q);
    cudaGetSymbolAddress((void**)&gk, g_k);
    cudaGetSymbolAddress((void**)&gvt, g_vt);
    cudaGetSymbolAddress((void**)&gS, g_S);
    cudaGetSymbolAddress((void**)&gOh, g_Oh);

    int qkv_smem = 3 * 2 * 5120 * (int)sizeof(__half);               // 61440
    cudaFuncSetAttribute(qkv_f16,
                         cudaFuncAttributeMaxDynamicSharedMemorySize, qkv_smem);
    cudaFuncSetAttribute(outproj_f16,
                         cudaFuncAttributeMaxDynamicSharedMemorySize, qkv_smem);
    int score_smem = 2 * 128 * 72 * (int)sizeof(__half);             // 36864
    cudaFuncSetAttribute(score_f16,
                         cudaFuncAttributeMaxDynamicSharedMemorySize, score_smem);
    int av_smem = 3 * 2 * 2560 * (int)sizeof(__half);                // 30720
    cudaFuncSetAttribute(av_f16,
                         cudaFuncAttributeMaxDynamicSharedMemorySize, av_smem);

    // fp16 conversions (x + 4 weight matrices)
    conv_x<<<M_TOK * DIMC / 1024, 256>>>(x, gxh);
    conv_wt<<<dim3(24, 24, 4), 256>>>(Wq, Wk, Wv, Wp, gwt);

    // QKV projections (fp16), one launch; Q pre-scaled; V fp16 transposed
    qkv_f16<<<dim3(6, 64, 3), 256, qkv_smem>>>(gxh, gwt, gq, gk, gvt);

    // raw scores S = Q K^T -> fp16, coalesced staged stores
    score_f16<<<dim3(8, 8, 96), 256, score_smem>>>(gq, gk, gS);

    // register-resident fused pre-mix + softmax + post-mix (FFMA2)
    softmax_mix_reg<<<dim3(1024, 8), 256>>>(gS, Wl, bl, Ww, bw);

    // attn @ V -> [tok, dim] fp16
    av_f16<<<dim3(16, 96), 256, av_smem>>>(gS, gvt, gOh);

    // final projection + bias (fp16 GEMM, fp32 accum/out)
    outproj_f16<<<dim3(6, 64), 256, qkv_smem>>>(gOh, gwt, out, bp);
}

// round 12
// speedup vs baseline: 1.8975x; 1.0374x over previous
#include <cuda_runtime.h>
#include <cuda_fp16.h>
#include <math.h>

#define DIMC 768
#define NH 12
#define HD 64
#define NB 8
#define NT 1024
#define M_TOK (NB*NT)   // 8192
#define NTNT (NT*NT)

// ---- scratch (device globals: no allocations allowed) ----
__device__ __half g_xh[M_TOK*DIMC];            // x in fp16
__device__ __half g_wt[4*DIMC*DIMC];           // Wq,Wk,Wv,Wp fp16 TRANSPOSED [n][k]
__device__ __half g_q[NB*NH*NT*HD];            // [b,h,n,d] fp16, Q pre-scaled
__device__ __half g_k[NB*NH*NT*HD];            // [b,h,n,d] fp16
__device__ __half g_vt[NB*NH*HD*NT];           // [b,h,d,tok] fp16 (transposed V)
__device__ __half g_S[(size_t)NB*NH*NT*NT];    // 201 MB scores / probs fp16 (in place)
__device__ __half g_Oh[(size_t)M_TOK*DIMC];    // [tok, dim] fp16

// ---------- helpers ----------
__device__ __forceinline__ void mma16h(float* d, unsigned a0, unsigned a1,
                                       unsigned a2, unsigned a3,
                                       unsigned b0, unsigned b1) {
    asm volatile(
        "mma.sync.aligned.m16n8k16.row.col.f32.f16.f16.f32 "
        "{%0,%1,%2,%3},{%4,%5,%6,%7},{%8,%9},{%0,%1,%2,%3};"
        : "+f"(d[0]), "+f"(d[1]), "+f"(d[2]), "+f"(d[3])
        : "r"(a0), "r"(a1), "r"(a2), "r"(a3), "r"(b0), "r"(b1));
}
__device__ __forceinline__ void cp16(void* s, const void* g) {
    unsigned sa = (unsigned)__cvta_generic_to_shared(s);
    asm volatile("cp.async.ca.shared.global [%0], [%1], 16;" :: "r"(sa), "l"(g));
}
#define CP_COMMIT asm volatile("cp.async.commit_group;")
#define CP_WAIT1  asm volatile("cp.async.wait_group 1;")
#define CP_WAIT0  asm volatile("cp.async.wait_group 0;")

// packed f32x2 (FFMA2) helpers — bit-identical to two scalar fmaf's
typedef unsigned long long ull;
__device__ __forceinline__ ull pack2(float lo, float hi) {
    ull r; asm("mov.b64 %0, {%1, %2};" : "=l"(r) : "f"(lo), "f"(hi)); return r;
}
__device__ __forceinline__ float2 unpack2(ull v) {
    float2 f; asm("mov.b64 {%0, %1}, %2;" : "=f"(f.x), "=f"(f.y) : "l"(v)); return f;
}
__device__ __forceinline__ void fma2(ull& d, ull a, ull b) {
    asm("fma.rn.f32x2 %0, %1, %2, %0;" : "+l"(d) : "l"(a), "l"(b));
}
__device__ __forceinline__ void mul2(ull& d, ull a, ull b) {
    asm("mul.rn.f32x2 %0, %1, %2;" : "=l"(d) : "l"(a), "l"(b));
}

// ============================================================
// conversion kernels
// ============================================================
__global__ __launch_bounds__(256) void conv_x(
    const float* __restrict__ x, __half* __restrict__ xh)
{
    int i = (blockIdx.x * 256 + threadIdx.x) * 4;
    float4 v = *(const float4*)&x[i];
    *(__half2*)&xh[i]     = __floats2half2_rn(v.x, v.y);
    *(__half2*)&xh[i + 2] = __floats2half2_rn(v.z, v.w);
}

// transpose+convert: out[n][k] = in[k][n], 32x32 tiles, z selects W
__global__ __launch_bounds__(256) void conv_wt(
    const float* __restrict__ Wq, const float* __restrict__ Wk,
    const float* __restrict__ Wv, const float* __restrict__ Wp,
    __half* __restrict__ Wt)
{
    __shared__ float t[32][33];
    int z = blockIdx.z;
    const float* W = (z == 0) ? Wq : (z == 1) ? Wk : (z == 2) ? Wv : Wp;
    __half* out = Wt + (size_t)z * DIMC * DIMC;
    int n0 = blockIdx.x * 32, k0 = blockIdx.y * 32;
    int tx = threadIdx.x & 31, ty = threadIdx.x >> 5;   // 32 x 8
#pragma unroll
    for (int i = ty; i < 32; i += 8)
        t[i][tx] = W[(size_t)(k0 + i) * DIMC + n0 + tx];
    __syncthreads();
#pragma unroll
    for (int i = ty; i < 32; i += 8)
        out[(size_t)(n0 + i) * DIMC + k0 + tx] = __float2half(t[tx][i]);
}

// ============================================================
// fp16 GEMM body: C[8192,768] = A @ Bm^T (Bm is [n][k] fp16).
// 128x128 tile, BK=32, 3-stage cp.async, 256 thr, warp 64x32.
// MODE 1: head-split fp16 [b,h,n,d] (scale).
// MODE 2: transposed fp16 V [b,h,d,tok] via smem staging.
// MODE 3: plain fp32 out + bias.
// ============================================================
template<int MODE>
__device__ __forceinline__ void projh_body(
    const __half* __restrict__ A, const __half* __restrict__ Bm,
    float* __restrict__ Cf, __half* __restrict__ Ch,
    const float* __restrict__ bias, float scale)
{
    extern __shared__ float smf[];
    __half* As = (__half*)smf;        // [3][128][40]
    __half* Bs = As + 3 * 5120;       // [3][128][40]

    int tid = threadIdx.x, lane = tid & 31, wid = tid >> 5;
    int warp_m = wid & 1, warp_n = wid >> 1;
    int rowBase = blockIdx.y * 128, colBase = blockIdx.x * 128;
    int lr = lane >> 2, lc = lane & 3;
    int m0 = warp_m * 64, n0 = warp_n * 32;

    const __half* Ap = A + (size_t)rowBase * DIMC;
    const __half* Bp = Bm + (size_t)colBase * DIMC;

#define QKV_LOAD(s, k0) do {                                            \
    __half* Ad = As + (s) * 5120;                                       \
    __half* Bd = Bs + (s) * 5120;                                       \
    _Pragma("unroll")                                                   \
    for (int i_ = 0; i_ < 2; i_++) {                                    \
        int t_ = tid + i_ * 256;                                        \
        int r_ = t_ >> 2, c_ = (t_ & 3) * 8;                            \
        cp16(&Ad[r_ * 40 + c_], Ap + (size_t)r_ * DIMC + (k0) + c_);    \
        cp16(&Bd[r_ * 40 + c_], Bp + (size_t)r_ * DIMC + (k0) + c_);    \
    }                                                                   \
    CP_COMMIT;                                                          \
} while (0)

    QKV_LOAD(0, 0);
    QKV_LOAD(1, 32);

    float acc[4][4][4] = {};
    const int NITER = DIMC / 32;   // 24
    for (int it = 0; it < NITER; it++) {
        CP_WAIT1;
        __syncthreads();
        int s = it % 3;
        const __half* Aq = As + s * 5120;
        const __half* Bq = Bs + s * 5120;
#pragma unroll
        for (int kk = 0; kk < 32; kk += 16) {
            unsigned a[4][4], b[4][2];
#pragma unroll
            for (int mi = 0; mi < 4; mi++) {
                int rb = (m0 + mi * 16 + lr) * 40 + kk + 2 * lc;
                a[mi][0] = *(const unsigned*)&Aq[rb];
                a[mi][1] = *(const unsigned*)&Aq[rb + 8 * 40];
                a[mi][2] = *(const unsigned*)&Aq[rb + 8];
                a[mi][3] = *(const unsigned*)&Aq[rb + 8 * 40 + 8];
            }
#pragma unroll
            for (int ni = 0; ni < 4; ni++) {
                int nb = (n0 + ni * 8 + lr) * 40 + kk + 2 * lc;
                b[ni][0] = *(const unsigned*)&Bq[nb];
                b[ni][1] = *(const unsigned*)&Bq[nb + 8];
            }
#pragma unroll
            for (int mi = 0; mi < 4; mi++)
#pragma unroll
                for (int ni = 0; ni < 4; ni++)
                    mma16h(acc[mi][ni], a[mi][0], a[mi][1], a[mi][2], a[mi][3],
                           b[ni][0], b[ni][1]);
        }
        __syncthreads();
        if (it + 2 < NITER) QKV_LOAD((it + 2) % 3, (it + 2) * 32);
        else CP_COMMIT;
    }
#undef QKV_LOAD

    if (MODE == 2) {
        // stage transposed fp16 tile: stg[local_col][local_row], stride 136
        __half* stg = (__half*)smf;   // 34816 B <= 61440 B
#pragma unroll
        for (int mi = 0; mi < 4; mi++) {
#pragma unroll
            for (int ni = 0; ni < 4; ni++) {
                int col = n0 + ni * 8 + 2 * lc;
#pragma unroll
                for (int half_ = 0; half_ < 2; half_++) {
                    int row = m0 + mi * 16 + lr + half_ * 8;
                    stg[col * 136 + row]       = __float2half(acc[mi][ni][half_*2 + 0]);
                    stg[(col + 1) * 136 + row] = __float2half(acc[mi][ni][half_*2 + 1]);
                }
            }
        }
        __syncthreads();
        int b_ = rowBase >> 10;
        int rloc = rowBase & 1023;
        for (int t = tid; t < 128 * 16; t += 256) {
            int col = t >> 4;
            int r8 = (t & 15) * 8;
            int gcol = colBase + col;
            int hh = gcol >> 6, d = gcol & 63;
            size_t dst = ((size_t)(b_ * NH + hh) * HD + d) * NT + rloc + r8;
            *(uint4*)&Ch[dst] = *(const uint4*)&stg[col * 136 + r8];
        }
        return;
    }

#pragma unroll
    for (int mi = 0; mi < 4; mi++) {
#pragma unroll
        for (int ni = 0; ni < 4; ni++) {
            int col = colBase + n0 + ni * 8 + 2 * lc;
            float bv0 = 0.f, bv1 = 0.f;
            if (MODE == 3) { bv0 = bias[col]; bv1 = bias[col + 1]; }
#pragma unroll
            for (int half_ = 0; half_ < 2; half_++) {
                int row = rowBase + m0 + mi * 16 + lr + half_ * 8;
                if (MODE == 3) {
                    *(float2*)&Cf[(size_t)row * DIMC + col] =
                        make_float2(acc[mi][ni][half_*2 + 0] + bv0,
                                    acc[mi][ni][half_*2 + 1] + bv1);
                } else {    // MODE 1: fp16 head-split [b,h,n,d]
                    int b_ = row >> 10, rr = row & 1023;
                    int h = col >> 6, d = col & 63;
                    *(__half2*)&Ch[(((size_t)(b_ * NH + h) * NT + rr) * HD + d)] =
                        __floats2half2_rn(acc[mi][ni][half_*2 + 0] * scale,
                                          acc[mi][ni][half_*2 + 1] * scale);
                }
            }
        }
    }
}

__global__ __launch_bounds__(256, 2) void qkv_f16(
    const __half* __restrict__ xh, const __half* __restrict__ Wt,
    __half* __restrict__ q, __half* __restrict__ k, __half* __restrict__ vt)
{
    int z = blockIdx.z;
    const __half* Bm = Wt + (size_t)z * DIMC * DIMC;
    if (z == 0)      projh_body<1>(xh, Bm, nullptr, q, nullptr, 0.125f);
    else if (z == 1) projh_body<1>(xh, Bm, nullptr, k, nullptr, 1.0f);
    else             projh_body<2>(xh, Bm, nullptr, vt, nullptr, 1.0f);
}

__global__ __launch_bounds__(256, 2) void outproj_f16(
    const __half* __restrict__ Oh, const __half* __restrict__ Wt,
    float* __restrict__ C, const float* __restrict__ bias)
{
    projh_body<3>(Oh, Wt + (size_t)3 * DIMC * DIMC, C, nullptr, bias, 1.0f);
}

// ============================================================
// score_f16: per (b,h): S = Q(1024x64) @ K^T, fp16 MMA.
// 128x128 tile, whole K=64 in smem. Smem-staged coalesced
// fp16 store epilogue (uint4 rows).
// ============================================================
__global__ __launch_bounds__(256, 2) void score_f16(
    const __half* __restrict__ Q, const __half* __restrict__ Kp,
    __half* __restrict__ S)
{
    extern __shared__ float smf[];
    __half* Qs = (__half*)smf;        // [128][72]
    __half* Ks = Qs + 128 * 72;       // [128][72]

    int bh = blockIdx.z;
    const __half* Qg = Q + (size_t)bh * NT * HD + (size_t)blockIdx.y * 128 * HD;
    const __half* Kg = Kp + (size_t)bh * NT * HD + (size_t)blockIdx.x * 128 * HD;

    int tid = threadIdx.x, lane = tid & 31, wid = tid >> 5;
    int lr = lane >> 2, lc = lane & 3;
    int warp_m = wid & 1, warp_n = wid >> 1;
    int m0 = warp_m * 64, n0 = warp_n * 32;

#pragma unroll
    for (int i = 0; i < 4; i++) {
        int t = tid + i * 256;
        int r = t >> 3, c = (t & 7) * 8;
        cp16(&Qs[r * 72 + c], Qg + (size_t)r * HD + c);
        cp16(&Ks[r * 72 + c], Kg + (size_t)r * HD + c);
    }
    CP_COMMIT;
    CP_WAIT0;
    __syncthreads();

    float acc[4][4][4] = {};
#pragma unroll
    for (int kk = 0; kk < 64; kk += 16) {
        unsigned a[4][4], b[4][2];
#pragma unroll
        for (int mi = 0; mi < 4; mi++) {
            int rb = (m0 + mi * 16 + lr) * 72 + kk + 2 * lc;
            a[mi][0] = *(const unsigned*)&Qs[rb];
            a[mi][1] = *(const unsigned*)&Qs[rb + 8 * 72];
            a[mi][2] = *(const unsigned*)&Qs[rb + 8];
            a[mi][3] = *(const unsigned*)&Qs[rb + 8 * 72 + 8];
        }
#pragma unroll
        for (int ni = 0; ni < 4; ni++) {
            int nb = (n0 + ni * 8 + lr) * 72 + kk + 2 * lc;
            b[ni][0] = *(const unsigned*)&Ks[nb];
            b[ni][1] = *(const unsigned*)&Ks[nb + 8];
        }
#pragma unroll
        for (int mi = 0; mi < 4; mi++)
#pragma unroll
            for (int ni = 0; ni < 4; ni++)
                mma16h(acc[mi][ni], a[mi][0], a[mi][1], a[mi][2], a[mi][3],
                       b[ni][0], b[ni][1]);
    }

    // stage fp16 tile in smem (reuse Qs/Ks), then coalesced uint4 flush
    __syncthreads();
    __half* stg = (__half*)smf;   // [128][136] halves = 34816 B <= 36864 B
#pragma unroll
    for (int mi = 0; mi < 4; mi++) {
#pragma unroll
        for (int ni = 0; ni < 4; ni++) {
            int c = n0 + ni * 8 + 2 * lc;
#pragma unroll
            for (int half_ = 0; half_ < 2; half_++) {
                int r = m0 + mi * 16 + lr + half_ * 8;
                *(__half2*)&stg[r * 136 + c] =
                    __floats2half2_rn(acc[mi][ni][half_*2], acc[mi][ni][half_*2 + 1]);
            }
        }
    }
    __syncthreads();

    __half* Sg = S + (size_t)bh * NTNT +
                 (size_t)(blockIdx.y * 128) * NT + blockIdx.x * 128;
#pragma unroll
    for (int t = tid; t < 2048; t += 256) {
        int r = t >> 4, c8 = (t & 15) * 8;
        *(uint4*)&Sg[(size_t)r * NT + c8] = *(const uint4*)&stg[r * 136 + c8];
    }
}

// ============================================================
// softmax_mix_reg: register-resident talking-heads softmax with
// packed f32x2 (FFMA2) mixing, h-outer accumulation to keep the
// live register set small (raw[12] + m2[12][2] only).
// 1 row/CTA, 256 thr, 4 j-cols/thread. Bit-identical math to the
// scalar version (same h-accumulation order).
// ============================================================
__global__ __launch_bounds__(256, 2) void softmax_mix_reg(
    __half* __restrict__ S, const float* __restrict__ Wl,
    const float* __restrict__ bl, const float* __restrict__ Ww,
    const float* __restrict__ bw)
{
    __shared__ ull wl2[144], ww2[144];
    __shared__ float blv[12], bwv[12];
    __shared__ float red[8][12];

    int tid = threadIdx.x, lane = tid & 31, wid = tid >> 5;
    int i = blockIdx.x, b = blockIdx.y;
    if (tid < 144) {
        float a = Wl[tid]; wl2[tid] = pack2(a, a);
        float c = Ww[tid]; ww2[tid] = pack2(c, c);
    }
    if (tid < 12)  { blv[tid] = bl[tid]; bwv[tid] = bw[tid]; }
    __syncthreads();

    size_t rowbase = (size_t)b * NH * NTNT + (size_t)i * NT;
    int j0 = tid * 4;

    // front-batched loads: 12 heads x 4 j (uint2 each)
    uint2 raw[12];
#pragma unroll
    for (int h = 0; h < 12; h++)
        raw[h] = *(const uint2*)&S[rowbase + (size_t)h * NTNT + j0];

    // pre-softmax mix, h-outer: m2[g] += wl[g][h] * s[h]
    ull m2[12][2];
#pragma unroll
    for (int g = 0; g < 12; g++) {
        ull b2 = pack2(blv[g], blv[g]);
        m2[g][0] = b2; m2[g][1] = b2;
    }
#pragma unroll
    for (int h = 0; h < 12; h++) {
        float2 f0 = __half22float2(*(__half2*)&raw[h].x);
        float2 f1 = __half22float2(*(__half2*)&raw[h].y);
        ull s0 = pack2(f0.x, f0.y);
        ull s1 = pack2(f1.x, f1.y);
#pragma unroll
        for (int g = 0; g < 12; g++) {
            ull w = wl2[g * 12 + h];
            fma2(m2[g][0], w, s0);
            fma2(m2[g][1], w, s1);
        }
    }

    // block max per head
#pragma unroll
    for (int h = 0; h < 12; h++) {
        float2 a0 = unpack2(m2[h][0]), a1 = unpack2(m2[h][1]);
        float a = fmaxf(fmaxf(a0.x, a0.y), fmaxf(a1.x, a1.y));
#pragma unroll
        for (int o = 16; o; o >>= 1) a = fmaxf(a, __shfl_xor_sync(0xffffffffu, a, o));
        if (lane == 0) red[wid][h] = a;
    }
    __syncthreads();
    float mxv[12];
#pragma unroll
    for (int h = 0; h < 12; h++) {
        float a = red[0][h];
#pragma unroll
        for (int w = 1; w < 8; w++) a = fmaxf(a, red[w][h]);
        mxv[h] = a;
    }
    __syncthreads();

    // exp + block sum per head; repack exp values into m2
#pragma unroll
    for (int h = 0; h < 12; h++) {
        float2 a0 = unpack2(m2[h][0]), a1 = unpack2(m2[h][1]);
        float e0 = __expf(a0.x - mxv[h]);
        float e1 = __expf(a0.y - mxv[h]);
        float e2 = __expf(a1.x - mxv[h]);
        float e3 = __expf(a1.y - mxv[h]);
        m2[h][0] = pack2(e0, e1);
        m2[h][1] = pack2(e2, e3);
        float s0 = (e0 + e1) + (e2 + e3);
#pragma unroll
        for (int o = 16; o; o >>= 1) s0 += __shfl_xor_sync(0xffffffffu, s0, o);
        if (lane == 0) red[wid][h] = s0;
    }
    __syncthreads();
#pragma unroll
    for (int h = 0; h < 12; h++) {
        float s0 = red[0][h];
#pragma unroll
        for (int w = 1; w < 8; w++) s0 += red[w][h];
        float rinv = 1.f / s0;
        ull r2 = pack2(rinv, rinv);
        mul2(m2[h][0], m2[h][0], r2);
        mul2(m2[h][1], m2[h][1], r2);
    }

    // post-softmax mix (g-outer, writes out immediately per g)
#pragma unroll
    for (int g = 0; g < 12; g++) {
        ull o0 = pack2(bwv[g], bwv[g]);
        ull o1 = o0;
#pragma unroll
        for (int h = 0; h < 12; h++) {
            ull w = ww2[g * 12 + h];
            fma2(o0, w, m2[h][0]);
            fma2(o1, w, m2[h][1]);
        }
        float2 f0 = unpack2(o0), f1 = unpack2(o1);
        uint2 u;
        *(__half2*)&u.x = __floats2half2_rn(f0.x, f0.y);
        *(__half2*)&u.y = __floats2half2_rn(f1.x, f1.y);
        *(uint2*)&S[rowbase + (size_t)g * NTNT + j0] = u;
    }
}

// ============================================================
// av_f16: per (b,h): O(1024x64) = P(1024x1024) @ V(1024x64),
// fp16 MMA, fp32 accum, fp16 O output. 64x64 tile, BK=32,
// 3-stage cp.async, 256 thr.
// ============================================================
__global__ __launch_bounds__(256, 4) void av_f16(
    const __half* __restrict__ P, const __half* __restrict__ Vt,
    __half* __restrict__ O)
{
    extern __shared__ float sm[];
    __half* Ps = (__half*)sm;            // [3][64][40]
    __half* Vs = Ps + 3 * 2560;          // [3][64][40]

    int bh = blockIdx.y;
    int b = bh / NH, h = bh % NH;
    const __half* Pg = P + (size_t)bh * NTNT + (size_t)blockIdx.x * 64 * NT;
    const __half* Vg = Vt + (size_t)bh * HD * NT;   // [d][tok]

    int tid = threadIdx.x, lane = tid & 31, wid = tid >> 5;
    int lr = lane >> 2, lc = lane & 3;
    int m0 = (wid & 3) * 16, n0 = (wid >> 2) * 32;

    int ldr = tid >> 2, ldc = (tid & 3) * 8;

#define AV_LOAD(s, k0) do {                                             \
    __half* Pd = Ps + (s) * 2560;                                       \
    __half* Vd = Vs + (s) * 2560;                                       \
    cp16(&Pd[ldr * 40 + ldc], Pg + (size_t)ldr * NT + (k0) + ldc);      \
    cp16(&Vd[ldr * 40 + ldc], Vg + (size_t)ldr * NT + (k0) + ldc);      \
    CP_COMMIT;                                                          \
} while (0)

    AV_LOAD(0, 0);
    AV_LOAD(1, 32);

    float acc[4][4] = {};
    const int NITER = NT / 32;   // 32
    for (int it = 0; it < NITER; it++) {
        CP_WAIT1;
        __syncthreads();
        int s = it % 3;
        const __half* Pq = Ps + s * 2560;
        const __half* Vq = Vs + s * 2560;
#pragma unroll
        for (int kk = 0; kk < 32; kk += 16) {
            unsigned a0, a1, a2, a3;
            {
                int rb = (m0 + lr) * 40 + kk + 2 * lc;
                a0 = *(const unsigned*)&Pq[rb];
                a1 = *(const unsigned*)&Pq[rb + 8 * 40];
                a2 = *(const unsigned*)&Pq[rb + 8];
                a3 = *(const unsigned*)&Pq[rb + 8 * 40 + 8];
            }
#pragma unroll
            for (int ni = 0; ni < 4; ni++) {
                int nb = (n0 + ni * 8 + lr) * 40 + kk + 2 * lc;
                unsigned b0 = *(const unsigned*)&Vq[nb];
                unsigned b1 = *(const unsigned*)&Vq[nb + 8];
                mma16h(acc[ni], a0, a1, a2, a3, b0, b1);
            }
        }
        __syncthreads();
        if (it + 2 < NITER) AV_LOAD((it + 2) % 3, (it + 2) * 32);
        else CP_COMMIT;
    }
#undef AV_LOAD

#pragma unroll
    for (int ni = 0; ni < 4; ni++) {
        int col = n0 + ni * 8 + 2 * lc;
#pragma unroll
        for (int half_ = 0; half_ < 2; half_++) {
            int row = blockIdx.x * 64 + m0 + lr + half_ * 8;
            *(__half2*)&O[(size_t)(b * NT + row) * DIMC + h * HD + col] =
                __floats2half2_rn(acc[ni][half_*2], acc[ni][half_*2 + 1]);
        }
    }
}

// ============================================================
extern "C" void kernel_launch(void* const* d_in, const int* in_sizes, int n_in,
                              void* d_out, int out_size)
{
    const float* x  = (const float*)d_in[0];
    const float* Wq = (const float*)d_in[1];
    const float* Wk = (const float*)d_in[2];
    const float* Wv = (const float*)d_in[3];
    const float* Wl = (const float*)d_in[4];
    const float* bl = (const float*)d_in[5];
    const float* Ww = (const float*)d_in[6];
    const float* bw = (const float*)d_in[7];
    const float* Wp = (const float*)d_in[8];
    const float* bp = (const float*)d_in[9];
    float* out = (float*)d_out;

    __half *gxh, *gwt, *gq, *gk, *gvt, *gS, *gOh;
    cudaGetSymbolAddress((void**)&gxh, g_xh);
    cudaGetSymbolAddress((void**)&gwt, g_wt);
    cudaGetSymbolAddress((void**)&gq, g_q);
    cudaGetSymbolAddress((void**)&gk, g_k);
    cudaGetSymbolAddress((void**)&gvt, g_vt);
    cudaGetSymbolAddress((void**)&gS, g_S);
    cudaGetSymbolAddress((void**)&gOh, g_Oh);

    int qkv_smem = 3 * 2 * 5120 * (int)sizeof(__half);               // 61440
    cudaFuncSetAttribute(qkv_f16,
                         cudaFuncAttributeMaxDynamicSharedMemorySize, qkv_smem);
    cudaFuncSetAttribute(outproj_f16,
                         cudaFuncAttributeMaxDynamicSharedMemorySize, qkv_smem);
    int score_smem = 2 * 128 * 72 * (int)sizeof(__half);             // 36864
    cudaFuncSetAttribute(score_f16,
                         cudaFuncAttributeMaxDynamicSharedMemorySize, score_smem);
    int av_smem = 3 * 2 * 2560 * (int)sizeof(__half);                // 30720
    cudaFuncSetAttribute(av_f16,
                         cudaFuncAttributeMaxDynamicSharedMemorySize, av_smem);

    // fp16 conversions (x + 4 weight matrices)
    conv_x<<<M_TOK * DIMC / 1024, 256>>>(x, gxh);
    conv_wt<<<dim3(24, 24, 4), 256>>>(Wq, Wk, Wv, Wp, gwt);

    // QKV projections (fp16), one launch; Q pre-scaled; V fp16 transposed
    qkv_f16<<<dim3(6, 64, 3), 256, qkv_smem>>>(gxh, gwt, gq, gk, gvt);

    // raw scores S = Q K^T -> fp16, coalesced staged stores
    score_f16<<<dim3(8, 8, 96), 256, score_smem>>>(gq, gk, gS);

    // register-resident fused pre-mix + softmax + post-mix (FFMA2, h-outer)
    softmax_mix_reg<<<dim3(1024, 8), 256>>>(gS, Wl, bl, Ww, bw);

    // attn @ V -> [tok, dim] fp16
    av_f16<<<dim3(16, 96), 256, av_smem>>>(gS, gvt, gOh);

    // final projection + bias (fp16 GEMM, fp32 accum/out)
    outproj_f16<<<dim3(6, 64), 256, qkv_smem>>>(gOh, gwt, out, bp);
}